// round 6
// baseline (speedup 1.0000x reference)
#include <cuda_runtime.h>
#include <cuda_bf16.h>
#include <math.h>
#include <stdint.h>

typedef __nv_bfloat16 bf16;

#define BB 4
#define SS 1020
#define DDIM 1024
#define HH 16
#define DH 64
#define LL 4
#define TPB_ 17
#define FF 4096
#define NTOK (BB*SS)
#define NOBS (BB*960)
#define NACT (BB*60)
#define VOBS_ 4096
#define VACT_ 16
#define DD_ (DDIM*DDIM)
#define DF_ (DDIM*FF)

// ---------------- static scratch ----------------
__device__ __align__(256) float g_x[NTOK*DDIM];
__device__ __align__(256) float g_qkv[NTOK*3*DDIM];
__device__ __align__(256) float g_t2[NACT*DDIM];
__device__ __align__(256) bf16 g_h_hi[NTOK*DDIM];
__device__ __align__(256) bf16 g_h_lo[NTOK*DDIM];
__device__ __align__(256) bf16 g_o_hi[NTOK*DDIM];
__device__ __align__(256) bf16 g_o_lo[NTOK*DDIM];
__device__ __align__(256) bf16 g_mid_hi[NTOK*FF];
__device__ __align__(256) bf16 g_mid_lo[NTOK*FF];
__device__ __align__(256) bf16 g_t1_hi[NOBS*DDIM];
__device__ __align__(256) bf16 g_t1_lo[NOBS*DDIM];
__device__ float g_bqkv[LL*3*DDIM];
__device__ int g_obs_rows[NOBS];
__device__ int g_act_rows[NACT];

#define WQKV_OFF 0
#define WO_OFF  (WQKV_OFF + LL*3*DD_)
#define W1_OFF  (WO_OFF + LL*DD_)
#define W2_OFF  (W1_OFF + LL*DF_)
#define HO1_OFF (W2_OFF + LL*DF_)
#define HO2_OFF (HO1_OFF + DD_)
#define HE1_OFF (HO2_OFF + VOBS_*DDIM)
#define WT_TOT  (HE1_OFF + DD_)
__device__ __align__(256) bf16 g_wt_hi[WT_TOT];
__device__ __align__(256) bf16 g_wt_lo[WT_TOT];

// ---------------- PTX helpers ----------------
__device__ __forceinline__ uint32_t s2u(const void* p){ return (uint32_t)__cvta_generic_to_shared(p); }
__device__ __forceinline__ void cp16(uint32_t d, const void* s){
    asm volatile("cp.async.cg.shared.global [%0], [%1], 16;\n"::"r"(d),"l"(s));
}
#define CP_COMMIT() asm volatile("cp.async.commit_group;\n":::"memory")
#define CP_WAIT1()  asm volatile("cp.async.wait_group 1;\n":::"memory")
#define CP_WAIT0()  asm volatile("cp.async.wait_group 0;\n":::"memory")

#define SWZ(o) ((o) ^ (((o)>>3)&0x70))

#define LDM4(r0,r1,r2,r3,a) \
    asm volatile("ldmatrix.sync.aligned.m8n8.x4.shared.b16 {%0,%1,%2,%3}, [%4];" \
        : "=r"(r0),"=r"(r1),"=r"(r2),"=r"(r3) : "r"(a))

#define MMA16816(c,a,b0,b1) \
    asm volatile("mma.sync.aligned.m16n8k16.row.col.f32.bf16.bf16.f32 " \
        "{%0,%1,%2,%3}, {%4,%5,%6,%7}, {%8,%9}, {%0,%1,%2,%3};" \
        : "+f"((c)[0]),"+f"((c)[1]),"+f"((c)[2]),"+f"((c)[3]) \
        : "r"((a)[0]),"r"((a)[1]),"r"((a)[2]),"r"((a)[3]), "r"(b0),"r"(b1))

// ---------------- mma.sync split-bf16 GEMM ----------------
#define BM 128
#define BN 256
#define STG 98304   // Ah 16K | Al 16K | Bh 32K | Bl 32K
#define GEMM_SMEM (2*STG)

template<int ACT, int OUTBF>
__global__ __launch_bounds__(256, 1)
void tcgemm(const bf16* __restrict__ Ah, const bf16* __restrict__ Al,
            const bf16* __restrict__ Bh, const bf16* __restrict__ Bl,
            const float* __restrict__ bias,
            float* __restrict__ C, bf16* __restrict__ Ch, bf16* __restrict__ Cl,
            const float* __restrict__ resid, const int* __restrict__ rowmap,
            int M, int N, int K)
{
    extern __shared__ char smem[];
    uint32_t sb = s2u(smem);
    int tid = threadIdx.x, lane = tid&31, wid = tid>>5;
    int wm = wid&1, wn = wid>>1;
    int m0 = blockIdx.y*BM, n0 = blockIdx.x*BN;

    size_t aOff[4]; uint32_t aSw[4];
    #pragma unroll
    for (int i=0;i<4;++i){
        int t = tid+256*i, r = t>>3, c = t&7;
        int am = m0+r; if (am > M-1) am = M-1;
        int ar = rowmap ? rowmap[am] : am;
        aOff[i] = (size_t)ar*K + c*8;
        uint32_t o = r*128 + c*16;
        aSw[i] = SWZ(o);
    }
    size_t bOff[8]; uint32_t bSw[8];
    #pragma unroll
    for (int i=0;i<8;++i){
        int t = tid+256*i, r = t>>3, c = t&7;
        bOff[i] = (size_t)(n0+r)*K + c*8;
        uint32_t o = r*128 + c*16;
        bSw[i] = SWZ(o);
    }

    const int NC = K/64;
    #define LOAD_STAGE(s_, ck_) do { \
        uint32_t aH_ = sb + (s_)*STG, aL_ = aH_ + 16384; \
        uint32_t bH_ = aH_ + 32768,  bL_ = aH_ + 65536; \
        size_t ko_ = (size_t)(ck_)*64; \
        _Pragma("unroll") \
        for (int i=0;i<4;++i){ cp16(aH_+aSw[i], Ah+aOff[i]+ko_); cp16(aL_+aSw[i], Al+aOff[i]+ko_); } \
        _Pragma("unroll") \
        for (int i=0;i<8;++i){ cp16(bH_+bSw[i], Bh+bOff[i]+ko_); cp16(bL_+bSw[i], Bl+bOff[i]+ko_); } \
    } while(0)

    LOAD_STAGE(0, 0); CP_COMMIT();

    int rA  = wm*64 + (lane&15);
    int kbA = (lane>>4)*16;
    int rB  = wn*64 + (lane&7) + ((lane>>4)<<3);
    int kbB = ((lane>>3)&1)*16;

    float acc[4][8][4];
    #pragma unroll
    for (int i=0;i<4;++i)
        #pragma unroll
        for (int j=0;j<8;++j)
            #pragma unroll
            for (int r=0;r<4;++r) acc[i][j][r]=0.f;

    for (int ck=0; ck<NC; ++ck){
        if (ck+1 < NC){ LOAD_STAGE((ck+1)&1, ck+1); CP_COMMIT(); CP_WAIT1(); }
        else CP_WAIT0();
        __syncthreads();
        int s = ck & 1;
        uint32_t uaH = sb + s*STG, uaL = uaH + 16384;
        uint32_t ubH = uaH + 32768, ubL = uaH + 65536;
        #pragma unroll
        for (int ks=0; ks<4; ++ks){
            uint32_t ah[4][4], al[4][4];
            #pragma unroll
            for (int mi=0;mi<4;++mi){
                uint32_t o = ((uint32_t)(rA + mi*16)<<7) + ks*32 + kbA;
                o = SWZ(o);
                LDM4(ah[mi][0],ah[mi][1],ah[mi][2],ah[mi][3], uaH + o);
                LDM4(al[mi][0],al[mi][1],al[mi][2],al[mi][3], uaL + o);
            }
            #pragma unroll
            for (int ng=0;ng<4;++ng){
                uint32_t bh[4], bl[4];
                uint32_t o = ((uint32_t)(rB + ng*16)<<7) + ks*32 + kbB;
                o = SWZ(o);
                LDM4(bh[0],bh[1],bh[2],bh[3], ubH + o);
                LDM4(bl[0],bl[1],bl[2],bl[3], ubL + o);
                #pragma unroll
                for (int mi=0;mi<4;++mi){
                    #pragma unroll
                    for (int j=0;j<2;++j){
                        MMA16816(acc[mi][ng*2+j], ah[mi], bh[j*2], bh[j*2+1]);
                        MMA16816(acc[mi][ng*2+j], ah[mi], bl[j*2], bl[j*2+1]);
                        MMA16816(acc[mi][ng*2+j], al[mi], bh[j*2], bh[j*2+1]);
                    }
                }
            }
        }
        __syncthreads();
    }

    int g = lane>>2, tg = lane&3;
    #pragma unroll
    for (int mi=0;mi<4;++mi){
        #pragma unroll
        for (int half=0; half<2; ++half){
            int m = m0 + wm*64 + mi*16 + g + half*8;
            if (m < M){
                #pragma unroll
                for (int nj=0;nj<8;++nj){
                    int n = n0 + wn*64 + nj*8 + tg*2;
                    float v0 = acc[mi][nj][half*2+0] + __ldg(bias+n);
                    float v1 = acc[mi][nj][half*2+1] + __ldg(bias+n+1);
                    if (ACT==1){
                        v0 = 0.5f*v0*(1.0f+erff(v0*0.70710678118654752f));
                        v1 = 0.5f*v1*(1.0f+erff(v1*0.70710678118654752f));
                    }
                    if (ACT==2){ v0 = fmaxf(v0,0.f); v1 = fmaxf(v1,0.f); }
                    if (resid){
                        float2 rr = *(const float2*)(resid + (size_t)m*N + n);
                        v0 += rr.x; v1 += rr.y;
                    }
                    if (OUTBF==0){
                        float2 w; w.x=v0; w.y=v1;
                        *(float2*)(C + (size_t)m*N + n) = w;
                    } else {
                        bf16 h0=__float2bfloat16(v0), h1=__float2bfloat16(v1);
                        __nv_bfloat162 H; H.x=h0; H.y=h1;
                        __nv_bfloat162 L;
                        L.x=__float2bfloat16(v0-__bfloat162float(h0));
                        L.y=__float2bfloat16(v1-__bfloat162float(h1));
                        *(__nv_bfloat162*)(Ch + (size_t)m*N + n) = H;
                        *(__nv_bfloat162*)(Cl + (size_t)m*N + n) = L;
                    }
                }
            }
        }
    }
}

// ---------------- fused weight transpose + split (single launch) ----------------
// segments mapped over blockIdx.x; tile = 64 k x 32 n; block (32,8)
__global__ void convert_all(const float* __restrict__ wq, const float* __restrict__ wk,
                            const float* __restrict__ wv, const float* __restrict__ wo,
                            const float* __restrict__ w1, const float* __restrict__ w2,
                            const float* __restrict__ ho1, const float* __restrict__ ho2,
                            const float* __restrict__ he1)
{
    int t = blockIdx.x;
    const float* src; int doff, K, N, base; size_t inMS, outMS;
    if      (t <  2048){ src=wq;  doff=WQKV_OFF;        K=DDIM; N=DDIM;  inMS=DD_; outMS=3*DD_; base=0; }
    else if (t <  4096){ src=wk;  doff=WQKV_OFF+DD_;    K=DDIM; N=DDIM;  inMS=DD_; outMS=3*DD_; base=2048; }
    else if (t <  6144){ src=wv;  doff=WQKV_OFF+2*DD_;  K=DDIM; N=DDIM;  inMS=DD_; outMS=3*DD_; base=4096; }
    else if (t <  8192){ src=wo;  doff=WO_OFF;          K=DDIM; N=DDIM;  inMS=DD_; outMS=DD_;   base=6144; }
    else if (t < 16384){ src=w1;  doff=W1_OFF;          K=DDIM; N=FF;    inMS=DF_; outMS=DF_;   base=8192; }
    else if (t < 24576){ src=w2;  doff=W2_OFF;          K=FF;   N=DDIM;  inMS=DF_; outMS=DF_;   base=16384; }
    else if (t < 25088){ src=ho1; doff=HO1_OFF;         K=DDIM; N=DDIM;  inMS=0;   outMS=0;     base=24576; }
    else if (t < 27136){ src=ho2; doff=HO2_OFF;         K=DDIM; N=VOBS_; inMS=0;   outMS=0;     base=25088; }
    else               { src=he1; doff=HE1_OFF;         K=DDIM; N=DDIM;  inMS=0;   outMS=0;     base=27136; }
    int r = t - base;
    int nt = N/32;
    int tpz = (K/64)*nt;
    int z = r/tpz, rr = r%tpz;
    int k0 = (rr/nt)*64, n0 = (rr%nt)*32;

    const float* Wm = src + (size_t)z*inMS;
    bf16* Whm = g_wt_hi + doff + (size_t)z*outMS;
    bf16* Wlm = g_wt_lo + doff + (size_t)z*outMS;

    __shared__ float tsh[64][33];
    int tx = threadIdx.x, ty = threadIdx.y;
    #pragma unroll
    for (int i=0;i<8;++i)
        tsh[ty+8*i][tx] = Wm[(size_t)(k0+ty+8*i)*N + n0+tx];
    __syncthreads();
    #pragma unroll
    for (int i=0;i<4;++i){
        int nn = ty + 8*i;
        float v0 = tsh[tx*2][nn], v1 = tsh[tx*2+1][nn];
        bf16 h0 = __float2bfloat16(v0), h1 = __float2bfloat16(v1);
        __nv_bfloat162 H; H.x=h0; H.y=h1;
        __nv_bfloat162 L;
        L.x = __float2bfloat16(v0-__bfloat162float(h0));
        L.y = __float2bfloat16(v1-__bfloat162float(h1));
        size_t o = (size_t)(n0+nn)*K + k0 + tx*2;
        *(__nv_bfloat162*)(Whm+o) = H;
        *(__nv_bfloat162*)(Wlm+o) = L;
    }
}

__global__ void pack_bqkv(const float* bq, const float* bk, const float* bv)
{
    int t = blockIdx.x*blockDim.x + threadIdx.x;
    if (t < LL*DDIM){
        int l = t/DDIM, d = t%DDIM;
        g_bqkv[(size_t)l*3*DDIM + d] = bq[t];
        g_bqkv[(size_t)l*3*DDIM + DDIM + d] = bk[t];
        g_bqkv[(size_t)l*3*DDIM + 2*DDIM + d] = bv[t];
    }
}

// ---------------- embed ----------------
__global__ void embed_kernel(const int* __restrict__ tokens, const float* __restrict__ pos_emb,
                             const float* __restrict__ emb_obs, const float* __restrict__ emb_act,
                             float* __restrict__ x)
{
    int row = blockIdx.x, s = row % SS;
    int tok = tokens[row];
    bool is_obs = (s % TPB_) < (TPB_-1);
    const float* e = is_obs ? (emb_obs + (size_t)min(tok,VOBS_-1)*DDIM)
                            : (emb_act + (size_t)min(tok,VACT_-1)*DDIM);
    const float* pe = pos_emb + (size_t)s*DDIM;
    float* xo = x + (size_t)row*DDIM;
    for (int d = threadIdx.x; d < DDIM; d += blockDim.x) xo[d] = e[d] + pe[d];
}

// ---------------- LN -> split bf16 ----------------
__device__ __forceinline__ float bsum256(float v)
{
    __shared__ float sh[8];
    int ln = threadIdx.x&31, w = threadIdx.x>>5;
    #pragma unroll
    for (int o=16;o>0;o>>=1) v += __shfl_xor_sync(0xffffffffu, v, o);
    if (ln==0) sh[w]=v;
    __syncthreads();
    if (w==0){
        float t = (ln<8)?sh[ln]:0.f;
        #pragma unroll
        for (int o=4;o>0;o>>=1) t += __shfl_xor_sync(0xffffffffu, t, o);
        if (ln==0) sh[0]=t;
    }
    __syncthreads();
    float r = sh[0];
    __syncthreads();
    return r;
}

__global__ void ln_kernel(const float* __restrict__ x, const float* __restrict__ g,
                          const float* __restrict__ b, bf16* __restrict__ oh, bf16* __restrict__ ol)
{
    int row = blockIdx.x, t = threadIdx.x;
    const float* xr = x + (size_t)row*DDIM;
    float v[4]; float s = 0.f;
    #pragma unroll
    for (int i=0;i<4;++i){ v[i]=xr[t+256*i]; s+=v[i]; }
    float mean = bsum256(s) * (1.f/DDIM);
    float q = 0.f;
    #pragma unroll
    for (int i=0;i<4;++i){ float d=v[i]-mean; q+=d*d; }
    float rstd = rsqrtf(bsum256(q)*(1.f/DDIM) + 1e-3f);
    #pragma unroll
    for (int i=0;i<4;++i){
        int idx = t+256*i;
        float y = (v[i]-mean)*rstd*g[idx] + b[idx];
        bf16 h = __float2bfloat16(y);
        oh[(size_t)row*DDIM+idx] = h;
        ol[(size_t)row*DDIM+idx] = __float2bfloat16(y-__bfloat162float(h));
    }
}

// ---------------- attention: 128 thr, 2 thr/query, 4-key unroll ----------------
__global__ __launch_bounds__(128)
void attn_kernel(const float* __restrict__ qkv,
                 bf16* __restrict__ o_hi, bf16* __restrict__ o_lo)
{
    const int RS = 3*DDIM;
    int bh = blockIdx.y, b = bh>>4, h = bh&15;
    int qt = blockIdx.x, tid = threadIdx.x;
    int qi = tid>>1, dh = tid&1;
    int i = qt*64 + qi;
    bool valid = i < SS;
    int iq = valid ? i : SS-1;
    size_t rb = (size_t)b*SS;

    float qreg[32];
    {
        const float4* q4 = (const float4*)(qkv + (rb+iq)*RS + h*DH + dh*32);
        #pragma unroll
        for (int d=0;d<8;++d){
            float4 t = q4[d];
            qreg[4*d]=t.x; qreg[4*d+1]=t.y; qreg[4*d+2]=t.z; qreg[4*d+3]=t.w;
        }
    }

    __shared__ float Ksh[68][64];
    __shared__ float Vsh[68][64];
    // zero pad rows 64..67 (read by 4-key groups near je=64, never loaded)
    for (int idx = tid; idx < 4*64; idx += 128){
        Ksh[64 + (idx>>6)][idx&63] = 0.f;
        Vsh[64 + (idx>>6)][idx&63] = 0.f;
    }

    float oacc[32];
    #pragma unroll
    for (int d=0;d<32;++d) oacc[d]=0.f;
    float m = -1e30f, l = 0.f;
    const float scale = 0.125f;

    for (int kt=0; kt<=qt; ++kt){
        int j0 = kt*64, nk = min(64, SS-j0);
        __syncthreads();
        #pragma unroll
        for (int it=0;it<8;++it){
            int idx = it*128+tid, j = idx>>4, d4 = idx&15;
            if (j < nk){
                *(float4*)&Ksh[j][4*d4] = *(const float4*)(qkv + (rb+j0+j)*RS + DDIM + h*DH + 4*d4);
                *(float4*)&Vsh[j][4*d4] = *(const float4*)(qkv + (rb+j0+j)*RS + 2*DDIM + h*DH + 4*d4);
            } else {
                *(float4*)&Ksh[j][4*d4] = make_float4(0.f,0.f,0.f,0.f);
                *(float4*)&Vsh[j][4*d4] = make_float4(0.f,0.f,0.f,0.f);
            }
        }
        __syncthreads();
        int je = min(nk, iq - j0 + 1);
        for (int jb=0; jb<je; jb+=4){
            const float *k0=&Ksh[jb][dh*32], *k1=&Ksh[jb+1][dh*32];
            const float *k2=&Ksh[jb+2][dh*32], *k3=&Ksh[jb+3][dh*32];
            float s0=0.f,s1=0.f,s2=0.f,s3=0.f;
            #pragma unroll
            for (int d=0;d<32;++d){
                float qd = qreg[d];
                s0 = fmaf(qd, k0[d], s0);
                s1 = fmaf(qd, k1[d], s1);
                s2 = fmaf(qd, k2[d], s2);
                s3 = fmaf(qd, k3[d], s3);
            }
            s0 += __shfl_xor_sync(0xffffffffu, s0, 1);
            s1 += __shfl_xor_sync(0xffffffffu, s1, 1);
            s2 += __shfl_xor_sync(0xffffffffu, s2, 1);
            s3 += __shfl_xor_sync(0xffffffffu, s3, 1);
            s0 = s0*scale;
            s1 = (jb+1 < je) ? s1*scale : -1e30f;
            s2 = (jb+2 < je) ? s2*scale : -1e30f;
            s3 = (jb+3 < je) ? s3*scale : -1e30f;
            float mx = fmaxf(fmaxf(s0,s1), fmaxf(s2,s3));
            float mn = fmaxf(m, mx);
            float c = __expf(m - mn);
            float p0 = __expf(s0-mn), p1 = __expf(s1-mn);
            float p2 = __expf(s2-mn), p3 = __expf(s3-mn);
            l = l*c + (p0+p1) + (p2+p3);
            const float *v0=&Vsh[jb][dh*32], *v1=&Vsh[jb+1][dh*32];
            const float *v2=&Vsh[jb+2][dh*32], *v3=&Vsh[jb+3][dh*32];
            #pragma unroll
            for (int d=0;d<32;++d){
                float t = fmaf(p0, v0[d], oacc[d]*c);
                t = fmaf(p1, v1[d], t);
                t = fmaf(p2, v2[d], t);
                t = fmaf(p3, v3[d], t);
                oacc[d] = t;
            }
            m = mn;
        }
    }
    if (valid){
        float inv = 1.f/l;
        size_t ob = (rb+i)*DDIM + h*DH + dh*32;
        #pragma unroll
        for (int d=0;d<32;++d){
            float val = oacc[d]*inv;
            bf16 hh = __float2bfloat16(val);
            o_hi[ob+d] = hh;
            o_lo[ob+d] = __float2bfloat16(val-__bfloat162float(hh));
        }
    }
}

// ---------------- misc ----------------
__global__ void build_idx_kernel()
{
    int t = blockIdx.x*blockDim.x + threadIdx.x;
    if (t < NOBS){
        int b = t/960, j = t%960, blk = j/16, r = j%16;
        g_obs_rows[t] = b*SS + blk*TPB_ + (r<15 ? r : 16);
    }
    if (t < NACT){
        int b = t/60, blk = t%60;
        g_act_rows[t] = b*SS + blk*TPB_ + (TPB_-1);
    }
}

__global__ void head_ends_kernel(const float* __restrict__ t2, const float* __restrict__ w,
                                 const float* __restrict__ bias, float* __restrict__ out)
{
    int r = blockIdx.x, tid = threadIdx.x;
    const float* a = t2 + (size_t)r*DDIM;
    float s0 = 0.f, s1 = 0.f;
    for (int k = tid; k < DDIM; k += 128){
        float av = a[k];
        s0 = fmaf(av, w[k*2], s0);
        s1 = fmaf(av, w[k*2+1], s1);
    }
    __shared__ float red[128];
    red[tid]=s0; __syncthreads();
    for (int st=64;st>0;st>>=1){ if (tid<st) red[tid]+=red[tid+st]; __syncthreads(); }
    if (tid==0) out[r*2] = red[0]+bias[0];
    __syncthreads();
    red[tid]=s1; __syncthreads();
    for (int st=64;st>0;st>>=1){ if (tid<st) red[tid]+=red[tid+st]; __syncthreads(); }
    if (tid==0) out[r*2+1] = red[0]+bias[1];
}

// ---------------- launch ----------------
extern "C" void kernel_launch(void* const* d_in, const int* in_sizes, int n_in,
                              void* d_out, int out_size)
{
    const int* tokens = (const int*)d_in[0];
    const float *pos_emb=(const float*)d_in[1], *emb_obs=(const float*)d_in[2], *emb_act=(const float*)d_in[3];
    const float *ln1_g=(const float*)d_in[4], *ln1_b=(const float*)d_in[5];
    const float *wq=(const float*)d_in[6], *bq=(const float*)d_in[7];
    const float *wk=(const float*)d_in[8], *bk=(const float*)d_in[9];
    const float *wv=(const float*)d_in[10], *bv=(const float*)d_in[11];
    const float *wo=(const float*)d_in[12], *bo=(const float*)d_in[13];
    const float *ln2_g=(const float*)d_in[14], *ln2_b=(const float*)d_in[15];
    const float *w1=(const float*)d_in[16], *b1=(const float*)d_in[17];
    const float *w2=(const float*)d_in[18], *b2=(const float*)d_in[19];
    const float *lnf_g=(const float*)d_in[20], *lnf_b=(const float*)d_in[21];
    const float *ho1=(const float*)d_in[22], *bo1=(const float*)d_in[23];
    const float *ho2=(const float*)d_in[24], *bo2=(const float*)d_in[25];
    const float *he1=(const float*)d_in[26], *be1=(const float*)d_in[27];
    const float *he2=(const float*)d_in[28], *be2=(const float*)d_in[29];
    float* out = (float*)d_out;

    float *x,*qkv,*t2,*bqkv;
    bf16 *h_hi,*h_lo,*o_hi,*o_lo,*mid_hi,*mid_lo,*t1_hi,*t1_lo,*wt_hi,*wt_lo;
    int *obsr,*actr;
    cudaGetSymbolAddress((void**)&x, g_x);
    cudaGetSymbolAddress((void**)&qkv, g_qkv);
    cudaGetSymbolAddress((void**)&t2, g_t2);
    cudaGetSymbolAddress((void**)&bqkv, g_bqkv);
    cudaGetSymbolAddress((void**)&h_hi, g_h_hi);
    cudaGetSymbolAddress((void**)&h_lo, g_h_lo);
    cudaGetSymbolAddress((void**)&o_hi, g_o_hi);
    cudaGetSymbolAddress((void**)&o_lo, g_o_lo);
    cudaGetSymbolAddress((void**)&mid_hi, g_mid_hi);
    cudaGetSymbolAddress((void**)&mid_lo, g_mid_lo);
    cudaGetSymbolAddress((void**)&t1_hi, g_t1_hi);
    cudaGetSymbolAddress((void**)&t1_lo, g_t1_lo);
    cudaGetSymbolAddress((void**)&wt_hi, g_wt_hi);
    cudaGetSymbolAddress((void**)&wt_lo, g_wt_lo);
    cudaGetSymbolAddress((void**)&obsr, g_obs_rows);
    cudaGetSymbolAddress((void**)&actr, g_act_rows);

    cudaFuncSetAttribute(tcgemm<0,0>, cudaFuncAttributeMaxDynamicSharedMemorySize, GEMM_SMEM);
    cudaFuncSetAttribute(tcgemm<1,1>, cudaFuncAttributeMaxDynamicSharedMemorySize, GEMM_SMEM);
    cudaFuncSetAttribute(tcgemm<2,1>, cudaFuncAttributeMaxDynamicSharedMemorySize, GEMM_SMEM);
    cudaFuncSetAttribute(tcgemm<2,0>, cudaFuncAttributeMaxDynamicSharedMemorySize, GEMM_SMEM);

    // 1 conversion launch (27648 tiles covers all weights)
    convert_all<<<27648, dim3(32,8)>>>(wq, wk, wv, wo, w1, w2, ho1, ho2, he1);
    pack_bqkv<<<(LL*DDIM+255)/256, 256>>>(bq, bk, bv);
    build_idx_kernel<<<(NOBS+255)/256, 256>>>();
    embed_kernel<<<NTOK, 256>>>(tokens, pos_emb, emb_obs, emb_act, x);

    #define GG(M_, N_) dim3((N_)/BN, ((M_)+BM-1)/BM)
    for (int l = 0; l < LL; ++l){
        size_t dd = (size_t)l*DD_;
        ln_kernel<<<NTOK, 256>>>(x, ln1_g+l*DDIM, ln1_b+l*DDIM, h_hi, h_lo);
        tcgemm<0,0><<<GG(NTOK, 3*DDIM), 256, GEMM_SMEM>>>(
            h_hi, h_lo, wt_hi+WQKV_OFF+(size_t)l*3*DD_, wt_lo+WQKV_OFF+(size_t)l*3*DD_,
            bqkv+(size_t)l*3*DDIM, qkv, nullptr, nullptr, nullptr, nullptr, NTOK, 3*DDIM, DDIM);
        attn_kernel<<<dim3((SS+63)/64, BB*HH), 128>>>(qkv, o_hi, o_lo);
        tcgemm<0,0><<<GG(NTOK, DDIM), 256, GEMM_SMEM>>>(
            o_hi, o_lo, wt_hi+WO_OFF+dd, wt_lo+WO_OFF+dd,
            bo+l*DDIM, x, nullptr, nullptr, x, nullptr, NTOK, DDIM, DDIM);
        ln_kernel<<<NTOK, 256>>>(x, ln2_g+l*DDIM, ln2_b+l*DDIM, h_hi, h_lo);
        tcgemm<1,1><<<GG(NTOK, FF), 256, GEMM_SMEM>>>(
            h_hi, h_lo, wt_hi+W1_OFF+(size_t)l*DF_, wt_lo+W1_OFF+(size_t)l*DF_,
            b1+(size_t)l*FF, nullptr, mid_hi, mid_lo, nullptr, nullptr, NTOK, FF, DDIM);
        tcgemm<0,0><<<GG(NTOK, DDIM), 256, GEMM_SMEM>>>(
            mid_hi, mid_lo, wt_hi+W2_OFF+(size_t)l*DF_, wt_lo+W2_OFF+(size_t)l*DF_,
            b2+l*DDIM, x, nullptr, nullptr, x, nullptr, NTOK, DDIM, FF);
    }

    ln_kernel<<<NTOK, 256>>>(x, lnf_g, lnf_b, h_hi, h_lo);

    tcgemm<2,1><<<GG(NOBS, DDIM), 256, GEMM_SMEM>>>(
        h_hi, h_lo, wt_hi+HO1_OFF, wt_lo+HO1_OFF, bo1,
        nullptr, t1_hi, t1_lo, nullptr, obsr, NOBS, DDIM, DDIM);
    tcgemm<0,0><<<GG(NOBS, VOBS_), 256, GEMM_SMEM>>>(
        t1_hi, t1_lo, wt_hi+HO2_OFF, wt_lo+HO2_OFF, bo2,
        out, nullptr, nullptr, nullptr, nullptr, NOBS, VOBS_, DDIM);

    tcgemm<2,0><<<GG(NACT, DDIM), 256, GEMM_SMEM>>>(
        h_hi, h_lo, wt_hi+HE1_OFF, wt_lo+HE1_OFF, be1,
        t2, nullptr, nullptr, nullptr, actr, NACT, DDIM, DDIM);
    head_ends_kernel<<<NACT, 128>>>(t2, he2, be2, out + (size_t)NOBS*VOBS_);
}

// round 7
// speedup vs baseline: 1.0031x; 1.0031x over previous
#include <cuda_runtime.h>
#include <cuda_bf16.h>
#include <math.h>
#include <stdint.h>

typedef __nv_bfloat16 bf16;

#define BB 4
#define SS 1020
#define DDIM 1024
#define HH 16
#define DH 64
#define LL 4
#define TPB_ 17
#define FF 4096
#define NTOK (BB*SS)
#define NOBS (BB*960)
#define NACT (BB*60)
#define VOBS_ 4096
#define VACT_ 16
#define DD_ (DDIM*DDIM)
#define DF_ (DDIM*FF)

// ---------------- static scratch ----------------
__device__ __align__(256) float g_x[NTOK*DDIM];
__device__ __align__(256) float g_qkv[NTOK*3*DDIM];
__device__ __align__(256) float g_t2[NACT*DDIM];
__device__ __align__(256) bf16 g_h_hi[NTOK*DDIM];
__device__ __align__(256) bf16 g_h_lo[NTOK*DDIM];
__device__ __align__(256) bf16 g_o_hi[NTOK*DDIM];
__device__ __align__(256) bf16 g_o_lo[NTOK*DDIM];
__device__ __align__(256) bf16 g_mid_hi[NTOK*FF];
__device__ __align__(256) bf16 g_mid_lo[NTOK*FF];
__device__ __align__(256) bf16 g_t1_hi[NOBS*DDIM];
__device__ __align__(256) bf16 g_t1_lo[NOBS*DDIM];
__device__ float g_bqkv[LL*3*DDIM];
__device__ int g_obs_rows[NOBS];
__device__ int g_act_rows[NACT];

#define WQKV_OFF 0
#define WO_OFF  (WQKV_OFF + LL*3*DD_)
#define W1_OFF  (WO_OFF + LL*DD_)
#define W2_OFF  (W1_OFF + LL*DF_)
#define HO1_OFF (W2_OFF + LL*DF_)
#define HO2_OFF (HO1_OFF + DD_)
#define HE1_OFF (HO2_OFF + VOBS_*DDIM)
#define WT_TOT  (HE1_OFF + DD_)
__device__ __align__(256) bf16 g_wt_hi[WT_TOT];
__device__ __align__(256) bf16 g_wt_lo[WT_TOT];

// ---------------- PTX helpers ----------------
__device__ __forceinline__ uint32_t s2u(const void* p){ return (uint32_t)__cvta_generic_to_shared(p); }
__device__ __forceinline__ void cp16(uint32_t d, const void* s){
    asm volatile("cp.async.cg.shared.global [%0], [%1], 16;\n"::"r"(d),"l"(s));
}
#define CP_COMMIT() asm volatile("cp.async.commit_group;\n":::"memory")
#define CP_WAIT1()  asm volatile("cp.async.wait_group 1;\n":::"memory")
#define CP_WAIT0()  asm volatile("cp.async.wait_group 0;\n":::"memory")

#define SWZ(o) ((o) ^ (((o)>>3)&0x70))

#define LDM4(r0,r1,r2,r3,a) \
    asm volatile("ldmatrix.sync.aligned.m8n8.x4.shared.b16 {%0,%1,%2,%3}, [%4];" \
        : "=r"(r0),"=r"(r1),"=r"(r2),"=r"(r3) : "r"(a))

#define MMA16816(c,a,b0,b1) \
    asm volatile("mma.sync.aligned.m16n8k16.row.col.f32.bf16.bf16.f32 " \
        "{%0,%1,%2,%3}, {%4,%5,%6,%7}, {%8,%9}, {%0,%1,%2,%3};" \
        : "+f"((c)[0]),"+f"((c)[1]),"+f"((c)[2]),"+f"((c)[3]) \
        : "r"((a)[0]),"r"((a)[1]),"r"((a)[2]),"r"((a)[3]), "r"(b0),"r"(b1))

// ---------------- mma.sync split-bf16 GEMM ----------------
#define BM 128
#define BN 256
#define STG 98304   // Ah 16K | Al 16K | Bh 32K | Bl 32K
#define GEMM_SMEM (2*STG)

template<int ACT, int OUTBF>
__global__ __launch_bounds__(256, 1)
void tcgemm(const bf16* __restrict__ Ah, const bf16* __restrict__ Al,
            const bf16* __restrict__ Bh, const bf16* __restrict__ Bl,
            const float* __restrict__ bias,
            float* __restrict__ C, bf16* __restrict__ Ch, bf16* __restrict__ Cl,
            const float* __restrict__ resid, const int* __restrict__ rowmap,
            int M, int N, int K)
{
    extern __shared__ char smem[];
    uint32_t sb = s2u(smem);
    int tid = threadIdx.x, lane = tid&31, wid = tid>>5;
    int wm = wid&1, wn = wid>>1;
    int m0 = blockIdx.y*BM, n0 = blockIdx.x*BN;

    size_t aOff[4]; uint32_t aSw[4];
    #pragma unroll
    for (int i=0;i<4;++i){
        int t = tid+256*i, r = t>>3, c = t&7;
        int am = m0+r; if (am > M-1) am = M-1;
        int ar = rowmap ? rowmap[am] : am;
        aOff[i] = (size_t)ar*K + c*8;
        uint32_t o = r*128 + c*16;
        aSw[i] = SWZ(o);
    }
    size_t bOff[8]; uint32_t bSw[8];
    #pragma unroll
    for (int i=0;i<8;++i){
        int t = tid+256*i, r = t>>3, c = t&7;
        bOff[i] = (size_t)(n0+r)*K + c*8;
        uint32_t o = r*128 + c*16;
        bSw[i] = SWZ(o);
    }

    const int NC = K/64;
    #define LOAD_STAGE(s_, ck_) do { \
        uint32_t aH_ = sb + (s_)*STG, aL_ = aH_ + 16384; \
        uint32_t bH_ = aH_ + 32768,  bL_ = aH_ + 65536; \
        size_t ko_ = (size_t)(ck_)*64; \
        _Pragma("unroll") \
        for (int i=0;i<4;++i){ cp16(aH_+aSw[i], Ah+aOff[i]+ko_); cp16(aL_+aSw[i], Al+aOff[i]+ko_); } \
        _Pragma("unroll") \
        for (int i=0;i<8;++i){ cp16(bH_+bSw[i], Bh+bOff[i]+ko_); cp16(bL_+bSw[i], Bl+bOff[i]+ko_); } \
    } while(0)

    LOAD_STAGE(0, 0); CP_COMMIT();

    int rA  = wm*64 + (lane&15);
    int kbA = (lane>>4)*16;
    int rB  = wn*64 + (lane&7) + ((lane>>4)<<3);
    int kbB = ((lane>>3)&1)*16;

    float acc[4][8][4];
    #pragma unroll
    for (int i=0;i<4;++i)
        #pragma unroll
        for (int j=0;j<8;++j)
            #pragma unroll
            for (int r=0;r<4;++r) acc[i][j][r]=0.f;

    for (int ck=0; ck<NC; ++ck){
        if (ck+1 < NC){ LOAD_STAGE((ck+1)&1, ck+1); CP_COMMIT(); CP_WAIT1(); }
        else CP_WAIT0();
        __syncthreads();
        int s = ck & 1;
        uint32_t uaH = sb + s*STG, uaL = uaH + 16384;
        uint32_t ubH = uaH + 32768, ubL = uaH + 65536;
        #pragma unroll
        for (int ks=0; ks<4; ++ks){
            uint32_t ah[4][4], al[4][4];
            #pragma unroll
            for (int mi=0;mi<4;++mi){
                uint32_t o = ((uint32_t)(rA + mi*16)<<7) + ks*32 + kbA;
                o = SWZ(o);
                LDM4(ah[mi][0],ah[mi][1],ah[mi][2],ah[mi][3], uaH + o);
                LDM4(al[mi][0],al[mi][1],al[mi][2],al[mi][3], uaL + o);
            }
            #pragma unroll
            for (int ng=0;ng<4;++ng){
                uint32_t bh[4], bl[4];
                uint32_t o = ((uint32_t)(rB + ng*16)<<7) + ks*32 + kbB;
                o = SWZ(o);
                LDM4(bh[0],bh[1],bh[2],bh[3], ubH + o);
                LDM4(bl[0],bl[1],bl[2],bl[3], ubL + o);
                #pragma unroll
                for (int mi=0;mi<4;++mi){
                    #pragma unroll
                    for (int j=0;j<2;++j){
                        MMA16816(acc[mi][ng*2+j], ah[mi], bh[j*2], bh[j*2+1]);
                        MMA16816(acc[mi][ng*2+j], ah[mi], bl[j*2], bl[j*2+1]);
                        MMA16816(acc[mi][ng*2+j], al[mi], bh[j*2], bh[j*2+1]);
                    }
                }
            }
        }
        __syncthreads();
    }

    int g = lane>>2, tg = lane&3;
    #pragma unroll
    for (int mi=0;mi<4;++mi){
        #pragma unroll
        for (int half=0; half<2; ++half){
            int m = m0 + wm*64 + mi*16 + g + half*8;
            if (m < M){
                #pragma unroll
                for (int nj=0;nj<8;++nj){
                    int n = n0 + wn*64 + nj*8 + tg*2;
                    float v0 = acc[mi][nj][half*2+0] + __ldg(bias+n);
                    float v1 = acc[mi][nj][half*2+1] + __ldg(bias+n+1);
                    if (ACT==1){
                        v0 = 0.5f*v0*(1.0f+erff(v0*0.70710678118654752f));
                        v1 = 0.5f*v1*(1.0f+erff(v1*0.70710678118654752f));
                    }
                    if (ACT==2){ v0 = fmaxf(v0,0.f); v1 = fmaxf(v1,0.f); }
                    if (resid){
                        float2 rr = *(const float2*)(resid + (size_t)m*N + n);
                        v0 += rr.x; v1 += rr.y;
                    }
                    if (OUTBF==0){
                        float2 w; w.x=v0; w.y=v1;
                        *(float2*)(C + (size_t)m*N + n) = w;
                    } else {
                        bf16 h0=__float2bfloat16(v0), h1=__float2bfloat16(v1);
                        __nv_bfloat162 H; H.x=h0; H.y=h1;
                        __nv_bfloat162 L;
                        L.x=__float2bfloat16(v0-__bfloat162float(h0));
                        L.y=__float2bfloat16(v1-__bfloat162float(h1));
                        *(__nv_bfloat162*)(Ch + (size_t)m*N + n) = H;
                        *(__nv_bfloat162*)(Cl + (size_t)m*N + n) = L;
                    }
                }
            }
        }
    }
}

// ---------------- fused weight transpose/split + bias pack + index build ----------------
// main blocks: 27648 weight tiles (64k x 32n). aux blocks (64): pack_bqkv + build_idx.
#define CV_MAIN 27648
__global__ void convert_all(const float* __restrict__ wq, const float* __restrict__ wk,
                            const float* __restrict__ wv, const float* __restrict__ wo,
                            const float* __restrict__ w1, const float* __restrict__ w2,
                            const float* __restrict__ ho1, const float* __restrict__ ho2,
                            const float* __restrict__ he1,
                            const float* __restrict__ bq, const float* __restrict__ bk,
                            const float* __restrict__ bv)
{
    int t = blockIdx.x;
    int tid = threadIdx.y*32 + threadIdx.x;
    if (t >= CV_MAIN){
        int idx = (t - CV_MAIN)*256 + tid;
        if (idx < LL*3*DDIM){
            int l = idx/(3*DDIM), r = idx%(3*DDIM), part = r/DDIM, d = r%DDIM;
            const float* src = part==0 ? bq : (part==1 ? bk : bv);
            g_bqkv[idx] = src[l*DDIM + d];
        }
        int j = idx - LL*3*DDIM;
        if (j >= 0 && j < NOBS){
            int b = j/960, jj = j%960, blk = jj/16, r = jj%16;
            g_obs_rows[j] = b*SS + blk*TPB_ + (r<15 ? r : 16);
        }
        if (j >= 0 && j < NACT){
            int b = j/60, blk = j%60;
            g_act_rows[j] = b*SS + blk*TPB_ + (TPB_-1);
        }
        return;
    }
    const float* src; int doff, K, N, base; size_t inMS, outMS;
    if      (t <  2048){ src=wq;  doff=WQKV_OFF;        K=DDIM; N=DDIM;  inMS=DD_; outMS=3*DD_; base=0; }
    else if (t <  4096){ src=wk;  doff=WQKV_OFF+DD_;    K=DDIM; N=DDIM;  inMS=DD_; outMS=3*DD_; base=2048; }
    else if (t <  6144){ src=wv;  doff=WQKV_OFF+2*DD_;  K=DDIM; N=DDIM;  inMS=DD_; outMS=3*DD_; base=4096; }
    else if (t <  8192){ src=wo;  doff=WO_OFF;          K=DDIM; N=DDIM;  inMS=DD_; outMS=DD_;   base=6144; }
    else if (t < 16384){ src=w1;  doff=W1_OFF;          K=DDIM; N=FF;    inMS=DF_; outMS=DF_;   base=8192; }
    else if (t < 24576){ src=w2;  doff=W2_OFF;          K=FF;   N=DDIM;  inMS=DF_; outMS=DF_;   base=16384; }
    else if (t < 25088){ src=ho1; doff=HO1_OFF;         K=DDIM; N=DDIM;  inMS=0;   outMS=0;     base=24576; }
    else if (t < 27136){ src=ho2; doff=HO2_OFF;         K=DDIM; N=VOBS_; inMS=0;   outMS=0;     base=25088; }
    else               { src=he1; doff=HE1_OFF;         K=DDIM; N=DDIM;  inMS=0;   outMS=0;     base=27136; }
    int r = t - base;
    int nt = N/32;
    int tpz = (K/64)*nt;
    int z = r/tpz, rr = r%tpz;
    int k0 = (rr/nt)*64, n0 = (rr%nt)*32;

    const float* Wm = src + (size_t)z*inMS;
    bf16* Whm = g_wt_hi + doff + (size_t)z*outMS;
    bf16* Wlm = g_wt_lo + doff + (size_t)z*outMS;

    __shared__ float tsh[64][33];
    int tx = threadIdx.x, ty = threadIdx.y;
    #pragma unroll
    for (int i=0;i<8;++i)
        tsh[ty+8*i][tx] = Wm[(size_t)(k0+ty+8*i)*N + n0+tx];
    __syncthreads();
    #pragma unroll
    for (int i=0;i<4;++i){
        int nn = ty + 8*i;
        float v0 = tsh[tx*2][nn], v1 = tsh[tx*2+1][nn];
        bf16 h0 = __float2bfloat16(v0), h1 = __float2bfloat16(v1);
        __nv_bfloat162 H; H.x=h0; H.y=h1;
        __nv_bfloat162 L;
        L.x = __float2bfloat16(v0-__bfloat162float(h0));
        L.y = __float2bfloat16(v1-__bfloat162float(h1));
        size_t o = (size_t)(n0+nn)*K + k0 + tx*2;
        *(__nv_bfloat162*)(Whm+o) = H;
        *(__nv_bfloat162*)(Wlm+o) = L;
    }
}

// ---------------- embed ----------------
__global__ void embed_kernel(const int* __restrict__ tokens, const float* __restrict__ pos_emb,
                             const float* __restrict__ emb_obs, const float* __restrict__ emb_act,
                             float* __restrict__ x)
{
    int row = blockIdx.x, s = row % SS;
    int tok = tokens[row];
    bool is_obs = (s % TPB_) < (TPB_-1);
    const float* e = is_obs ? (emb_obs + (size_t)min(tok,VOBS_-1)*DDIM)
                            : (emb_act + (size_t)min(tok,VACT_-1)*DDIM);
    const float* pe = pos_emb + (size_t)s*DDIM;
    float* xo = x + (size_t)row*DDIM;
    for (int d = threadIdx.x; d < DDIM; d += blockDim.x) xo[d] = e[d] + pe[d];
}

// ---------------- LN -> split bf16 ----------------
__device__ __forceinline__ float bsum256(float v)
{
    __shared__ float sh[8];
    int ln = threadIdx.x&31, w = threadIdx.x>>5;
    #pragma unroll
    for (int o=16;o>0;o>>=1) v += __shfl_xor_sync(0xffffffffu, v, o);
    if (ln==0) sh[w]=v;
    __syncthreads();
    if (w==0){
        float t = (ln<8)?sh[ln]:0.f;
        #pragma unroll
        for (int o=4;o>0;o>>=1) t += __shfl_xor_sync(0xffffffffu, t, o);
        if (ln==0) sh[0]=t;
    }
    __syncthreads();
    float r = sh[0];
    __syncthreads();
    return r;
}

__global__ void ln_kernel(const float* __restrict__ x, const float* __restrict__ g,
                          const float* __restrict__ b, bf16* __restrict__ oh, bf16* __restrict__ ol)
{
    int row = blockIdx.x, t = threadIdx.x;
    const float* xr = x + (size_t)row*DDIM;
    float v[4]; float s = 0.f;
    #pragma unroll
    for (int i=0;i<4;++i){ v[i]=xr[t+256*i]; s+=v[i]; }
    float mean = bsum256(s) * (1.f/DDIM);
    float q = 0.f;
    #pragma unroll
    for (int i=0;i<4;++i){ float d=v[i]-mean; q+=d*d; }
    float rstd = rsqrtf(bsum256(q)*(1.f/DDIM) + 1e-3f);
    #pragma unroll
    for (int i=0;i<4;++i){
        int idx = t+256*i;
        float y = (v[i]-mean)*rstd*g[idx] + b[idx];
        bf16 h = __float2bfloat16(y);
        oh[(size_t)row*DDIM+idx] = h;
        ol[(size_t)row*DDIM+idx] = __float2bfloat16(y-__bfloat162float(h));
    }
}

// ---------------- attention: 128 thr, 2 thr/query, 4-key unroll ----------------
__global__ __launch_bounds__(128)
void attn_kernel(const float* __restrict__ qkv,
                 bf16* __restrict__ o_hi, bf16* __restrict__ o_lo)
{
    const int RS = 3*DDIM;
    int bh = blockIdx.y, b = bh>>4, h = bh&15;
    int qt = blockIdx.x, tid = threadIdx.x;
    int qi = tid>>1, dh = tid&1;
    int i = qt*64 + qi;
    bool valid = i < SS;
    int iq = valid ? i : SS-1;
    size_t rb = (size_t)b*SS;

    float qreg[32];
    {
        const float4* q4 = (const float4*)(qkv + (rb+iq)*RS + h*DH + dh*32);
        #pragma unroll
        for (int d=0;d<8;++d){
            float4 t = q4[d];
            qreg[4*d]=t.x; qreg[4*d+1]=t.y; qreg[4*d+2]=t.z; qreg[4*d+3]=t.w;
        }
    }

    __shared__ float Ksh[68][64];
    __shared__ float Vsh[68][64];
    for (int idx = tid; idx < 4*64; idx += 128){
        Ksh[64 + (idx>>6)][idx&63] = 0.f;
        Vsh[64 + (idx>>6)][idx&63] = 0.f;
    }

    float oacc[32];
    #pragma unroll
    for (int d=0;d<32;++d) oacc[d]=0.f;
    float m = -1e30f, l = 0.f;
    const float scale = 0.125f;

    for (int kt=0; kt<=qt; ++kt){
        int j0 = kt*64, nk = min(64, SS-j0);
        __syncthreads();
        #pragma unroll
        for (int it=0;it<8;++it){
            int idx = it*128+tid, j = idx>>4, d4 = idx&15;
            if (j < nk){
                *(float4*)&Ksh[j][4*d4] = *(const float4*)(qkv + (rb+j0+j)*RS + DDIM + h*DH + 4*d4);
                *(float4*)&Vsh[j][4*d4] = *(const float4*)(qkv + (rb+j0+j)*RS + 2*DDIM + h*DH + 4*d4);
            } else {
                *(float4*)&Ksh[j][4*d4] = make_float4(0.f,0.f,0.f,0.f);
                *(float4*)&Vsh[j][4*d4] = make_float4(0.f,0.f,0.f,0.f);
            }
        }
        __syncthreads();
        int je = min(nk, iq - j0 + 1);
        for (int jb=0; jb<je; jb+=4){
            const float *k0=&Ksh[jb][dh*32], *k1=&Ksh[jb+1][dh*32];
            const float *k2=&Ksh[jb+2][dh*32], *k3=&Ksh[jb+3][dh*32];
            float s0=0.f,s1=0.f,s2=0.f,s3=0.f;
            #pragma unroll
            for (int d=0;d<32;++d){
                float qd = qreg[d];
                s0 = fmaf(qd, k0[d], s0);
                s1 = fmaf(qd, k1[d], s1);
                s2 = fmaf(qd, k2[d], s2);
                s3 = fmaf(qd, k3[d], s3);
            }
            s0 += __shfl_xor_sync(0xffffffffu, s0, 1);
            s1 += __shfl_xor_sync(0xffffffffu, s1, 1);
            s2 += __shfl_xor_sync(0xffffffffu, s2, 1);
            s3 += __shfl_xor_sync(0xffffffffu, s3, 1);
            s0 = s0*scale;
            s1 = (jb+1 < je) ? s1*scale : -1e30f;
            s2 = (jb+2 < je) ? s2*scale : -1e30f;
            s3 = (jb+3 < je) ? s3*scale : -1e30f;
            float mx = fmaxf(fmaxf(s0,s1), fmaxf(s2,s3));
            float mn = fmaxf(m, mx);
            float c = __expf(m - mn);
            float p0 = __expf(s0-mn), p1 = __expf(s1-mn);
            float p2 = __expf(s2-mn), p3 = __expf(s3-mn);
            l = l*c + (p0+p1) + (p2+p3);
            const float *v0=&Vsh[jb][dh*32], *v1=&Vsh[jb+1][dh*32];
            const float *v2=&Vsh[jb+2][dh*32], *v3=&Vsh[jb+3][dh*32];
            #pragma unroll
            for (int d=0;d<32;++d){
                float t = fmaf(p0, v0[d], oacc[d]*c);
                t = fmaf(p1, v1[d], t);
                t = fmaf(p2, v2[d], t);
                t = fmaf(p3, v3[d], t);
                oacc[d] = t;
            }
            m = mn;
        }
    }
    if (valid){
        float inv = 1.f/l;
        size_t ob = (rb+i)*DDIM + h*DH + dh*32;
        #pragma unroll
        for (int d=0;d<32;++d){
            float val = oacc[d]*inv;
            bf16 hh = __float2bfloat16(val);
            o_hi[ob+d] = hh;
            o_lo[ob+d] = __float2bfloat16(val-__bfloat162float(hh));
        }
    }
}

// ---------------- tiny N=2 head ----------------
__global__ void head_ends_kernel(const float* __restrict__ t2, const float* __restrict__ w,
                                 const float* __restrict__ bias, float* __restrict__ out)
{
    int r = blockIdx.x, tid = threadIdx.x;
    const float* a = t2 + (size_t)r*DDIM;
    float s0 = 0.f, s1 = 0.f;
    for (int k = tid; k < DDIM; k += 128){
        float av = a[k];
        s0 = fmaf(av, w[k*2], s0);
        s1 = fmaf(av, w[k*2+1], s1);
    }
    __shared__ float red[128];
    red[tid]=s0; __syncthreads();
    for (int st=64;st>0;st>>=1){ if (tid<st) red[tid]+=red[tid+st]; __syncthreads(); }
    if (tid==0) out[r*2] = red[0]+bias[0];
    __syncthreads();
    red[tid]=s1; __syncthreads();
    for (int st=64;st>0;st>>=1){ if (tid<st) red[tid]+=red[tid+st]; __syncthreads(); }
    if (tid==0) out[r*2+1] = red[0]+bias[1];
}

// ---------------- launch ----------------
extern "C" void kernel_launch(void* const* d_in, const int* in_sizes, int n_in,
                              void* d_out, int out_size)
{
    const int* tokens = (const int*)d_in[0];
    const float *pos_emb=(const float*)d_in[1], *emb_obs=(const float*)d_in[2], *emb_act=(const float*)d_in[3];
    const float *ln1_g=(const float*)d_in[4], *ln1_b=(const float*)d_in[5];
    const float *wq=(const float*)d_in[6], *bq=(const float*)d_in[7];
    const float *wk=(const float*)d_in[8], *bk=(const float*)d_in[9];
    const float *wv=(const float*)d_in[10], *bv=(const float*)d_in[11];
    const float *wo=(const float*)d_in[12], *bo=(const float*)d_in[13];
    const float *ln2_g=(const float*)d_in[14], *ln2_b=(const float*)d_in[15];
    const float *w1=(const float*)d_in[16], *b1=(const float*)d_in[17];
    const float *w2=(const float*)d_in[18], *b2=(const float*)d_in[19];
    const float *lnf_g=(const float*)d_in[20], *lnf_b=(const float*)d_in[21];
    const float *ho1=(const float*)d_in[22], *bo1=(const float*)d_in[23];
    const float *ho2=(const float*)d_in[24], *bo2=(const float*)d_in[25];
    const float *he1=(const float*)d_in[26], *be1=(const float*)d_in[27];
    const float *he2=(const float*)d_in[28], *be2=(const float*)d_in[29];
    float* out = (float*)d_out;

    float *x,*qkv,*t2,*bqkv;
    bf16 *h_hi,*h_lo,*o_hi,*o_lo,*mid_hi,*mid_lo,*t1_hi,*t1_lo,*wt_hi,*wt_lo;
    int *obsr,*actr;
    cudaGetSymbolAddress((void**)&x, g_x);
    cudaGetSymbolAddress((void**)&qkv, g_qkv);
    cudaGetSymbolAddress((void**)&t2, g_t2);
    cudaGetSymbolAddress((void**)&bqkv, g_bqkv);
    cudaGetSymbolAddress((void**)&h_hi, g_h_hi);
    cudaGetSymbolAddress((void**)&h_lo, g_h_lo);
    cudaGetSymbolAddress((void**)&o_hi, g_o_hi);
    cudaGetSymbolAddress((void**)&o_lo, g_o_lo);
    cudaGetSymbolAddress((void**)&mid_hi, g_mid_hi);
    cudaGetSymbolAddress((void**)&mid_lo, g_mid_lo);
    cudaGetSymbolAddress((void**)&t1_hi, g_t1_hi);
    cudaGetSymbolAddress((void**)&t1_lo, g_t1_lo);
    cudaGetSymbolAddress((void**)&wt_hi, g_wt_hi);
    cudaGetSymbolAddress((void**)&wt_lo, g_wt_lo);
    cudaGetSymbolAddress((void**)&obsr, g_obs_rows);
    cudaGetSymbolAddress((void**)&actr, g_act_rows);

    cudaFuncSetAttribute(tcgemm<0,0>, cudaFuncAttributeMaxDynamicSharedMemorySize, GEMM_SMEM);
    cudaFuncSetAttribute(tcgemm<1,1>, cudaFuncAttributeMaxDynamicSharedMemorySize, GEMM_SMEM);
    cudaFuncSetAttribute(tcgemm<2,1>, cudaFuncAttributeMaxDynamicSharedMemorySize, GEMM_SMEM);
    cudaFuncSetAttribute(tcgemm<2,0>, cudaFuncAttributeMaxDynamicSharedMemorySize, GEMM_SMEM);

    // launch #1: all weight conversion + bias pack + index build
    convert_all<<<CV_MAIN + 64, dim3(32,8)>>>(wq, wk, wv, wo, w1, w2, ho1, ho2, he1, bq, bk, bv);
    // launch #2
    embed_kernel<<<NTOK, 256>>>(tokens, pos_emb, emb_obs, emb_act, x);

    #define GG(M_, N_) dim3((N_)/BN, ((M_)+BM-1)/BM)
    for (int l = 0; l < LL; ++l){
        size_t dd = (size_t)l*DD_;
        // launch #3 (l=0): ln -> launch #4 (l=0): tcgemm QKV  [ncu capture target]
        ln_kernel<<<NTOK, 256>>>(x, ln1_g+l*DDIM, ln1_b+l*DDIM, h_hi, h_lo);
        tcgemm<0,0><<<GG(NTOK, 3*DDIM), 256, GEMM_SMEM>>>(
            h_hi, h_lo, wt_hi+WQKV_OFF+(size_t)l*3*DD_, wt_lo+WQKV_OFF+(size_t)l*3*DD_,
            bqkv+(size_t)l*3*DDIM, qkv, nullptr, nullptr, nullptr, nullptr, NTOK, 3*DDIM, DDIM);
        attn_kernel<<<dim3((SS+63)/64, BB*HH), 128>>>(qkv, o_hi, o_lo);
        tcgemm<0,0><<<GG(NTOK, DDIM), 256, GEMM_SMEM>>>(
            o_hi, o_lo, wt_hi+WO_OFF+dd, wt_lo+WO_OFF+dd,
            bo+l*DDIM, x, nullptr, nullptr, x, nullptr, NTOK, DDIM, DDIM);
        ln_kernel<<<NTOK, 256>>>(x, ln2_g+l*DDIM, ln2_b+l*DDIM, h_hi, h_lo);
        tcgemm<1,1><<<GG(NTOK, FF), 256, GEMM_SMEM>>>(
            h_hi, h_lo, wt_hi+W1_OFF+(size_t)l*DF_, wt_lo+W1_OFF+(size_t)l*DF_,
            b1+(size_t)l*FF, nullptr, mid_hi, mid_lo, nullptr, nullptr, NTOK, FF, DDIM);
        tcgemm<0,0><<<GG(NTOK, DDIM), 256, GEMM_SMEM>>>(
            mid_hi, mid_lo, wt_hi+W2_OFF+(size_t)l*DF_, wt_lo+W2_OFF+(size_t)l*DF_,
            b2+l*DDIM, x, nullptr, nullptr, x, nullptr, NTOK, DDIM, FF);
    }

    ln_kernel<<<NTOK, 256>>>(x, lnf_g, lnf_b, h_hi, h_lo);

    tcgemm<2,1><<<GG(NOBS, DDIM), 256, GEMM_SMEM>>>(
        h_hi, h_lo, wt_hi+HO1_OFF, wt_lo+HO1_OFF, bo1,
        nullptr, t1_hi, t1_lo, nullptr, obsr, NOBS, DDIM, DDIM);
    tcgemm<0,0><<<GG(NOBS, VOBS_), 256, GEMM_SMEM>>>(
        t1_hi, t1_lo, wt_hi+HO2_OFF, wt_lo+HO2_OFF, bo2,
        out, nullptr, nullptr, nullptr, nullptr, NOBS, VOBS_, DDIM);

    tcgemm<2,0><<<GG(NACT, DDIM), 256, GEMM_SMEM>>>(
        h_hi, h_lo, wt_hi+HE1_OFF, wt_lo+HE1_OFF, be1,
        t2, nullptr, nullptr, nullptr, actr, NACT, DDIM, DDIM);
    head_ends_kernel<<<NACT, 128>>>(t2, he2, be2, out + (size_t)NOBS*VOBS_);
}

// round 8
// speedup vs baseline: 1.0193x; 1.0161x over previous
#include <cuda_runtime.h>
#include <cuda_bf16.h>
#include <math.h>
#include <stdint.h>

typedef __nv_bfloat16 bf16;

#define BB 4
#define SS 1020
#define DDIM 1024
#define HH 16
#define DH 64
#define LL 4
#define TPB_ 17
#define FF 4096
#define NTOK (BB*SS)
#define NOBS (BB*960)
#define NACT (BB*60)
#define VOBS_ 4096
#define VACT_ 16
#define DD_ (DDIM*DDIM)
#define DF_ (DDIM*FF)

// ---------------- static scratch ----------------
__device__ __align__(256) float g_x[NTOK*DDIM];
__device__ __align__(256) float g_qkv[NTOK*3*DDIM];
__device__ __align__(256) float g_t2[NACT*DDIM];
__device__ __align__(256) bf16 g_h_hi[NTOK*DDIM];
__device__ __align__(256) bf16 g_h_lo[NTOK*DDIM];
__device__ __align__(256) bf16 g_o_hi[NTOK*DDIM];
__device__ __align__(256) bf16 g_o_lo[NTOK*DDIM];
__device__ __align__(256) bf16 g_mid_hi[NTOK*FF];
__device__ __align__(256) bf16 g_mid_lo[NTOK*FF];
__device__ __align__(256) bf16 g_t1_hi[NOBS*DDIM];
__device__ __align__(256) bf16 g_t1_lo[NOBS*DDIM];
__device__ float g_bqkv[LL*3*DDIM];
__device__ int g_obs_rows[NOBS];
__device__ int g_act_rows[NACT];

#define WQKV_OFF 0
#define WO_OFF  (WQKV_OFF + LL*3*DD_)
#define W1_OFF  (WO_OFF + LL*DD_)
#define W2_OFF  (W1_OFF + LL*DF_)
#define HO1_OFF (W2_OFF + LL*DF_)
#define HO2_OFF (HO1_OFF + DD_)
#define HE1_OFF (HO2_OFF + VOBS_*DDIM)
#define WT_TOT  (HE1_OFF + DD_)
__device__ __align__(256) bf16 g_wt_hi[WT_TOT];
__device__ __align__(256) bf16 g_wt_lo[WT_TOT];

// ---------------- PTX helpers ----------------
__device__ __forceinline__ uint32_t s2u(const void* p){ return (uint32_t)__cvta_generic_to_shared(p); }
__device__ __forceinline__ void cp16(uint32_t d, const void* s){
    asm volatile("cp.async.cg.shared.global [%0], [%1], 16;\n"::"r"(d),"l"(s));
}
#define CP_COMMIT() asm volatile("cp.async.commit_group;\n":::"memory")
#define CP_WAIT2()  asm volatile("cp.async.wait_group 2;\n":::"memory")
#define CP_WAIT0()  asm volatile("cp.async.wait_group 0;\n":::"memory")

#define SWZ64(o) ((o) ^ (((o)>>3)&0x30))

#define LDM4(r0,r1,r2,r3,a) \
    asm volatile("ldmatrix.sync.aligned.m8n8.x4.shared.b16 {%0,%1,%2,%3}, [%4];" \
        : "=r"(r0),"=r"(r1),"=r"(r2),"=r"(r3) : "r"(a))

#define MMA16816(c,a,b0,b1) \
    asm volatile("mma.sync.aligned.m16n8k16.row.col.f32.bf16.bf16.f32 " \
        "{%0,%1,%2,%3}, {%4,%5,%6,%7}, {%8,%9}, {%0,%1,%2,%3};" \
        : "+f"((c)[0]),"+f"((c)[1]),"+f"((c)[2]),"+f"((c)[3]) \
        : "r"((a)[0]),"r"((a)[1]),"r"((a)[2]),"r"((a)[3]), "r"(b0),"r"(b1))

// ---------------- mma.sync split-bf16 GEMM (2 CTA/SM) ----------------
// BM=128, BN=128, BK=32, 3-stage pipeline, 64B-pitch SW64 tiles.
// stage: Ah 8K | Al 8K | Bh 8K | Bl 8K = 32K; x3 = 96K/CTA.
#define BM 128
#define BN 128
#define STG 32768
#define GEMM_SMEM (3*STG)

template<int ACT, int OUTBF>
__global__ __launch_bounds__(256, 2)
void tcgemm(const bf16* __restrict__ Ah, const bf16* __restrict__ Al,
            const bf16* __restrict__ Bh, const bf16* __restrict__ Bl,
            const float* __restrict__ bias,
            float* __restrict__ C, bf16* __restrict__ Ch, bf16* __restrict__ Cl,
            const float* __restrict__ resid, const int* __restrict__ rowmap,
            int M, int N, int K)
{
    extern __shared__ char smem[];
    uint32_t sb = s2u(smem);
    int tid = threadIdx.x, lane = tid&31, wid = tid>>5;
    int wm = wid&1, wn = wid>>1;          // 2m x 4n warps; warp tile 64x32
    int m0 = blockIdx.y*BM, n0 = blockIdx.x*BN;

    // loaders: 128 rows x 4 granules(16B) per tile; 2 per thread
    size_t aOff[2]; uint32_t aSw[2];
    size_t bOff[2]; uint32_t bSw[2];
    #pragma unroll
    for (int i=0;i<2;++i){
        int t = tid+256*i, r = t>>2, c = t&3;
        int am = m0+r; if (am > M-1) am = M-1;
        int ar = rowmap ? rowmap[am] : am;
        aOff[i] = (size_t)ar*K + c*8;
        bOff[i] = (size_t)(n0+r)*K + c*8;
        uint32_t o = r*64 + c*16;
        aSw[i] = SWZ64(o);
        bSw[i] = SWZ64(o);
    }

    const int NC = K/32;
    #define LOAD_STAGE(s_, ck_) do { \
        uint32_t aH_ = sb + (s_)*STG, aL_ = aH_ + 8192; \
        uint32_t bH_ = aH_ + 16384,  bL_ = aH_ + 24576; \
        size_t ko_ = (size_t)(ck_)*32; \
        _Pragma("unroll") \
        for (int i=0;i<2;++i){ cp16(aH_+aSw[i], Ah+aOff[i]+ko_); cp16(aL_+aSw[i], Al+aOff[i]+ko_); } \
        _Pragma("unroll") \
        for (int i=0;i<2;++i){ cp16(bH_+bSw[i], Bh+bOff[i]+ko_); cp16(bL_+bSw[i], Bl+bOff[i]+ko_); } \
    } while(0)

    LOAD_STAGE(0, 0); CP_COMMIT();
    LOAD_STAGE(1, 1); CP_COMMIT();

    int rA  = wm*64 + (lane&15);
    int kbA = (lane>>4)*16;
    int rB  = wn*32 + (lane&7) + ((lane>>4)<<3);
    int kbB = ((lane>>3)&1)*16;

    float acc[4][4][4];
    #pragma unroll
    for (int i=0;i<4;++i)
        #pragma unroll
        for (int j=0;j<4;++j)
            #pragma unroll
            for (int r=0;r<4;++r) acc[i][j][r]=0.f;

    for (int ck=0; ck<NC; ++ck){
        if (ck+2 < NC){ LOAD_STAGE((ck+2)%3, ck+2); CP_COMMIT(); CP_WAIT2(); }
        else CP_WAIT0();
        __syncthreads();
        uint32_t base = sb + (ck%3)*STG;
        uint32_t uaH = base, uaL = base + 8192;
        uint32_t ubH = base + 16384, ubL = base + 24576;
        #pragma unroll
        for (int ks=0; ks<2; ++ks){
            uint32_t bh[2][4], bl[2][4];
            #pragma unroll
            for (int ng=0;ng<2;++ng){
                uint32_t o = (uint32_t)(rB + ng*16)*64 + ks*32 + kbB;
                o = SWZ64(o);
                LDM4(bh[ng][0],bh[ng][1],bh[ng][2],bh[ng][3], ubH + o);
                LDM4(bl[ng][0],bl[ng][1],bl[ng][2],bl[ng][3], ubL + o);
            }
            #pragma unroll
            for (int mi=0;mi<4;++mi){
                uint32_t ah[4], al[4];
                uint32_t o = (uint32_t)(rA + mi*16)*64 + ks*32 + kbA;
                o = SWZ64(o);
                LDM4(ah[0],ah[1],ah[2],ah[3], uaH + o);
                LDM4(al[0],al[1],al[2],al[3], uaL + o);
                #pragma unroll
                for (int ng=0;ng<2;++ng){
                    #pragma unroll
                    for (int j=0;j<2;++j){
                        MMA16816(acc[mi][ng*2+j], ah, bh[ng][j*2], bh[ng][j*2+1]);
                        MMA16816(acc[mi][ng*2+j], ah, bl[ng][j*2], bl[ng][j*2+1]);
                        MMA16816(acc[mi][ng*2+j], al, bh[ng][j*2], bh[ng][j*2+1]);
                    }
                }
            }
        }
        __syncthreads();
    }

    int g = lane>>2, tg = lane&3;
    #pragma unroll
    for (int mi=0;mi<4;++mi){
        #pragma unroll
        for (int half=0; half<2; ++half){
            int m = m0 + wm*64 + mi*16 + g + half*8;
            if (m < M){
                #pragma unroll
                for (int nj=0;nj<4;++nj){
                    int n = n0 + wn*32 + nj*8 + tg*2;
                    float v0 = acc[mi][nj][half*2+0] + __ldg(bias+n);
                    float v1 = acc[mi][nj][half*2+1] + __ldg(bias+n+1);
                    if (ACT==1){
                        v0 = 0.5f*v0*(1.0f+erff(v0*0.70710678118654752f));
                        v1 = 0.5f*v1*(1.0f+erff(v1*0.70710678118654752f));
                    }
                    if (ACT==2){ v0 = fmaxf(v0,0.f); v1 = fmaxf(v1,0.f); }
                    if (resid){
                        float2 rr = *(const float2*)(resid + (size_t)m*N + n);
                        v0 += rr.x; v1 += rr.y;
                    }
                    if (OUTBF==0){
                        float2 w; w.x=v0; w.y=v1;
                        *(float2*)(C + (size_t)m*N + n) = w;
                    } else {
                        bf16 h0=__float2bfloat16(v0), h1=__float2bfloat16(v1);
                        __nv_bfloat162 H; H.x=h0; H.y=h1;
                        __nv_bfloat162 L;
                        L.x=__float2bfloat16(v0-__bfloat162float(h0));
                        L.y=__float2bfloat16(v1-__bfloat162float(h1));
                        *(__nv_bfloat162*)(Ch + (size_t)m*N + n) = H;
                        *(__nv_bfloat162*)(Cl + (size_t)m*N + n) = L;
                    }
                }
            }
        }
    }
}

// ---------------- fused weight transpose/split + bias pack + index build ----------------
#define CV_MAIN 27648
__global__ void convert_all(const float* __restrict__ wq, const float* __restrict__ wk,
                            const float* __restrict__ wv, const float* __restrict__ wo,
                            const float* __restrict__ w1, const float* __restrict__ w2,
                            const float* __restrict__ ho1, const float* __restrict__ ho2,
                            const float* __restrict__ he1,
                            const float* __restrict__ bq, const float* __restrict__ bk,
                            const float* __restrict__ bv)
{
    int t = blockIdx.x;
    int tid = threadIdx.y*32 + threadIdx.x;
    if (t >= CV_MAIN){
        int idx = (t - CV_MAIN)*256 + tid;
        if (idx < LL*3*DDIM){
            int l = idx/(3*DDIM), r = idx%(3*DDIM), part = r/DDIM, d = r%DDIM;
            const float* src = part==0 ? bq : (part==1 ? bk : bv);
            g_bqkv[idx] = src[l*DDIM + d];
        }
        int j = idx - LL*3*DDIM;
        if (j >= 0 && j < NOBS){
            int b = j/960, jj = j%960, blk = jj/16, r = jj%16;
            g_obs_rows[j] = b*SS + blk*TPB_ + (r<15 ? r : 16);
        }
        if (j >= 0 && j < NACT){
            int b = j/60, blk = j%60;
            g_act_rows[j] = b*SS + blk*TPB_ + (TPB_-1);
        }
        return;
    }
    const float* src; int doff, K, N, base; size_t inMS, outMS;
    if      (t <  2048){ src=wq;  doff=WQKV_OFF;        K=DDIM; N=DDIM;  inMS=DD_; outMS=3*DD_; base=0; }
    else if (t <  4096){ src=wk;  doff=WQKV_OFF+DD_;    K=DDIM; N=DDIM;  inMS=DD_; outMS=3*DD_; base=2048; }
    else if (t <  6144){ src=wv;  doff=WQKV_OFF+2*DD_;  K=DDIM; N=DDIM;  inMS=DD_; outMS=3*DD_; base=4096; }
    else if (t <  8192){ src=wo;  doff=WO_OFF;          K=DDIM; N=DDIM;  inMS=DD_; outMS=DD_;   base=6144; }
    else if (t < 16384){ src=w1;  doff=W1_OFF;          K=DDIM; N=FF;    inMS=DF_; outMS=DF_;   base=8192; }
    else if (t < 24576){ src=w2;  doff=W2_OFF;          K=FF;   N=DDIM;  inMS=DF_; outMS=DF_;   base=16384; }
    else if (t < 25088){ src=ho1; doff=HO1_OFF;         K=DDIM; N=DDIM;  inMS=0;   outMS=0;     base=24576; }
    else if (t < 27136){ src=ho2; doff=HO2_OFF;         K=DDIM; N=VOBS_; inMS=0;   outMS=0;     base=25088; }
    else               { src=he1; doff=HE1_OFF;         K=DDIM; N=DDIM;  inMS=0;   outMS=0;     base=27136; }
    int r = t - base;
    int nt = N/32;
    int tpz = (K/64)*nt;
    int z = r/tpz, rr = r%tpz;
    int k0 = (rr/nt)*64, n0 = (rr%nt)*32;

    const float* Wm = src + (size_t)z*inMS;
    bf16* Whm = g_wt_hi + doff + (size_t)z*outMS;
    bf16* Wlm = g_wt_lo + doff + (size_t)z*outMS;

    __shared__ float tsh[64][33];
    int tx = threadIdx.x, ty = threadIdx.y;
    #pragma unroll
    for (int i=0;i<8;++i)
        tsh[ty+8*i][tx] = Wm[(size_t)(k0+ty+8*i)*N + n0+tx];
    __syncthreads();
    #pragma unroll
    for (int i=0;i<4;++i){
        int nn = ty + 8*i;
        float v0 = tsh[tx*2][nn], v1 = tsh[tx*2+1][nn];
        bf16 h0 = __float2bfloat16(v0), h1 = __float2bfloat16(v1);
        __nv_bfloat162 H; H.x=h0; H.y=h1;
        __nv_bfloat162 L;
        L.x = __float2bfloat16(v0-__bfloat162float(h0));
        L.y = __float2bfloat16(v1-__bfloat162float(h1));
        size_t o = (size_t)(n0+nn)*K + k0 + tx*2;
        *(__nv_bfloat162*)(Whm+o) = H;
        *(__nv_bfloat162*)(Wlm+o) = L;
    }
}

// ---------------- embed ----------------
__global__ void embed_kernel(const int* __restrict__ tokens, const float* __restrict__ pos_emb,
                             const float* __restrict__ emb_obs, const float* __restrict__ emb_act,
                             float* __restrict__ x)
{
    int row = blockIdx.x, s = row % SS;
    int tok = tokens[row];
    bool is_obs = (s % TPB_) < (TPB_-1);
    const float* e = is_obs ? (emb_obs + (size_t)min(tok,VOBS_-1)*DDIM)
                            : (emb_act + (size_t)min(tok,VACT_-1)*DDIM);
    const float* pe = pos_emb + (size_t)s*DDIM;
    float* xo = x + (size_t)row*DDIM;
    for (int d = threadIdx.x; d < DDIM; d += blockDim.x) xo[d] = e[d] + pe[d];
}

// ---------------- LN -> split bf16 ----------------
__device__ __forceinline__ float bsum256(float v)
{
    __shared__ float sh[8];
    int ln = threadIdx.x&31, w = threadIdx.x>>5;
    #pragma unroll
    for (int o=16;o>0;o>>=1) v += __shfl_xor_sync(0xffffffffu, v, o);
    if (ln==0) sh[w]=v;
    __syncthreads();
    if (w==0){
        float t = (ln<8)?sh[ln]:0.f;
        #pragma unroll
        for (int o=4;o>0;o>>=1) t += __shfl_xor_sync(0xffffffffu, t, o);
        if (ln==0) sh[0]=t;
    }
    __syncthreads();
    float r = sh[0];
    __syncthreads();
    return r;
}

__global__ void ln_kernel(const float* __restrict__ x, const float* __restrict__ g,
                          const float* __restrict__ b, bf16* __restrict__ oh, bf16* __restrict__ ol)
{
    int row = blockIdx.x, t = threadIdx.x;
    const float* xr = x + (size_t)row*DDIM;
    float v[4]; float s = 0.f;
    #pragma unroll
    for (int i=0;i<4;++i){ v[i]=xr[t+256*i]; s+=v[i]; }
    float mean = bsum256(s) * (1.f/DDIM);
    float q = 0.f;
    #pragma unroll
    for (int i=0;i<4;++i){ float d=v[i]-mean; q+=d*d; }
    float rstd = rsqrtf(bsum256(q)*(1.f/DDIM) + 1e-3f);
    #pragma unroll
    for (int i=0;i<4;++i){
        int idx = t+256*i;
        float y = (v[i]-mean)*rstd*g[idx] + b[idx];
        bf16 h = __float2bfloat16(y);
        oh[(size_t)row*DDIM+idx] = h;
        ol[(size_t)row*DDIM+idx] = __float2bfloat16(y-__bfloat162float(h));
    }
}

// ---------------- attention (R5 64-thread version) ----------------
__global__ void attn_kernel(const float* __restrict__ qkv,
                            bf16* __restrict__ o_hi, bf16* __restrict__ o_lo)
{
    const int RS = 3*DDIM;
    int bh = blockIdx.y, b = bh>>4, h = bh&15;
    int qt = blockIdx.x, tid = threadIdx.x;
    int i = qt*64 + tid;
    bool valid = i < SS;
    int irow = valid ? i : SS-1;
    size_t rb = (size_t)b*SS;

    float qreg[64];
    {
        const float4* q4 = (const float4*)(qkv + (rb+irow)*RS + h*DH);
        #pragma unroll
        for (int d=0;d<16;++d){
            float4 t = q4[d];
            qreg[4*d]=t.x; qreg[4*d+1]=t.y; qreg[4*d+2]=t.z; qreg[4*d+3]=t.w;
        }
    }
    __shared__ float4 Ksh[64][16];
    __shared__ float4 Vsh[64][16];
    float oacc[64];
    #pragma unroll
    for (int d=0;d<64;++d) oacc[d]=0.f;
    float m = -1e30f, l = 0.f;
    const float scale = 0.125f;

    for (int kt=0; kt<=qt; ++kt){
        int j0 = kt*64, nk = min(64, SS-j0);
        __syncthreads();
        #pragma unroll
        for (int it=0;it<16;++it){
            int idx = it*64+tid, j = idx>>4, d4 = idx&15;
            if (j < nk){
                Ksh[j][d4] = *(const float4*)(qkv + (rb+j0+j)*RS + DDIM + h*DH + 4*d4);
                Vsh[j][d4] = *(const float4*)(qkv + (rb+j0+j)*RS + 2*DDIM + h*DH + 4*d4);
            }
        }
        __syncthreads();
        if (valid){
            const float* Ks = (const float*)Ksh;
            const float* Vs = (const float*)Vsh;
            int je = min(nk, i-j0+1);
            for (int j=0;j<je;++j){
                const float* kr = Ks + j*64;
                float s = 0.f;
                #pragma unroll
                for (int d=0;d<64;++d) s = fmaf(qreg[d], kr[d], s);
                s *= scale;
                const float* vr = Vs + j*64;
                if (s > m){
                    float c = __expf(m-s);
                    l = l*c + 1.f;
                    #pragma unroll
                    for (int d=0;d<64;++d) oacc[d] = fmaf(oacc[d], c, vr[d]);
                    m = s;
                } else {
                    float p = __expf(s-m);
                    l += p;
                    #pragma unroll
                    for (int d=0;d<64;++d) oacc[d] = fmaf(p, vr[d], oacc[d]);
                }
            }
        }
    }
    if (valid){
        float inv = 1.f/l;
        size_t ob = (rb+irow)*DDIM + h*DH;
        #pragma unroll
        for (int d=0;d<64;++d){
            float val = oacc[d]*inv;
            bf16 hh = __float2bfloat16(val);
            o_hi[ob+d] = hh;
            o_lo[ob+d] = __float2bfloat16(val-__bfloat162float(hh));
        }
    }
}

// ---------------- tiny N=2 head ----------------
__global__ void head_ends_kernel(const float* __restrict__ t2, const float* __restrict__ w,
                                 const float* __restrict__ bias, float* __restrict__ out)
{
    int r = blockIdx.x, tid = threadIdx.x;
    const float* a = t2 + (size_t)r*DDIM;
    float s0 = 0.f, s1 = 0.f;
    for (int k = tid; k < DDIM; k += 128){
        float av = a[k];
        s0 = fmaf(av, w[k*2], s0);
        s1 = fmaf(av, w[k*2+1], s1);
    }
    __shared__ float red[128];
    red[tid]=s0; __syncthreads();
    for (int st=64;st>0;st>>=1){ if (tid<st) red[tid]+=red[tid+st]; __syncthreads(); }
    if (tid==0) out[r*2] = red[0]+bias[0];
    __syncthreads();
    red[tid]=s1; __syncthreads();
    for (int st=64;st>0;st>>=1){ if (tid<st) red[tid]+=red[tid+st]; __syncthreads(); }
    if (tid==0) out[r*2+1] = red[0]+bias[1];
}

// ---------------- launch ----------------
extern "C" void kernel_launch(void* const* d_in, const int* in_sizes, int n_in,
                              void* d_out, int out_size)
{
    const int* tokens = (const int*)d_in[0];
    const float *pos_emb=(const float*)d_in[1], *emb_obs=(const float*)d_in[2], *emb_act=(const float*)d_in[3];
    const float *ln1_g=(const float*)d_in[4], *ln1_b=(const float*)d_in[5];
    const float *wq=(const float*)d_in[6], *bq=(const float*)d_in[7];
    const float *wk=(const float*)d_in[8], *bk=(const float*)d_in[9];
    const float *wv=(const float*)d_in[10], *bv=(const float*)d_in[11];
    const float *wo=(const float*)d_in[12], *bo=(const float*)d_in[13];
    const float *ln2_g=(const float*)d_in[14], *ln2_b=(const float*)d_in[15];
    const float *w1=(const float*)d_in[16], *b1=(const float*)d_in[17];
    const float *w2=(const float*)d_in[18], *b2=(const float*)d_in[19];
    const float *lnf_g=(const float*)d_in[20], *lnf_b=(const float*)d_in[21];
    const float *ho1=(const float*)d_in[22], *bo1=(const float*)d_in[23];
    const float *ho2=(const float*)d_in[24], *bo2=(const float*)d_in[25];
    const float *he1=(const float*)d_in[26], *be1=(const float*)d_in[27];
    const float *he2=(const float*)d_in[28], *be2=(const float*)d_in[29];
    float* out = (float*)d_out;

    float *x,*qkv,*t2,*bqkv;
    bf16 *h_hi,*h_lo,*o_hi,*o_lo,*mid_hi,*mid_lo,*t1_hi,*t1_lo,*wt_hi,*wt_lo;
    int *obsr,*actr;
    cudaGetSymbolAddress((void**)&x, g_x);
    cudaGetSymbolAddress((void**)&qkv, g_qkv);
    cudaGetSymbolAddress((void**)&t2, g_t2);
    cudaGetSymbolAddress((void**)&bqkv, g_bqkv);
    cudaGetSymbolAddress((void**)&h_hi, g_h_hi);
    cudaGetSymbolAddress((void**)&h_lo, g_h_lo);
    cudaGetSymbolAddress((void**)&o_hi, g_o_hi);
    cudaGetSymbolAddress((void**)&o_lo, g_o_lo);
    cudaGetSymbolAddress((void**)&mid_hi, g_mid_hi);
    cudaGetSymbolAddress((void**)&mid_lo, g_mid_lo);
    cudaGetSymbolAddress((void**)&t1_hi, g_t1_hi);
    cudaGetSymbolAddress((void**)&t1_lo, g_t1_lo);
    cudaGetSymbolAddress((void**)&wt_hi, g_wt_hi);
    cudaGetSymbolAddress((void**)&wt_lo, g_wt_lo);
    cudaGetSymbolAddress((void**)&obsr, g_obs_rows);
    cudaGetSymbolAddress((void**)&actr, g_act_rows);

    cudaFuncSetAttribute(tcgemm<0,0>, cudaFuncAttributeMaxDynamicSharedMemorySize, GEMM_SMEM);
    cudaFuncSetAttribute(tcgemm<1,1>, cudaFuncAttributeMaxDynamicSharedMemorySize, GEMM_SMEM);
    cudaFuncSetAttribute(tcgemm<2,1>, cudaFuncAttributeMaxDynamicSharedMemorySize, GEMM_SMEM);
    cudaFuncSetAttribute(tcgemm<2,0>, cudaFuncAttributeMaxDynamicSharedMemorySize, GEMM_SMEM);

    convert_all<<<CV_MAIN + 64, dim3(32,8)>>>(wq, wk, wv, wo, w1, w2, ho1, ho2, he1, bq, bk, bv);
    embed_kernel<<<NTOK, 256>>>(tokens, pos_emb, emb_obs, emb_act, x);

    #define GG(M_, N_) dim3((N_)/BN, ((M_)+BM-1)/BM)
    for (int l = 0; l < LL; ++l){
        size_t dd = (size_t)l*DD_;
        ln_kernel<<<NTOK, 256>>>(x, ln1_g+l*DDIM, ln1_b+l*DDIM, h_hi, h_lo);
        tcgemm<0,0><<<GG(NTOK, 3*DDIM), 256, GEMM_SMEM>>>(
            h_hi, h_lo, wt_hi+WQKV_OFF+(size_t)l*3*DD_, wt_lo+WQKV_OFF+(size_t)l*3*DD_,
            bqkv+(size_t)l*3*DDIM, qkv, nullptr, nullptr, nullptr, nullptr, NTOK, 3*DDIM, DDIM);
        attn_kernel<<<dim3((SS+63)/64, BB*HH), 64>>>(qkv, o_hi, o_lo);
        tcgemm<0,0><<<GG(NTOK, DDIM), 256, GEMM_SMEM>>>(
            o_hi, o_lo, wt_hi+WO_OFF+dd, wt_lo+WO_OFF+dd,
            bo+l*DDIM, x, nullptr, nullptr, x, nullptr, NTOK, DDIM, DDIM);
        ln_kernel<<<NTOK, 256>>>(x, ln2_g+l*DDIM, ln2_b+l*DDIM, h_hi, h_lo);
        tcgemm<1,1><<<GG(NTOK, FF), 256, GEMM_SMEM>>>(
            h_hi, h_lo, wt_hi+W1_OFF+(size_t)l*DF_, wt_lo+W1_OFF+(size_t)l*DF_,
            b1+(size_t)l*FF, nullptr, mid_hi, mid_lo, nullptr, nullptr, NTOK, FF, DDIM);
        tcgemm<0,0><<<GG(NTOK, DDIM), 256, GEMM_SMEM>>>(
            mid_hi, mid_lo, wt_hi+W2_OFF+(size_t)l*DF_, wt_lo+W2_OFF+(size_t)l*DF_,
            b2+l*DDIM, x, nullptr, nullptr, x, nullptr, NTOK, DDIM, FF);
    }

    ln_kernel<<<NTOK, 256>>>(x, lnf_g, lnf_b, h_hi, h_lo);

    tcgemm<2,1><<<GG(NOBS, DDIM), 256, GEMM_SMEM>>>(
        h_hi, h_lo, wt_hi+HO1_OFF, wt_lo+HO1_OFF, bo1,
        nullptr, t1_hi, t1_lo, nullptr, obsr, NOBS, DDIM, DDIM);
    tcgemm<0,0><<<GG(NOBS, VOBS_), 256, GEMM_SMEM>>>(
        t1_hi, t1_lo, wt_hi+HO2_OFF, wt_lo+HO2_OFF, bo2,
        out, nullptr, nullptr, nullptr, nullptr, NOBS, VOBS_, DDIM);

    tcgemm<2,0><<<GG(NACT, DDIM), 256, GEMM_SMEM>>>(
        h_hi, h_lo, wt_hi+HE1_OFF, wt_lo+HE1_OFF, be1,
        t2, nullptr, nullptr, nullptr, actr, NACT, DDIM, DDIM);
    head_ends_kernel<<<NACT, 128>>>(t2, he2, be2, out + (size_t)NOBS*VOBS_);
}

// round 11
// speedup vs baseline: 1.0339x; 1.0143x over previous
#include <cuda_runtime.h>
#include <cuda_bf16.h>
#include <math.h>
#include <stdint.h>

typedef __nv_bfloat16 bf16;

#define BB 4
#define SS 1020
#define DDIM 1024
#define HH 16
#define DH 64
#define LL 4
#define TPB_ 17
#define FF 4096
#define NTOK (BB*SS)
#define NOBS (BB*960)
#define NACT (BB*60)
#define VOBS_ 4096
#define VACT_ 16
#define DD_ (DDIM*DDIM)
#define DF_ (DDIM*FF)

// ---------------- static scratch ----------------
__device__ __align__(256) float g_x[NTOK*DDIM];
__device__ __align__(256) float g_qkv[NTOK*3*DDIM];
__device__ __align__(256) float g_t2[NACT*DDIM];
__device__ __align__(256) bf16 g_h_hi[NTOK*DDIM];
__device__ __align__(256) bf16 g_h_lo[NTOK*DDIM];
__device__ __align__(256) bf16 g_o_hi[NTOK*DDIM];
__device__ __align__(256) bf16 g_o_lo[NTOK*DDIM];
__device__ __align__(256) bf16 g_mid_hi[NTOK*FF];
__device__ __align__(256) bf16 g_mid_lo[NTOK*FF];
__device__ __align__(256) bf16 g_t1_hi[NOBS*DDIM];
__device__ __align__(256) bf16 g_t1_lo[NOBS*DDIM];
__device__ float g_bqkv[LL*3*DDIM];
__device__ int g_obs_rows[NOBS];
__device__ int g_act_rows[NACT];

#define WQKV_OFF 0
#define WO_OFF  (WQKV_OFF + LL*3*DD_)
#define W1_OFF  (WO_OFF + LL*DD_)
#define W2_OFF  (W1_OFF + LL*DF_)
#define HO1_OFF (W2_OFF + LL*DF_)
#define HO2_OFF (HO1_OFF + DD_)
#define HE1_OFF (HO2_OFF + VOBS_*DDIM)
#define WT_TOT  (HE1_OFF + DD_)
__device__ __align__(256) bf16 g_wt_hi[WT_TOT];
__device__ __align__(256) bf16 g_wt_lo[WT_TOT];

// ---------------- PTX helpers ----------------
__device__ __forceinline__ uint32_t s2u(const void* p){ return (uint32_t)__cvta_generic_to_shared(p); }
__device__ __forceinline__ void cp16(uint32_t d, const void* s){
    asm volatile("cp.async.cg.shared.global [%0], [%1], 16;\n"::"r"(d),"l"(s));
}
#define CP_COMMIT() asm volatile("cp.async.commit_group;\n":::"memory")
#define CP_WAIT2()  asm volatile("cp.async.wait_group 2;\n":::"memory")
#define CP_WAIT0()  asm volatile("cp.async.wait_group 0;\n":::"memory")

#define SWZ64(o) ((o) ^ (((o)>>3)&0x30))

#define LDM4(r0,r1,r2,r3,a) \
    asm volatile("ldmatrix.sync.aligned.m8n8.x4.shared.b16 {%0,%1,%2,%3}, [%4];" \
        : "=r"(r0),"=r"(r1),"=r"(r2),"=r"(r3) : "r"(a))

#define MMA16816(c,a,b0,b1) \
    asm volatile("mma.sync.aligned.m16n8k16.row.col.f32.bf16.bf16.f32 " \
        "{%0,%1,%2,%3}, {%4,%5,%6,%7}, {%8,%9}, {%0,%1,%2,%3};" \
        : "+f"((c)[0]),"+f"((c)[1]),"+f"((c)[2]),"+f"((c)[3]) \
        : "r"((a)[0]),"r"((a)[1]),"r"((a)[2]),"r"((a)[3]), "r"(b0),"r"(b1))

// ---------------- mma.sync split-bf16 GEMM (2 CTA/SM) ----------------
#define BM 128
#define BN 128
#define STG 32768
#define GEMM_SMEM (3*STG)

template<int ACT, int OUTBF>
__global__ __launch_bounds__(256, 2)
void tcgemm(const bf16* __restrict__ Ah, const bf16* __restrict__ Al,
            const bf16* __restrict__ Bh, const bf16* __restrict__ Bl,
            const float* __restrict__ bias,
            float* __restrict__ C, bf16* __restrict__ Ch, bf16* __restrict__ Cl,
            const float* __restrict__ resid, const int* __restrict__ rowmap,
            int M, int N, int K)
{
    extern __shared__ char smem[];
    uint32_t sb = s2u(smem);
    int tid = threadIdx.x, lane = tid&31, wid = tid>>5;
    int wm = wid&1, wn = wid>>1;
    int m0 = blockIdx.y*BM, n0 = blockIdx.x*BN;

    size_t aOff[2]; uint32_t aSw[2];
    size_t bOff[2]; uint32_t bSw[2];
    #pragma unroll
    for (int i=0;i<2;++i){
        int t = tid+256*i, r = t>>2, c = t&3;
        int am = m0+r; if (am > M-1) am = M-1;
        int ar = rowmap ? rowmap[am] : am;
        aOff[i] = (size_t)ar*K + c*8;
        bOff[i] = (size_t)(n0+r)*K + c*8;
        uint32_t o = r*64 + c*16;
        aSw[i] = SWZ64(o);
        bSw[i] = SWZ64(o);
    }

    const int NC = K/32;
    #define LOAD_STAGE(s_, ck_) do { \
        uint32_t aH_ = sb + (s_)*STG, aL_ = aH_ + 8192; \
        uint32_t bH_ = aH_ + 16384,  bL_ = aH_ + 24576; \
        size_t ko_ = (size_t)(ck_)*32; \
        _Pragma("unroll") \
        for (int i=0;i<2;++i){ cp16(aH_+aSw[i], Ah+aOff[i]+ko_); cp16(aL_+aSw[i], Al+aOff[i]+ko_); } \
        _Pragma("unroll") \
        for (int i=0;i<2;++i){ cp16(bH_+bSw[i], Bh+bOff[i]+ko_); cp16(bL_+bSw[i], Bl+bOff[i]+ko_); } \
    } while(0)

    LOAD_STAGE(0, 0); CP_COMMIT();
    LOAD_STAGE(1, 1); CP_COMMIT();

    int rA  = wm*64 + (lane&15);
    int kbA = (lane>>4)*16;
    int rB  = wn*32 + (lane&7) + ((lane>>4)<<3);
    int kbB = ((lane>>3)&1)*16;

    float acc[4][4][4];
    #pragma unroll
    for (int i=0;i<4;++i)
        #pragma unroll
        for (int j=0;j<4;++j)
            #pragma unroll
            for (int r=0;r<4;++r) acc[i][j][r]=0.f;

    for (int ck=0; ck<NC; ++ck){
        if (ck+2 < NC){ LOAD_STAGE((ck+2)%3, ck+2); CP_COMMIT(); CP_WAIT2(); }
        else CP_WAIT0();
        __syncthreads();
        uint32_t base = sb + (ck%3)*STG;
        uint32_t uaH = base, uaL = base + 8192;
        uint32_t ubH = base + 16384, ubL = base + 24576;
        #pragma unroll
        for (int ks=0; ks<2; ++ks){
            uint32_t bh[2][4], bl[2][4];
            #pragma unroll
            for (int ng=0;ng<2;++ng){
                uint32_t o = (uint32_t)(rB + ng*16)*64 + ks*32 + kbB;
                o = SWZ64(o);
                LDM4(bh[ng][0],bh[ng][1],bh[ng][2],bh[ng][3], ubH + o);
                LDM4(bl[ng][0],bl[ng][1],bl[ng][2],bl[ng][3], ubL + o);
            }
            #pragma unroll
            for (int mi=0;mi<4;++mi){
                uint32_t ah[4], al[4];
                uint32_t o = (uint32_t)(rA + mi*16)*64 + ks*32 + kbA;
                o = SWZ64(o);
                LDM4(ah[0],ah[1],ah[2],ah[3], uaH + o);
                LDM4(al[0],al[1],al[2],al[3], uaL + o);
                #pragma unroll
                for (int ng=0;ng<2;++ng){
                    #pragma unroll
                    for (int j=0;j<2;++j){
                        MMA16816(acc[mi][ng*2+j], ah, bh[ng][j*2], bh[ng][j*2+1]);
                        MMA16816(acc[mi][ng*2+j], ah, bl[ng][j*2], bl[ng][j*2+1]);
                        MMA16816(acc[mi][ng*2+j], al, bh[ng][j*2], bh[ng][j*2+1]);
                    }
                }
            }
        }
        __syncthreads();
    }

    int g = lane>>2, tg = lane&3;
    #pragma unroll
    for (int mi=0;mi<4;++mi){
        #pragma unroll
        for (int half=0; half<2; ++half){
            int m = m0 + wm*64 + mi*16 + g + half*8;
            if (m < M){
                #pragma unroll
                for (int nj=0;nj<4;++nj){
                    int n = n0 + wn*32 + nj*8 + tg*2;
                    float v0 = acc[mi][nj][half*2+0] + __ldg(bias+n);
                    float v1 = acc[mi][nj][half*2+1] + __ldg(bias+n+1);
                    if (ACT==1){
                        v0 = 0.5f*v0*(1.0f+erff(v0*0.70710678118654752f));
                        v1 = 0.5f*v1*(1.0f+erff(v1*0.70710678118654752f));
                    }
                    if (ACT==2){ v0 = fmaxf(v0,0.f); v1 = fmaxf(v1,0.f); }
                    if (resid){
                        float2 rr = *(const float2*)(resid + (size_t)m*N + n);
                        v0 += rr.x; v1 += rr.y;
                    }
                    if (OUTBF==0){
                        float2 w; w.x=v0; w.y=v1;
                        *(float2*)(C + (size_t)m*N + n) = w;
                    } else {
                        bf16 h0=__float2bfloat16(v0), h1=__float2bfloat16(v1);
                        __nv_bfloat162 H; H.x=h0; H.y=h1;
                        __nv_bfloat162 L;
                        L.x=__float2bfloat16(v0-__bfloat162float(h0));
                        L.y=__float2bfloat16(v1-__bfloat162float(h1));
                        *(__nv_bfloat162*)(Ch + (size_t)m*N + n) = H;
                        *(__nv_bfloat162*)(Cl + (size_t)m*N + n) = L;
                    }
                }
            }
        }
    }
}

// ---------------- fused prologue: weight transpose/split + biases + idx + EMBED ----------------
#define CV_MAIN 27648
#define CV_AUX  64
__global__ void convert_all(const float* __restrict__ wq, const float* __restrict__ wk,
                            const float* __restrict__ wv, const float* __restrict__ wo,
                            const float* __restrict__ w1, const float* __restrict__ w2,
                            const float* __restrict__ ho1, const float* __restrict__ ho2,
                            const float* __restrict__ he1,
                            const float* __restrict__ bq, const float* __restrict__ bk,
                            const float* __restrict__ bv,
                            const int* __restrict__ tokens, const float* __restrict__ pos_emb,
                            const float* __restrict__ emb_obs, const float* __restrict__ emb_act)
{
    int t = blockIdx.x;
    int tid = threadIdx.y*32 + threadIdx.x;
    if (t >= CV_MAIN + CV_AUX){
        // embed: one row per block
        int row = t - (CV_MAIN + CV_AUX);
        int s = row % SS;
        int tok = tokens[row];
        bool is_obs = (s % TPB_) < (TPB_-1);
        const float* e = is_obs ? (emb_obs + (size_t)min(tok,VOBS_-1)*DDIM)
                                : (emb_act + (size_t)min(tok,VACT_-1)*DDIM);
        const float* pe = pos_emb + (size_t)s*DDIM;
        float* xo = g_x + (size_t)row*DDIM;
        for (int d = tid; d < DDIM; d += 256) xo[d] = e[d] + pe[d];
        return;
    }
    if (t >= CV_MAIN){
        int idx = (t - CV_MAIN)*256 + tid;
        if (idx < LL*3*DDIM){
            int l = idx/(3*DDIM), r = idx%(3*DDIM), part = r/DDIM, d = r%DDIM;
            const float* src = part==0 ? bq : (part==1 ? bk : bv);
            g_bqkv[idx] = src[l*DDIM + d];
        }
        int j = idx - LL*3*DDIM;
        if (j >= 0 && j < NOBS){
            int b = j/960, jj = j%960, blk = jj/16, r = jj%16;
            g_obs_rows[j] = b*SS + blk*TPB_ + (r<15 ? r : 16);
        }
        if (j >= 0 && j < NACT){
            int b = j/60, blk = j%60;
            g_act_rows[j] = b*SS + blk*TPB_ + (TPB_-1);
        }
        return;
    }
    const float* src; int doff, K, N, base; size_t inMS, outMS;
    if      (t <  2048){ src=wq;  doff=WQKV_OFF;        K=DDIM; N=DDIM;  inMS=DD_; outMS=3*DD_; base=0; }
    else if (t <  4096){ src=wk;  doff=WQKV_OFF+DD_;    K=DDIM; N=DDIM;  inMS=DD_; outMS=3*DD_; base=2048; }
    else if (t <  6144){ src=wv;  doff=WQKV_OFF+2*DD_;  K=DDIM; N=DDIM;  inMS=DD_; outMS=3*DD_; base=4096; }
    else if (t <  8192){ src=wo;  doff=WO_OFF;          K=DDIM; N=DDIM;  inMS=DD_; outMS=DD_;   base=6144; }
    else if (t < 16384){ src=w1;  doff=W1_OFF;          K=DDIM; N=FF;    inMS=DF_; outMS=DF_;   base=8192; }
    else if (t < 24576){ src=w2;  doff=W2_OFF;          K=FF;   N=DDIM;  inMS=DF_; outMS=DF_;   base=16384; }
    else if (t < 25088){ src=ho1; doff=HO1_OFF;         K=DDIM; N=DDIM;  inMS=0;   outMS=0;     base=24576; }
    else if (t < 27136){ src=ho2; doff=HO2_OFF;         K=DDIM; N=VOBS_; inMS=0;   outMS=0;     base=25088; }
    else               { src=he1; doff=HE1_OFF;         K=DDIM; N=DDIM;  inMS=0;   outMS=0;     base=27136; }
    int r = t - base;
    int nt = N/32;
    int tpz = (K/64)*nt;
    int z = r/tpz, rr = r%tpz;
    int k0 = (rr/nt)*64, n0 = (rr%nt)*32;

    const float* Wm = src + (size_t)z*inMS;
    bf16* Whm = g_wt_hi + doff + (size_t)z*outMS;
    bf16* Wlm = g_wt_lo + doff + (size_t)z*outMS;

    __shared__ float tsh[64][33];
    int tx = threadIdx.x, ty = threadIdx.y;
    #pragma unroll
    for (int i=0;i<8;++i)
        tsh[ty+8*i][tx] = Wm[(size_t)(k0+ty+8*i)*N + n0+tx];
    __syncthreads();
    #pragma unroll
    for (int i=0;i<4;++i){
        int nn = ty + 8*i;
        float v0 = tsh[tx*2][nn], v1 = tsh[tx*2+1][nn];
        bf16 h0 = __float2bfloat16(v0), h1 = __float2bfloat16(v1);
        __nv_bfloat162 H; H.x=h0; H.y=h1;
        __nv_bfloat162 L;
        L.x = __float2bfloat16(v0-__bfloat162float(h0));
        L.y = __float2bfloat16(v1-__bfloat162float(h1));
        size_t o = (size_t)(n0+nn)*K + k0 + tx*2;
        *(__nv_bfloat162*)(Whm+o) = H;
        *(__nv_bfloat162*)(Wlm+o) = L;
    }
}

// ---------------- LN -> split bf16 ----------------
__device__ __forceinline__ float bsum256(float v)
{
    __shared__ float sh[8];
    int ln = threadIdx.x&31, w = threadIdx.x>>5;
    #pragma unroll
    for (int o=16;o>0;o>>=1) v += __shfl_xor_sync(0xffffffffu, v, o);
    if (ln==0) sh[w]=v;
    __syncthreads();
    if (w==0){
        float t = (ln<8)?sh[ln]:0.f;
        #pragma unroll
        for (int o=4;o>0;o>>=1) t += __shfl_xor_sync(0xffffffffu, t, o);
        if (ln==0) sh[0]=t;
    }
    __syncthreads();
    float r = sh[0];
    __syncthreads();
    return r;
}

__global__ void ln_kernel(const float* __restrict__ x, const float* __restrict__ g,
                          const float* __restrict__ b, bf16* __restrict__ oh, bf16* __restrict__ ol)
{
    int row = blockIdx.x, t = threadIdx.x;
    const float* xr = x + (size_t)row*DDIM;
    float v[4]; float s = 0.f;
    #pragma unroll
    for (int i=0;i<4;++i){ v[i]=xr[t+256*i]; s+=v[i]; }
    float mean = bsum256(s) * (1.f/DDIM);
    float q = 0.f;
    #pragma unroll
    for (int i=0;i<4;++i){ float d=v[i]-mean; q+=d*d; }
    float rstd = rsqrtf(bsum256(q)*(1.f/DDIM) + 1e-3f);
    #pragma unroll
    for (int i=0;i<4;++i){
        int idx = t+256*i;
        float y = (v[i]-mean)*rstd*g[idx] + b[idx];
        bf16 h = __float2bfloat16(y);
        oh[(size_t)row*DDIM+idx] = h;
        ol[(size_t)row*DDIM+idx] = __float2bfloat16(y-__bfloat162float(h));
    }
}

// ---------------- attention (64 thr/blk, 4-way ILP dot) ----------------
__global__ void attn_kernel(const float* __restrict__ qkv,
                            bf16* __restrict__ o_hi, bf16* __restrict__ o_lo)
{
    const int RS = 3*DDIM;
    int bh = blockIdx.y, b = bh>>4, h = bh&15;
    int qt = blockIdx.x, tid = threadIdx.x;
    int i = qt*64 + tid;
    bool valid = i < SS;
    int irow = valid ? i : SS-1;
    size_t rb = (size_t)b*SS;

    float qreg[64];
    {
        const float4* q4 = (const float4*)(qkv + (rb+irow)*RS + h*DH);
        #pragma unroll
        for (int d=0;d<16;++d){
            float4 t = q4[d];
            qreg[4*d]=t.x; qreg[4*d+1]=t.y; qreg[4*d+2]=t.z; qreg[4*d+3]=t.w;
        }
    }
    __shared__ float4 Ksh[64][16];
    __shared__ float4 Vsh[64][16];
    float oacc[64];
    #pragma unroll
    for (int d=0;d<64;++d) oacc[d]=0.f;
    float m = -1e30f, l = 0.f;
    const float scale = 0.125f;

    for (int kt=0; kt<=qt; ++kt){
        int j0 = kt*64, nk = min(64, SS-j0);
        __syncthreads();
        #pragma unroll
        for (int it=0;it<16;++it){
            int idx = it*64+tid, j = idx>>4, d4 = idx&15;
            if (j < nk){
                Ksh[j][d4] = *(const float4*)(qkv + (rb+j0+j)*RS + DDIM + h*DH + 4*d4);
                Vsh[j][d4] = *(const float4*)(qkv + (rb+j0+j)*RS + 2*DDIM + h*DH + 4*d4);
            }
        }
        __syncthreads();
        if (valid){
            const float* Ks = (const float*)Ksh;
            const float* Vs = (const float*)Vsh;
            int je = min(nk, i-j0+1);
            for (int j=0;j<je;++j){
                const float* kr = Ks + j*64;
                float p0=0.f,p1=0.f,p2=0.f,p3=0.f;
                #pragma unroll
                for (int d=0;d<64;d+=4){
                    p0 = fmaf(qreg[d+0], kr[d+0], p0);
                    p1 = fmaf(qreg[d+1], kr[d+1], p1);
                    p2 = fmaf(qreg[d+2], kr[d+2], p2);
                    p3 = fmaf(qreg[d+3], kr[d+3], p3);
                }
                float s = ((p0+p1)+(p2+p3))*scale;
                const float* vr = Vs + j*64;
                if (s > m){
                    float c = __expf(m-s);
                    l = l*c + 1.f;
                    #pragma unroll
                    for (int d=0;d<64;++d) oacc[d] = fmaf(oacc[d], c, vr[d]);
                    m = s;
                } else {
                    float p = __expf(s-m);
                    l += p;
                    #pragma unroll
                    for (int d=0;d<64;++d) oacc[d] = fmaf(p, vr[d], oacc[d]);
                }
            }
        }
    }
    if (valid){
        float inv = 1.f/l;
        size_t ob = (rb+irow)*DDIM + h*DH;
        #pragma unroll
        for (int d=0;d<64;++d){
            float val = oacc[d]*inv;
            bf16 hh = __float2bfloat16(val);
            o_hi[ob+d] = hh;
            o_lo[ob+d] = __float2bfloat16(val-__bfloat162float(hh));
        }
    }
}

// ---------------- tiny N=2 head ----------------
__global__ void head_ends_kernel(const float* __restrict__ t2, const float* __restrict__ w,
                                 const float* __restrict__ bias, float* __restrict__ out)
{
    int r = blockIdx.x, tid = threadIdx.x;
    const float* a = t2 + (size_t)r*DDIM;
    float s0 = 0.f, s1 = 0.f;
    for (int k = tid; k < DDIM; k += 128){
        float av = a[k];
        s0 = fmaf(av, w[k*2], s0);
        s1 = fmaf(av, w[k*2+1], s1);
    }
    __shared__ float red[128];
    red[tid]=s0; __syncthreads();
    for (int st=64;st>0;st>>=1){ if (tid<st) red[tid]+=red[tid+st]; __syncthreads(); }
    if (tid==0) out[r*2] = red[0]+bias[0];
    __syncthreads();
    red[tid]=s1; __syncthreads();
    for (int st=64;st>0;st>>=1){ if (tid<st) red[tid]+=red[tid+st]; __syncthreads(); }
    if (tid==0) out[r*2+1] = red[0]+bias[1];
}

// ---------------- launch ----------------
extern "C" void kernel_launch(void* const* d_in, const int* in_sizes, int n_in,
                              void* d_out, int out_size)
{
    const int* tokens = (const int*)d_in[0];
    const float *pos_emb=(const float*)d_in[1], *emb_obs=(const float*)d_in[2], *emb_act=(const float*)d_in[3];
    const float *ln1_g=(const float*)d_in[4], *ln1_b=(const float*)d_in[5];
    const float *wq=(const float*)d_in[6], *bq=(const float*)d_in[7];
    const float *wk=(const float*)d_in[8], *bk=(const float*)d_in[9];
    const float *wv=(const float*)d_in[10], *bv=(const float*)d_in[11];
    const float *wo=(const float*)d_in[12], *bo=(const float*)d_in[13];
    const float *ln2_g=(const float*)d_in[14], *ln2_b=(const float*)d_in[15];
    const float *w1=(const float*)d_in[16], *b1=(const float*)d_in[17];
    const float *w2=(const float*)d_in[18], *b2=(const float*)d_in[19];
    const float *lnf_g=(const float*)d_in[20], *lnf_b=(const float*)d_in[21];
    const float *ho1=(const float*)d_in[22], *bo1=(const float*)d_in[23];
    const float *ho2=(const float*)d_in[24], *bo2=(const float*)d_in[25];
    const float *he1=(const float*)d_in[26], *be1=(const float*)d_in[27];
    const float *he2=(const float*)d_in[28], *be2=(const float*)d_in[29];
    float* out = (float*)d_out;

    float *x,*qkv,*t2,*bqkv;
    bf16 *h_hi,*h_lo,*o_hi,*o_lo,*mid_hi,*mid_lo,*t1_hi,*t1_lo,*wt_hi,*wt_lo;
    int *obsr,*actr;
    cudaGetSymbolAddress((void**)&x, g_x);
    cudaGetSymbolAddress((void**)&qkv, g_qkv);
    cudaGetSymbolAddress((void**)&t2, g_t2);
    cudaGetSymbolAddress((void**)&bqkv, g_bqkv);
    cudaGetSymbolAddress((void**)&h_hi, g_h_hi);
    cudaGetSymbolAddress((void**)&h_lo, g_h_lo);
    cudaGetSymbolAddress((void**)&o_hi, g_o_hi);
    cudaGetSymbolAddress((void**)&o_lo, g_o_lo);
    cudaGetSymbolAddress((void**)&mid_hi, g_mid_hi);
    cudaGetSymbolAddress((void**)&mid_lo, g_mid_lo);
    cudaGetSymbolAddress((void**)&t1_hi, g_t1_hi);
    cudaGetSymbolAddress((void**)&t1_lo, g_t1_lo);
    cudaGetSymbolAddress((void**)&wt_hi, g_wt_hi);
    cudaGetSymbolAddress((void**)&wt_lo, g_wt_lo);
    cudaGetSymbolAddress((void**)&obsr, g_obs_rows);
    cudaGetSymbolAddress((void**)&actr, g_act_rows);

    cudaFuncSetAttribute(tcgemm<0,0>, cudaFuncAttributeMaxDynamicSharedMemorySize, GEMM_SMEM);
    cudaFuncSetAttribute(tcgemm<1,1>, cudaFuncAttributeMaxDynamicSharedMemorySize, GEMM_SMEM);
    cudaFuncSetAttribute(tcgemm<2,1>, cudaFuncAttributeMaxDynamicSharedMemorySize, GEMM_SMEM);
    cudaFuncSetAttribute(tcgemm<2,0>, cudaFuncAttributeMaxDynamicSharedMemorySize, GEMM_SMEM);

    // launch #1: weights + biases + idx + embed (all independent prologue work)
    convert_all<<<CV_MAIN + CV_AUX + NTOK, dim3(32,8)>>>(
        wq, wk, wv, wo, w1, w2, ho1, ho2, he1, bq, bk, bv,
        tokens, pos_emb, emb_obs, emb_act);

    #define GG(M_, N_) dim3((N_)/BN, ((M_)+BM-1)/BM)
    for (int l = 0; l < LL; ++l){
        size_t dd = (size_t)l*DD_;
        // l=0: ln=#2, QKV=#3, attn=#4 (ncu capture target)
        ln_kernel<<<NTOK, 256>>>(x, ln1_g+l*DDIM, ln1_b+l*DDIM, h_hi, h_lo);
        tcgemm<0,0><<<GG(NTOK, 3*DDIM), 256, GEMM_SMEM>>>(
            h_hi, h_lo, wt_hi+WQKV_OFF+(size_t)l*3*DD_, wt_lo+WQKV_OFF+(size_t)l*3*DD_,
            bqkv+(size_t)l*3*DDIM, qkv, nullptr, nullptr, nullptr, nullptr, NTOK, 3*DDIM, DDIM);
        attn_kernel<<<dim3((SS+63)/64, BB*HH), 64>>>(qkv, o_hi, o_lo);
        tcgemm<0,0><<<GG(NTOK, DDIM), 256, GEMM_SMEM>>>(
            o_hi, o_lo, wt_hi+WO_OFF+dd, wt_lo+WO_OFF+dd,
            bo+l*DDIM, x, nullptr, nullptr, x, nullptr, NTOK, DDIM, DDIM);
        ln_kernel<<<NTOK, 256>>>(x, ln2_g+l*DDIM, ln2_b+l*DDIM, h_hi, h_lo);
        tcgemm<1,1><<<GG(NTOK, FF), 256, GEMM_SMEM>>>(
            h_hi, h_lo, wt_hi+W1_OFF+(size_t)l*DF_, wt_lo+W1_OFF+(size_t)l*DF_,
            b1+(size_t)l*FF, nullptr, mid_hi, mid_lo, nullptr, nullptr, NTOK, FF, DDIM);
        tcgemm<0,0><<<GG(NTOK, DDIM), 256, GEMM_SMEM>>>(
            mid_hi, mid_lo, wt_hi+W2_OFF+(size_t)l*DF_, wt_lo+W2_OFF+(size_t)l*DF_,
            b2+l*DDIM, x, nullptr, nullptr, x, nullptr, NTOK, DDIM, FF);
    }

    ln_kernel<<<NTOK, 256>>>(x, lnf_g, lnf_b, h_hi, h_lo);

    tcgemm<2,1><<<GG(NOBS, DDIM), 256, GEMM_SMEM>>>(
        h_hi, h_lo, wt_hi+HO1_OFF, wt_lo+HO1_OFF, bo1,
        nullptr, t1_hi, t1_lo, nullptr, obsr, NOBS, DDIM, DDIM);
    tcgemm<0,0><<<GG(NOBS, VOBS_), 256, GEMM_SMEM>>>(
        t1_hi, t1_lo, wt_hi+HO2_OFF, wt_lo+HO2_OFF, bo2,
        out, nullptr, nullptr, nullptr, nullptr, NOBS, VOBS_, DDIM);

    tcgemm<2,0><<<GG(NACT, DDIM), 256, GEMM_SMEM>>>(
        h_hi, h_lo, wt_hi+HE1_OFF, wt_lo+HE1_OFF, be1,
        t2, nullptr, nullptr, nullptr, actr, NACT, DDIM, DDIM);
    head_ends_kernel<<<NACT, 128>>>(t2, he2, be2, out + (size_t)NOBS*VOBS_);
}

// round 13
// speedup vs baseline: 1.3360x; 1.2922x over previous
#include <cuda_runtime.h>
#include <cuda_bf16.h>
#include <math.h>
#include <stdint.h>

typedef __nv_bfloat16 bf16;

#define BB 4
#define SS 1020
#define DDIM 1024
#define HH 16
#define DH 64
#define LL 4
#define TPB_ 17
#define FF 4096
#define NTOK (BB*SS)
#define NOBS (BB*960)
#define NACT (BB*60)
#define VOBS_ 4096
#define VACT_ 16
#define DD_ (DDIM*DDIM)
#define DF_ (DDIM*FF)
#define SPAD 1024
#define NBH (BB*HH)

// ---------------- static scratch ----------------
__device__ __align__(256) float g_x[NTOK*DDIM];
__device__ __align__(256) float g_t2[NACT*DDIM];
__device__ __align__(256) bf16 g_qkv_hi[NTOK*3*DDIM];
__device__ __align__(256) bf16 g_qkv_lo[NTOK*3*DDIM];
__device__ __align__(256) float g_S[(size_t)NBH*SS*SPAD];
__device__ __align__(256) bf16 g_P_hi[(size_t)NBH*SS*SPAD];
__device__ __align__(256) bf16 g_P_lo[(size_t)NBH*SS*SPAD];
__device__ __align__(256) bf16 g_vT_hi[NBH*DH*SPAD];
__device__ __align__(256) bf16 g_vT_lo[NBH*DH*SPAD];
__device__ __align__(256) bf16 g_h_hi[NTOK*DDIM];
__device__ __align__(256) bf16 g_h_lo[NTOK*DDIM];
__device__ __align__(256) bf16 g_o_hi[NTOK*DDIM];
__device__ __align__(256) bf16 g_o_lo[NTOK*DDIM];
__device__ __align__(256) bf16 g_mid_hi[NTOK*FF];
__device__ __align__(256) bf16 g_mid_lo[NTOK*FF];
__device__ __align__(256) bf16 g_t1_hi[NOBS*DDIM];
__device__ __align__(256) bf16 g_t1_lo[NOBS*DDIM];
__device__ float g_bqkv[LL*3*DDIM];
__device__ int g_obs_rows[NOBS];
__device__ int g_act_rows[NACT];

#define WQKV_OFF 0
#define WO_OFF  (WQKV_OFF + LL*3*DD_)
#define W1_OFF  (WO_OFF + LL*DD_)
#define W2_OFF  (W1_OFF + LL*DF_)
#define HO1_OFF (W2_OFF + LL*DF_)
#define HO2_OFF (HO1_OFF + DD_)
#define HE1_OFF (HO2_OFF + VOBS_*DDIM)
#define WT_TOT  (HE1_OFF + DD_)
__device__ __align__(256) bf16 g_wt_hi[WT_TOT];
__device__ __align__(256) bf16 g_wt_lo[WT_TOT];

// ---------------- PTX helpers ----------------
__device__ __forceinline__ uint32_t s2u(const void* p){ return (uint32_t)__cvta_generic_to_shared(p); }
__device__ __forceinline__ void cp16(uint32_t d, const void* s){
    asm volatile("cp.async.cg.shared.global [%0], [%1], 16;\n"::"r"(d),"l"(s));
}
#define CP_COMMIT() asm volatile("cp.async.commit_group;\n":::"memory")
#define CP_WAIT1()  asm volatile("cp.async.wait_group 1;\n":::"memory")
#define CP_WAIT0()  asm volatile("cp.async.wait_group 0;\n":::"memory")

#define SWZ64(o)  ((o) ^ (((o)>>3)&0x30))
#define SWZ128(o) ((o) ^ (((o)>>3)&0x70))

#define LDM4(r0,r1,r2,r3,a) \
    asm volatile("ldmatrix.sync.aligned.m8n8.x4.shared.b16 {%0,%1,%2,%3}, [%4];" \
        : "=r"(r0),"=r"(r1),"=r"(r2),"=r"(r3) : "r"(a))

#define MMA16816(c,a,b0,b1) \
    asm volatile("mma.sync.aligned.m16n8k16.row.col.f32.bf16.bf16.f32 " \
        "{%0,%1,%2,%3}, {%4,%5,%6,%7}, {%8,%9}, {%0,%1,%2,%3};" \
        : "+f"((c)[0]),"+f"((c)[1]),"+f"((c)[2]),"+f"((c)[3]) \
        : "r"((a)[0]),"r"((a)[1]),"r"((a)[2]),"r"((a)[3]), "r"(b0),"r"(b1))

__device__ __forceinline__ void split_store(bf16* Ph, bf16* Pl, size_t off, float v0, float v1){
    bf16 h0=__float2bfloat16(v0), h1=__float2bfloat16(v1);
    __nv_bfloat162 H; H.x=h0; H.y=h1;
    __nv_bfloat162 L;
    L.x=__float2bfloat16(v0-__bfloat162float(h0));
    L.y=__float2bfloat16(v1-__bfloat162float(h1));
    *(__nv_bfloat162*)(Ph+off)=H;
    *(__nv_bfloat162*)(Pl+off)=L;
}

// ---------------- mma.sync split-bf16 GEMM (R8 proven config) ----------------
#define BM 128
#define BN 128
#define STG 32768
#define GEMM_SMEM (3*STG)

template<int ACT, int OUTBF>
__global__ __launch_bounds__(256, 2)
void tcgemm(const bf16* __restrict__ Ah, const bf16* __restrict__ Al,
            const bf16* __restrict__ Bh, const bf16* __restrict__ Bl,
            const float* __restrict__ bias,
            float* __restrict__ C, bf16* __restrict__ Ch, bf16* __restrict__ Cl,
            const float* __restrict__ resid, const int* __restrict__ rowmap,
            int M, int N, int K)
{
    extern __shared__ char smem[];
    uint32_t sb = s2u(smem);
    int tid = threadIdx.x, lane = tid&31, wid = tid>>5;
    int wm = wid&1, wn = wid>>1;
    int m0 = blockIdx.y*BM, n0 = blockIdx.x*BN;

    size_t aOff[2], bOff[2]; uint32_t aSw[2];
    #pragma unroll
    for (int i=0;i<2;++i){
        int t = tid+256*i, r = t>>2, c = t&3;
        int am = m0+r; if (am > M-1) am = M-1;
        int ar = rowmap ? rowmap[am] : am;
        aOff[i] = (size_t)ar*K + c*8;
        bOff[i] = (size_t)(n0+r)*K + c*8;
        uint32_t o = r*64 + c*16;
        aSw[i] = SWZ64(o);
    }

    const int NC = K/32;
    #define LOAD_STAGE(s_, ck_) do { \
        uint32_t aH_ = sb + (s_)*STG, aL_ = aH_ + 8192; \
        uint32_t bH_ = aH_ + 16384,  bL_ = aH_ + 24576; \
        size_t ko_ = (size_t)(ck_)*32; \
        _Pragma("unroll") \
        for (int i=0;i<2;++i){ cp16(aH_+aSw[i], Ah+aOff[i]+ko_); cp16(aL_+aSw[i], Al+aOff[i]+ko_); } \
        _Pragma("unroll") \
        for (int i=0;i<2;++i){ cp16(bH_+aSw[i], Bh+bOff[i]+ko_); cp16(bL_+aSw[i], Bl+bOff[i]+ko_); } \
    } while(0)

    LOAD_STAGE(0, 0); CP_COMMIT();
    LOAD_STAGE(1, 1); CP_COMMIT();

    int rA  = wm*64 + (lane&15);
    int kbA = (lane>>4)*16;
    int rB  = wn*32 + (lane&7) + ((lane>>4)<<3);
    int kbB = ((lane>>3)&1)*16;

    float acc[4][4][4];
    #pragma unroll
    for (int i=0;i<4;++i)
        #pragma unroll
        for (int j=0;j<4;++j)
            #pragma unroll
            for (int r=0;r<4;++r) acc[i][j][r]=0.f;

    for (int ck=0; ck<NC; ++ck){
        if (ck+2 < NC){ LOAD_STAGE((ck+2)%3, ck+2); CP_COMMIT(); asm volatile("cp.async.wait_group 2;\n":::"memory"); }
        else CP_WAIT0();
        __syncthreads();
        uint32_t base = sb + (ck%3)*STG;
        uint32_t uaH = base, uaL = base + 8192;
        uint32_t ubH = base + 16384, ubL = base + 24576;
        #pragma unroll
        for (int ks=0; ks<2; ++ks){
            uint32_t bh_[2][4], bl_[2][4];
            #pragma unroll
            for (int ng=0;ng<2;++ng){
                uint32_t o = (uint32_t)(rB + ng*16)*64 + ks*32 + kbB;
                o = SWZ64(o);
                LDM4(bh_[ng][0],bh_[ng][1],bh_[ng][2],bh_[ng][3], ubH + o);
                LDM4(bl_[ng][0],bl_[ng][1],bl_[ng][2],bl_[ng][3], ubL + o);
            }
            #pragma unroll
            for (int mi=0;mi<4;++mi){
                uint32_t ah[4], al[4];
                uint32_t o = (uint32_t)(rA + mi*16)*64 + ks*32 + kbA;
                o = SWZ64(o);
                LDM4(ah[0],ah[1],ah[2],ah[3], uaH + o);
                LDM4(al[0],al[1],al[2],al[3], uaL + o);
                #pragma unroll
                for (int ng=0;ng<2;++ng){
                    #pragma unroll
                    for (int j=0;j<2;++j){
                        MMA16816(acc[mi][ng*2+j], ah, bh_[ng][j*2], bh_[ng][j*2+1]);
                        MMA16816(acc[mi][ng*2+j], ah, bl_[ng][j*2], bl_[ng][j*2+1]);
                        MMA16816(acc[mi][ng*2+j], al, bh_[ng][j*2], bh_[ng][j*2+1]);
                    }
                }
            }
        }
        __syncthreads();
    }

    int g = lane>>2, tg = lane&3;
    #pragma unroll
    for (int mi=0;mi<4;++mi){
        #pragma unroll
        for (int half=0; half<2; ++half){
            int m = m0 + wm*64 + mi*16 + g + half*8;
            if (m < M){
                #pragma unroll
                for (int nj=0;nj<4;++nj){
                    int n = n0 + wn*32 + nj*8 + tg*2;
                    float v0 = acc[mi][nj][half*2+0] + __ldg(bias+n);
                    float v1 = acc[mi][nj][half*2+1] + __ldg(bias+n+1);
                    if (ACT==1){
                        v0 = 0.5f*v0*(1.0f+erff(v0*0.70710678118654752f));
                        v1 = 0.5f*v1*(1.0f+erff(v1*0.70710678118654752f));
                    }
                    if (ACT==2){ v0 = fmaxf(v0,0.f); v1 = fmaxf(v1,0.f); }
                    if (resid){
                        float2 rr = *(const float2*)(resid + (size_t)m*N + n);
                        v0 += rr.x; v1 += rr.y;
                    }
                    if (OUTBF==0){
                        float2 w; w.x=v0; w.y=v1;
                        *(float2*)(C + (size_t)m*N + n) = w;
                    } else {
                        split_store(Ch, Cl, (size_t)m*N + n, v0, v1);
                    }
                }
            }
        }
    }
}

// ---------------- QK gemm: S = scale*Q@K^T with causal mask (per bh) ----------------
#define QK_SMEM 65536
__global__ __launch_bounds__(256, 2)
void qk_gemm(const bf16* __restrict__ qkvh, const bf16* __restrict__ qkvl,
             float* __restrict__ S)
{
    int bh = blockIdx.z, b = bh>>4, h = bh&15;
    int m0 = blockIdx.y*128, n0 = blockIdx.x*128;
    if (n0 > m0) return;
    extern __shared__ char smem[];
    uint32_t sb = s2u(smem);
    uint32_t aH = sb, aL = sb+16384, bH = sb+32768, bL = sb+49152;
    int tid = threadIdx.x, lane = tid&31, wid = tid>>5;
    int wm = wid&1, wn = wid>>1;

    const bf16* qh = qkvh + (size_t)(b*SS)*3*DDIM + h*DH;
    const bf16* ql = qkvl + (size_t)(b*SS)*3*DDIM + h*DH;
    const bf16* kh = qh + DDIM;
    const bf16* kl = ql + DDIM;

    // FIXED loader: full 128B-per-row tiles (8 granules/row), 4 iters
    #pragma unroll
    for (int i=0;i<4;++i){
        int t = tid+256*i, r = t>>3, c = t&7;
        int ar = min(m0+r, SS-1), br = min(n0+r, SS-1);
        size_t ao = (size_t)ar*3*DDIM + c*8;
        size_t bo = (size_t)br*3*DDIM + c*8;
        uint32_t o = SWZ128((uint32_t)(r*128 + c*16));
        cp16(aH+o, qh+ao); cp16(aL+o, ql+ao);
        cp16(bH+o, kh+bo); cp16(bL+o, kl+bo);
    }
    CP_COMMIT(); CP_WAIT0();
    __syncthreads();

    int rA  = wm*64 + (lane&15);
    int kbA = (lane>>4)*16;
    int rB  = wn*32 + (lane&7) + ((lane>>4)<<3);
    int kbB = ((lane>>3)&1)*16;

    float acc[4][4][4];
    #pragma unroll
    for (int i=0;i<4;++i)
        #pragma unroll
        for (int j=0;j<4;++j)
            #pragma unroll
            for (int r=0;r<4;++r) acc[i][j][r]=0.f;

    #pragma unroll
    for (int ks=0; ks<4; ++ks){
        uint32_t bhf[2][4], blf[2][4];
        #pragma unroll
        for (int ng=0;ng<2;++ng){
            uint32_t o = SWZ128(((uint32_t)(rB + ng*16)<<7) + ks*32 + kbB);
            LDM4(bhf[ng][0],bhf[ng][1],bhf[ng][2],bhf[ng][3], bH + o);
            LDM4(blf[ng][0],blf[ng][1],blf[ng][2],blf[ng][3], bL + o);
        }
        #pragma unroll
        for (int mi=0;mi<4;++mi){
            uint32_t ah[4], al[4];
            uint32_t o = SWZ128(((uint32_t)(rA + mi*16)<<7) + ks*32 + kbA);
            LDM4(ah[0],ah[1],ah[2],ah[3], aH + o);
            LDM4(al[0],al[1],al[2],al[3], aL + o);
            #pragma unroll
            for (int ng=0;ng<2;++ng){
                #pragma unroll
                for (int j=0;j<2;++j){
                    MMA16816(acc[mi][ng*2+j], ah, bhf[ng][j*2], bhf[ng][j*2+1]);
                    MMA16816(acc[mi][ng*2+j], ah, blf[ng][j*2], blf[ng][j*2+1]);
                    MMA16816(acc[mi][ng*2+j], al, bhf[ng][j*2], bhf[ng][j*2+1]);
                }
            }
        }
    }

    float* Sb = S + (size_t)bh*SS*SPAD;
    int g = lane>>2, tg = lane&3;
    #pragma unroll
    for (int mi=0;mi<4;++mi){
        #pragma unroll
        for (int half=0; half<2; ++half){
            int qi = m0 + wm*64 + mi*16 + g + half*8;
            if (qi < SS){
                #pragma unroll
                for (int nj=0;nj<4;++nj){
                    int kj = n0 + wn*32 + nj*8 + tg*2;
                    float v0 = (kj   <= qi) ? acc[mi][nj][half*2+0]*0.125f : -1e30f;
                    float v1 = (kj+1 <= qi) ? acc[mi][nj][half*2+1]*0.125f : -1e30f;
                    float2 w; w.x=v0; w.y=v1;
                    *(float2*)(Sb + (size_t)qi*SPAD + kj) = w;
                }
            }
        }
    }
}

// ---------------- softmax rows -> split bf16 P (zero-padded to tile bound) ----------------
__global__ void softmax_kernel(const float* __restrict__ S,
                               bf16* __restrict__ Ph, bf16* __restrict__ Pl)
{
    int i = blockIdx.x, bh = blockIdx.y, tid = threadIdx.x;
    const float* row = S + (size_t)bh*SS*SPAD + (size_t)i*SPAD;
    int n = i+1;
    __shared__ float red[128];
    float mx = -1e30f;
    for (int j=tid;j<n;j+=128) mx = fmaxf(mx, row[j]);
    red[tid]=mx; __syncthreads();
    for (int st=64;st>0;st>>=1){ if (tid<st) red[tid]=fmaxf(red[tid],red[tid+st]); __syncthreads(); }
    mx = red[0]; __syncthreads();
    float sm = 0.f;
    for (int j=tid;j<n;j+=128) sm += __expf(row[j]-mx);
    red[tid]=sm; __syncthreads();
    for (int st=64;st>0;st>>=1){ if (tid<st) red[tid]+=red[tid+st]; __syncthreads(); }
    float invl = 1.f/red[0];
    int kend = ((i>>7)+1)<<7;
    bf16* ph = Ph + (size_t)bh*SS*SPAD + (size_t)i*SPAD;
    bf16* pl = Pl + (size_t)bh*SS*SPAD + (size_t)i*SPAD;
    for (int j=tid;j<kend;j+=128){
        float w = (j<n) ? __expf(row[j]-mx)*invl : 0.f;
        bf16 hh = __float2bfloat16(w);
        ph[j] = hh;
        pl[j] = __float2bfloat16(w-__bfloat162float(hh));
    }
}

// ---------------- V transpose per bh: vT[d][token] split bf16 ----------------
__global__ void vT_kernel(const bf16* __restrict__ qkvh, const bf16* __restrict__ qkvl)
{
    int bh = blockIdx.y, b = bh>>4, h = bh&15;
    int t0 = blockIdx.x*64;
    __shared__ bf16 sh[64][65], sl[64][65];
    int tx = threadIdx.x, ty = threadIdx.y;
    #pragma unroll
    for (int i=0;i<8;++i){
        int tok = min(t0 + ty + 8*i, SS-1);
        size_t off = (size_t)(b*SS+tok)*3*DDIM + 2*DDIM + h*DH + tx*2;
        __nv_bfloat162 vh = *(const __nv_bfloat162*)(qkvh + off);
        __nv_bfloat162 vl = *(const __nv_bfloat162*)(qkvl + off);
        sh[ty+8*i][tx*2] = vh.x; sh[ty+8*i][tx*2+1] = vh.y;
        sl[ty+8*i][tx*2] = vl.x; sl[ty+8*i][tx*2+1] = vl.y;
    }
    __syncthreads();
    bf16* oh = g_vT_hi + (size_t)bh*DH*SPAD;
    bf16* ol = g_vT_lo + (size_t)bh*DH*SPAD;
    #pragma unroll
    for (int i=0;i<8;++i){
        int d = ty + 8*i;
        __nv_bfloat162 H, L;
        H.x = sh[tx*2][d]; H.y = sh[tx*2+1][d];
        L.x = sl[tx*2][d]; L.y = sl[tx*2+1][d];
        *(__nv_bfloat162*)(oh + (size_t)d*SPAD + t0 + tx*2) = H;
        *(__nv_bfloat162*)(ol + (size_t)d*SPAD + t0 + tx*2) = L;
    }
}

// ---------------- PV gemm: O = P @ vT^T (per bh), BM=128 BN=64 BK=32 ----------------
#define PV_STG 24576
#define PV_SMEM (2*PV_STG)
__global__ __launch_bounds__(256, 2)
void pv_gemm(const bf16* __restrict__ Ph, const bf16* __restrict__ Pl)
{
    int bh = blockIdx.z, b = bh>>4, h = bh&15;
    int m0 = blockIdx.y*128;
    extern __shared__ char smem[];
    uint32_t sb = s2u(smem);
    int tid = threadIdx.x, lane = tid&31, wid = tid>>5;
    int wm = wid&3, wn = wid>>2;

    const bf16* Ah = Ph + (size_t)bh*SS*SPAD;
    const bf16* Al = Pl + (size_t)bh*SS*SPAD;
    const bf16* Bh = g_vT_hi + (size_t)bh*DH*SPAD;
    const bf16* Bl = g_vT_lo + (size_t)bh*DH*SPAD;

    size_t aOff[2]; uint32_t aSw[2];
    #pragma unroll
    for (int i=0;i<2;++i){
        int t = tid+256*i, r = t>>2, c = t&3;
        aOff[i] = (size_t)min(m0+r, SS-1)*SPAD + c*8;
        aSw[i] = SWZ64((uint32_t)(r*64 + c*16));
    }
    size_t bOff; uint32_t bSw;
    {
        int r = tid>>2, c = tid&3;
        bOff = (size_t)r*SPAD + c*8;
        bSw = SWZ64((uint32_t)(r*64 + c*16));
    }

    const int NC = (m0+128)/32;
    #define PV_LOAD(s_, ck_) do { \
        uint32_t aH_ = sb + (s_)*PV_STG, aL_ = aH_ + 8192; \
        uint32_t bH_ = aH_ + 16384,  bL_ = aH_ + 20480; \
        size_t ko_ = (size_t)(ck_)*32; \
        _Pragma("unroll") \
        for (int i=0;i<2;++i){ cp16(aH_+aSw[i], Ah+aOff[i]+ko_); cp16(aL_+aSw[i], Al+aOff[i]+ko_); } \
        cp16(bH_+bSw, Bh+bOff+ko_); cp16(bL_+bSw, Bl+bOff+ko_); \
    } while(0)

    PV_LOAD(0, 0); CP_COMMIT();

    int rA  = wm*32 + (lane&15);
    int kbA = (lane>>4)*16;
    int rB  = wn*32 + (lane&7) + ((lane>>4)<<3);
    int kbB = ((lane>>3)&1)*16;

    float acc[2][4][4];
    #pragma unroll
    for (int i=0;i<2;++i)
        #pragma unroll
        for (int j=0;j<4;++j)
            #pragma unroll
            for (int r=0;r<4;++r) acc[i][j][r]=0.f;

    for (int ck=0; ck<NC; ++ck){
        if (ck+1 < NC){ PV_LOAD((ck+1)&1, ck+1); CP_COMMIT(); CP_WAIT1(); }
        else CP_WAIT0();
        __syncthreads();
        uint32_t base = sb + (ck&1)*PV_STG;
        uint32_t uaH = base, uaL = base + 8192;
        uint32_t ubH = base + 16384, ubL = base + 20480;
        #pragma unroll
        for (int ks=0; ks<2; ++ks){
            uint32_t bhf[2][4], blf[2][4];
            #pragma unroll
            for (int ng=0;ng<2;++ng){
                uint32_t o = SWZ64((uint32_t)(rB + ng*16)*64 + ks*32 + kbB);
                LDM4(bhf[ng][0],bhf[ng][1],bhf[ng][2],bhf[ng][3], ubH + o);
                LDM4(blf[ng][0],blf[ng][1],blf[ng][2],blf[ng][3], ubL + o);
            }
            #pragma unroll
            for (int mi=0;mi<2;++mi){
                uint32_t ah[4], al[4];
                uint32_t o = SWZ64((uint32_t)(rA + mi*16)*64 + ks*32 + kbA);
                LDM4(ah[0],ah[1],ah[2],ah[3], uaH + o);
                LDM4(al[0],al[1],al[2],al[3], uaL + o);
                #pragma unroll
                for (int ng=0;ng<2;++ng){
                    #pragma unroll
                    for (int j=0;j<2;++j){
                        MMA16816(acc[mi][ng*2+j], ah, bhf[ng][j*2], bhf[ng][j*2+1]);
                        MMA16816(acc[mi][ng*2+j], ah, blf[ng][j*2], blf[ng][j*2+1]);
                        MMA16816(acc[mi][ng*2+j], al, bhf[ng][j*2], bhf[ng][j*2+1]);
                    }
                }
            }
        }
        __syncthreads();
    }

    int g = lane>>2, tg = lane&3;
    #pragma unroll
    for (int mi=0;mi<2;++mi){
        #pragma unroll
        for (int half=0; half<2; ++half){
            int q = m0 + wm*32 + mi*16 + g + half*8;
            if (q < SS){
                size_t rowoff = (size_t)(b*SS+q)*DDIM + h*DH;
                #pragma unroll
                for (int nj=0;nj<4;++nj){
                    int d = wn*32 + nj*8 + tg*2;
                    split_store(g_o_hi, g_o_lo, rowoff + d,
                                acc[mi][nj][half*2+0], acc[mi][nj][half*2+1]);
                }
            }
        }
    }
}

// ---------------- fused prologue (weights/bias/idx/embed) ----------------
#define CV_MAIN 27648
#define CV_AUX  64
__global__ void convert_all(const float* __restrict__ wq, const float* __restrict__ wk,
                            const float* __restrict__ wv, const float* __restrict__ wo,
                            const float* __restrict__ w1, const float* __restrict__ w2,
                            const float* __restrict__ ho1, const float* __restrict__ ho2,
                            const float* __restrict__ he1,
                            const float* __restrict__ bq, const float* __restrict__ bk,
                            const float* __restrict__ bv,
                            const int* __restrict__ tokens, const float* __restrict__ pos_emb,
                            const float* __restrict__ emb_obs, const float* __restrict__ emb_act)
{
    int t = blockIdx.x;
    int tid = threadIdx.y*32 + threadIdx.x;
    if (t >= CV_MAIN + CV_AUX){
        int row = t - (CV_MAIN + CV_AUX);
        int s = row % SS;
        int tok = tokens[row];
        bool is_obs = (s % TPB_) < (TPB_-1);
        const float* e = is_obs ? (emb_obs + (size_t)min(tok,VOBS_-1)*DDIM)
                                : (emb_act + (size_t)min(tok,VACT_-1)*DDIM);
        const float* pe = pos_emb + (size_t)s*DDIM;
        float* xo = g_x + (size_t)row*DDIM;
        for (int d = tid; d < DDIM; d += 256) xo[d] = e[d] + pe[d];
        return;
    }
    if (t >= CV_MAIN){
        int idx = (t - CV_MAIN)*256 + tid;
        if (idx < LL*3*DDIM){
            int l = idx/(3*DDIM), r = idx%(3*DDIM), part = r/DDIM, d = r%DDIM;
            const float* src = part==0 ? bq : (part==1 ? bk : bv);
            g_bqkv[idx] = src[l*DDIM + d];
        }
        int j = idx - LL*3*DDIM;
        if (j >= 0 && j < NOBS){
            int b = j/960, jj = j%960, blk = jj/16, r = jj%16;
            g_obs_rows[j] = b*SS + blk*TPB_ + (r<15 ? r : 16);
        }
        if (j >= 0 && j < NACT){
            int b = j/60, blk = j%60;
            g_act_rows[j] = b*SS + blk*TPB_ + (TPB_-1);
        }
        return;
    }
    const float* src; int doff, K, N, base; size_t inMS, outMS;
    if      (t <  2048){ src=wq;  doff=WQKV_OFF;        K=DDIM; N=DDIM;  inMS=DD_; outMS=3*DD_; base=0; }
    else if (t <  4096){ src=wk;  doff=WQKV_OFF+DD_;    K=DDIM; N=DDIM;  inMS=DD_; outMS=3*DD_; base=2048; }
    else if (t <  6144){ src=wv;  doff=WQKV_OFF+2*DD_;  K=DDIM; N=DDIM;  inMS=DD_; outMS=3*DD_; base=4096; }
    else if (t <  8192){ src=wo;  doff=WO_OFF;          K=DDIM; N=DDIM;  inMS=DD_; outMS=DD_;   base=6144; }
    else if (t < 16384){ src=w1;  doff=W1_OFF;          K=DDIM; N=FF;    inMS=DF_; outMS=DF_;   base=8192; }
    else if (t < 24576){ src=w2;  doff=W2_OFF;          K=FF;   N=DDIM;  inMS=DF_; outMS=DF_;   base=16384; }
    else if (t < 25088){ src=ho1; doff=HO1_OFF;         K=DDIM; N=DDIM;  inMS=0;   outMS=0;     base=24576; }
    else if (t < 27136){ src=ho2; doff=HO2_OFF;         K=DDIM; N=VOBS_; inMS=0;   outMS=0;     base=25088; }
    else               { src=he1; doff=HE1_OFF;         K=DDIM; N=DDIM;  inMS=0;   outMS=0;     base=27136; }
    int r = t - base;
    int nt = N/32;
    int tpz = (K/64)*nt;
    int z = r/tpz, rr = r%tpz;
    int k0 = (rr/nt)*64, n0 = (rr%nt)*32;

    const float* Wm = src + (size_t)z*inMS;
    bf16* Whm = g_wt_hi + doff + (size_t)z*outMS;
    bf16* Wlm = g_wt_lo + doff + (size_t)z*outMS;

    __shared__ float tsh[64][33];
    int tx = threadIdx.x, ty = threadIdx.y;
    #pragma unroll
    for (int i=0;i<8;++i)
        tsh[ty+8*i][tx] = Wm[(size_t)(k0+ty+8*i)*N + n0+tx];
    __syncthreads();
    #pragma unroll
    for (int i=0;i<4;++i){
        int nn = ty + 8*i;
        float v0 = tsh[tx*2][nn], v1 = tsh[tx*2+1][nn];
        size_t o = (size_t)(n0+nn)*K + k0 + tx*2;
        split_store(Whm, Wlm, o, v0, v1);
    }
}

// ---------------- LN -> split bf16 ----------------
__device__ __forceinline__ float bsum256(float v)
{
    __shared__ float sh[8];
    int ln = threadIdx.x&31, w = threadIdx.x>>5;
    #pragma unroll
    for (int o=16;o>0;o>>=1) v += __shfl_xor_sync(0xffffffffu, v, o);
    if (ln==0) sh[w]=v;
    __syncthreads();
    if (w==0){
        float t = (ln<8)?sh[ln]:0.f;
        #pragma unroll
        for (int o=4;o>0;o>>=1) t += __shfl_xor_sync(0xffffffffu, t, o);
        if (ln==0) sh[0]=t;
    }
    __syncthreads();
    float r = sh[0];
    __syncthreads();
    return r;
}

__global__ void ln_kernel(const float* __restrict__ x, const float* __restrict__ g,
                          const float* __restrict__ b, bf16* __restrict__ oh, bf16* __restrict__ ol)
{
    int row = blockIdx.x, t = threadIdx.x;
    const float* xr = x + (size_t)row*DDIM;
    float v[4]; float s = 0.f;
    #pragma unroll
    for (int i=0;i<4;++i){ v[i]=xr[t+256*i]; s+=v[i]; }
    float mean = bsum256(s) * (1.f/DDIM);
    float q = 0.f;
    #pragma unroll
    for (int i=0;i<4;++i){ float d=v[i]-mean; q+=d*d; }
    float rstd = rsqrtf(bsum256(q)*(1.f/DDIM) + 1e-3f);
    #pragma unroll
    for (int i=0;i<4;++i){
        int idx = t+256*i;
        float y = (v[i]-mean)*rstd*g[idx] + b[idx];
        bf16 h = __float2bfloat16(y);
        oh[(size_t)row*DDIM+idx] = h;
        ol[(size_t)row*DDIM+idx] = __float2bfloat16(y-__bfloat162float(h));
    }
}

// ---------------- tiny N=2 head ----------------
__global__ void head_ends_kernel(const float* __restrict__ t2, const float* __restrict__ w,
                                 const float* __restrict__ bias, float* __restrict__ out)
{
    int r = blockIdx.x, tid = threadIdx.x;
    const float* a = t2 + (size_t)r*DDIM;
    float s0 = 0.f, s1 = 0.f;
    for (int k = tid; k < DDIM; k += 128){
        float av = a[k];
        s0 = fmaf(av, w[k*2], s0);
        s1 = fmaf(av, w[k*2+1], s1);
    }
    __shared__ float red[128];
    red[tid]=s0; __syncthreads();
    for (int st=64;st>0;st>>=1){ if (tid<st) red[tid]+=red[tid+st]; __syncthreads(); }
    if (tid==0) out[r*2] = red[0]+bias[0];
    __syncthreads();
    red[tid]=s1; __syncthreads();
    for (int st=64;st>0;st>>=1){ if (tid<st) red[tid]+=red[tid+st]; __syncthreads(); }
    if (tid==0) out[r*2+1] = red[0]+bias[1];
}

// ---------------- launch ----------------
extern "C" void kernel_launch(void* const* d_in, const int* in_sizes, int n_in,
                              void* d_out, int out_size)
{
    const int* tokens = (const int*)d_in[0];
    const float *pos_emb=(const float*)d_in[1], *emb_obs=(const float*)d_in[2], *emb_act=(const float*)d_in[3];
    const float *ln1_g=(const float*)d_in[4], *ln1_b=(const float*)d_in[5];
    const float *wq=(const float*)d_in[6], *bq=(const float*)d_in[7];
    const float *wk=(const float*)d_in[8], *bk=(const float*)d_in[9];
    const float *wv=(const float*)d_in[10], *bv=(const float*)d_in[11];
    const float *wo=(const float*)d_in[12], *bo=(const float*)d_in[13];
    const float *ln2_g=(const float*)d_in[14], *ln2_b=(const float*)d_in[15];
    const float *w1=(const float*)d_in[16], *b1=(const float*)d_in[17];
    const float *w2=(const float*)d_in[18], *b2=(const float*)d_in[19];
    const float *lnf_g=(const float*)d_in[20], *lnf_b=(const float*)d_in[21];
    const float *ho1=(const float*)d_in[22], *bo1=(const float*)d_in[23];
    const float *ho2=(const float*)d_in[24], *bo2=(const float*)d_in[25];
    const float *he1=(const float*)d_in[26], *be1=(const float*)d_in[27];
    const float *he2=(const float*)d_in[28], *be2=(const float*)d_in[29];
    float* out = (float*)d_out;

    float *x,*t2,*bqkv,*S;
    bf16 *qkvh,*qkvl,*Ph,*Pl,*h_hi,*h_lo,*o_hi,*o_lo,*mid_hi,*mid_lo,*t1_hi,*t1_lo,*wt_hi,*wt_lo;
    int *obsr,*actr;
    cudaGetSymbolAddress((void**)&x, g_x);
    cudaGetSymbolAddress((void**)&t2, g_t2);
    cudaGetSymbolAddress((void**)&bqkv, g_bqkv);
    cudaGetSymbolAddress((void**)&S, g_S);
    cudaGetSymbolAddress((void**)&qkvh, g_qkv_hi);
    cudaGetSymbolAddress((void**)&qkvl, g_qkv_lo);
    cudaGetSymbolAddress((void**)&Ph, g_P_hi);
    cudaGetSymbolAddress((void**)&Pl, g_P_lo);
    cudaGetSymbolAddress((void**)&h_hi, g_h_hi);
    cudaGetSymbolAddress((void**)&h_lo, g_h_lo);
    cudaGetSymbolAddress((void**)&o_hi, g_o_hi);
    cudaGetSymbolAddress((void**)&o_lo, g_o_lo);
    cudaGetSymbolAddress((void**)&mid_hi, g_mid_hi);
    cudaGetSymbolAddress((void**)&mid_lo, g_mid_lo);
    cudaGetSymbolAddress((void**)&t1_hi, g_t1_hi);
    cudaGetSymbolAddress((void**)&t1_lo, g_t1_lo);
    cudaGetSymbolAddress((void**)&wt_hi, g_wt_hi);
    cudaGetSymbolAddress((void**)&wt_lo, g_wt_lo);
    cudaGetSymbolAddress((void**)&obsr, g_obs_rows);
    cudaGetSymbolAddress((void**)&actr, g_act_rows);

    cudaFuncSetAttribute(tcgemm<0,0>, cudaFuncAttributeMaxDynamicSharedMemorySize, GEMM_SMEM);
    cudaFuncSetAttribute(tcgemm<0,1>, cudaFuncAttributeMaxDynamicSharedMemorySize, GEMM_SMEM);
    cudaFuncSetAttribute(tcgemm<1,1>, cudaFuncAttributeMaxDynamicSharedMemorySize, GEMM_SMEM);
    cudaFuncSetAttribute(tcgemm<2,1>, cudaFuncAttributeMaxDynamicSharedMemorySize, GEMM_SMEM);
    cudaFuncSetAttribute(tcgemm<2,0>, cudaFuncAttributeMaxDynamicSharedMemorySize, GEMM_SMEM);
    cudaFuncSetAttribute(qk_gemm, cudaFuncAttributeMaxDynamicSharedMemorySize, QK_SMEM);
    cudaFuncSetAttribute(pv_gemm, cudaFuncAttributeMaxDynamicSharedMemorySize, PV_SMEM);

    convert_all<<<CV_MAIN + CV_AUX + NTOK, dim3(32,8)>>>(
        wq, wk, wv, wo, w1, w2, ho1, ho2, he1, bq, bk, bv,
        tokens, pos_emb, emb_obs, emb_act);

    #define GG(M_, N_) dim3((N_)/BN, ((M_)+BM-1)/BM)
    for (int l = 0; l < LL; ++l){
        size_t dd = (size_t)l*DD_;
        ln_kernel<<<NTOK, 256>>>(x, ln1_g+l*DDIM, ln1_b+l*DDIM, h_hi, h_lo);
        tcgemm<0,1><<<GG(NTOK, 3*DDIM), 256, GEMM_SMEM>>>(
            h_hi, h_lo, wt_hi+WQKV_OFF+(size_t)l*3*DD_, wt_lo+WQKV_OFF+(size_t)l*3*DD_,
            bqkv+(size_t)l*3*DDIM, nullptr, qkvh, qkvl, nullptr, nullptr, NTOK, 3*DDIM, DDIM);
        qk_gemm<<<dim3(8,8,NBH), 256, QK_SMEM>>>(qkvh, qkvl, S);
        vT_kernel<<<dim3(16,NBH), dim3(32,8)>>>(qkvh, qkvl);
        softmax_kernel<<<dim3(SS,NBH), 128>>>(S, Ph, Pl);
        pv_gemm<<<dim3(1,8,NBH), 256, PV_SMEM>>>(Ph, Pl);
        tcgemm<0,0><<<GG(NTOK, DDIM), 256, GEMM_SMEM>>>(
            o_hi, o_lo, wt_hi+WO_OFF+dd, wt_lo+WO_OFF+dd,
            bo+l*DDIM, x, nullptr, nullptr, x, nullptr, NTOK, DDIM, DDIM);
        ln_kernel<<<NTOK, 256>>>(x, ln2_g+l*DDIM, ln2_b+l*DDIM, h_hi, h_lo);
        tcgemm<1,1><<<GG(NTOK, FF), 256, GEMM_SMEM>>>(
            h_hi, h_lo, wt_hi+W1_OFF+(size_t)l*DF_, wt_lo+W1_OFF+(size_t)l*DF_,
            b1+(size_t)l*FF, nullptr, mid_hi, mid_lo, nullptr, nullptr, NTOK, FF, DDIM);
        tcgemm<0,0><<<GG(NTOK, DDIM), 256, GEMM_SMEM>>>(
            mid_hi, mid_lo, wt_hi+W2_OFF+(size_t)l*DF_, wt_lo+W2_OFF+(size_t)l*DF_,
            b2+l*DDIM, x, nullptr, nullptr, x, nullptr, NTOK, DDIM, FF);
    }

    ln_kernel<<<NTOK, 256>>>(x, lnf_g, lnf_b, h_hi, h_lo);

    tcgemm<2,1><<<GG(NOBS, DDIM), 256, GEMM_SMEM>>>(
        h_hi, h_lo, wt_hi+HO1_OFF, wt_lo+HO1_OFF, bo1,
        nullptr, t1_hi, t1_lo, nullptr, obsr, NOBS, DDIM, DDIM);
    tcgemm<0,0><<<GG(NOBS, VOBS_), 256, GEMM_SMEM>>>(
        t1_hi, t1_lo, wt_hi+HO2_OFF, wt_lo+HO2_OFF, bo2,
        out, nullptr, nullptr, nullptr, nullptr, NOBS, VOBS_, DDIM);

    tcgemm<2,0><<<GG(NACT, DDIM), 256, GEMM_SMEM>>>(
        h_hi, h_lo, wt_hi+HE1_OFF, wt_lo+HE1_OFF, be1,
        t2, nullptr, nullptr, nullptr, actr, NACT, DDIM, DDIM);
    head_ends_kernel<<<NACT, 128>>>(t2, he2, be2, out + (size_t)NOBS*VOBS_);
}

// round 14
// speedup vs baseline: 1.9275x; 1.4427x over previous
#include <cuda_runtime.h>
#include <cuda_fp16.h>
#include <math.h>
#include <stdint.h>

typedef __half f16;

#define BB 4
#define SS 1020
#define DDIM 1024
#define HH 16
#define DH 64
#define LL 4
#define TPB_ 17
#define FF 4096
#define NTOK (BB*SS)
#define NOBS (BB*960)
#define NACT (BB*60)
#define VOBS_ 4096
#define VACT_ 16
#define DD_ (DDIM*DDIM)
#define DF_ (DDIM*FF)
#define SPAD 1024
#define NBH (BB*HH)

// ---------------- static scratch ----------------
__device__ __align__(256) float g_x[NTOK*DDIM];
__device__ __align__(256) float g_t2[NACT*DDIM];
__device__ __align__(256) f16 g_qkv_hi[NTOK*3*DDIM];
__device__ __align__(256) f16 g_qkv_lo[NTOK*3*DDIM];
__device__ __align__(256) float g_S[(size_t)NBH*SS*SPAD];
__device__ __align__(256) f16 g_P_hi[(size_t)NBH*SS*SPAD];
__device__ __align__(256) f16 g_P_lo[(size_t)NBH*SS*SPAD];
__device__ __align__(256) f16 g_vT_hi[NBH*DH*SPAD];
__device__ __align__(256) f16 g_h_hi[NTOK*DDIM];
__device__ __align__(256) f16 g_h_lo[NTOK*DDIM];
__device__ __align__(256) f16 g_o_hi[NTOK*DDIM];
__device__ __align__(256) f16 g_o_lo[NTOK*DDIM];
__device__ __align__(256) f16 g_mid_hi[NTOK*FF];
__device__ __align__(256) f16 g_mid_lo[NTOK*FF];
__device__ __align__(256) f16 g_t1_hi[NOBS*DDIM];
__device__ __align__(256) f16 g_t1_lo[NOBS*DDIM];
__device__ float g_bqkv[LL*3*DDIM];
__device__ int g_obs_rows[NOBS];
__device__ int g_act_rows[NACT];

#define WQKV_OFF 0
#define WO_OFF  (WQKV_OFF + LL*3*DD_)
#define W1_OFF  (WO_OFF + LL*DD_)
#define W2_OFF  (W1_OFF + LL*DF_)
#define HO1_OFF (W2_OFF + LL*DF_)
#define HO2_OFF (HO1_OFF + DD_)
#define HE1_OFF (HO2_OFF + VOBS_*DDIM)
#define WT_TOT  (HE1_OFF + DD_)
__device__ __align__(256) f16 g_wt_hi[WT_TOT];

// ---------------- PTX helpers ----------------
__device__ __forceinline__ uint32_t s2u(const void* p){ return (uint32_t)__cvta_generic_to_shared(p); }
__device__ __forceinline__ void cp16(uint32_t d, const void* s){
    asm volatile("cp.async.cg.shared.global [%0], [%1], 16;\n"::"r"(d),"l"(s));
}
#define CP_COMMIT() asm volatile("cp.async.commit_group;\n":::"memory")
#define CP_WAIT1()  asm volatile("cp.async.wait_group 1;\n":::"memory")
#define CP_WAIT0()  asm volatile("cp.async.wait_group 0;\n":::"memory")

#define SWZ64(o)  ((o) ^ (((o)>>3)&0x30))
#define SWZ128(o) ((o) ^ (((o)>>3)&0x70))

#define LDM4(r0,r1,r2,r3,a) \
    asm volatile("ldmatrix.sync.aligned.m8n8.x4.shared.b16 {%0,%1,%2,%3}, [%4];" \
        : "=r"(r0),"=r"(r1),"=r"(r2),"=r"(r3) : "r"(a))

#define MMA16816(c,a,b0,b1) \
    asm volatile("mma.sync.aligned.m16n8k16.row.col.f32.f16.f16.f32 " \
        "{%0,%1,%2,%3}, {%4,%5,%6,%7}, {%8,%9}, {%0,%1,%2,%3};" \
        : "+f"((c)[0]),"+f"((c)[1]),"+f"((c)[2]),"+f"((c)[3]) \
        : "r"((a)[0]),"r"((a)[1]),"r"((a)[2]),"r"((a)[3]), "r"(b0),"r"(b1))

__device__ __forceinline__ void split_store(f16* Ph, f16* Pl, size_t off, float v0, float v1){
    f16 h0=__float2half_rn(v0), h1=__float2half_rn(v1);
    __half2 H; H.x=h0; H.y=h1;
    __half2 L;
    L.x=__float2half_rn(v0-__half2float(h0));
    L.y=__float2half_rn(v1-__half2float(h1));
    *(__half2*)(Ph+off)=H;
    *(__half2*)(Pl+off)=L;
}

// ---------------- mma.sync fp16 GEMM: A 2-term split, B single fp16 ----------------
#define BM 128
#define BN 128
#define STG 24576              // Ah 8K | Al 8K | Bh 8K
#define GEMM_SMEM (3*STG)      // 73728

template<int ACT, int OUTBF>
__global__ __launch_bounds__(256, 2)
void tcgemm(const f16* __restrict__ Ah, const f16* __restrict__ Al,
            const f16* __restrict__ Bh,
            const float* __restrict__ bias,
            float* __restrict__ C, f16* __restrict__ Ch, f16* __restrict__ Cl,
            const float* __restrict__ resid, const int* __restrict__ rowmap,
            int M, int N, int K)
{
    extern __shared__ char smem[];
    uint32_t sb = s2u(smem);
    int tid = threadIdx.x, lane = tid&31, wid = tid>>5;
    int wm = wid&1, wn = wid>>1;
    int m0 = blockIdx.y*BM, n0 = blockIdx.x*BN;

    size_t aOff[2], bOff[2]; uint32_t aSw[2];
    #pragma unroll
    for (int i=0;i<2;++i){
        int t = tid+256*i, r = t>>2, c = t&3;
        int am = m0+r; if (am > M-1) am = M-1;
        int ar = rowmap ? rowmap[am] : am;
        aOff[i] = (size_t)ar*K + c*8;
        bOff[i] = (size_t)(n0+r)*K + c*8;
        uint32_t o = r*64 + c*16;
        aSw[i] = SWZ64(o);
    }

    const int NC = K/32;
    #define LOAD_STAGE(s_, ck_) do { \
        uint32_t aH_ = sb + (s_)*STG, aL_ = aH_ + 8192, bH_ = aH_ + 16384; \
        size_t ko_ = (size_t)(ck_)*32; \
        _Pragma("unroll") \
        for (int i=0;i<2;++i){ cp16(aH_+aSw[i], Ah+aOff[i]+ko_); cp16(aL_+aSw[i], Al+aOff[i]+ko_); \
                               cp16(bH_+aSw[i], Bh+bOff[i]+ko_); } \
    } while(0)

    LOAD_STAGE(0, 0); CP_COMMIT();
    LOAD_STAGE(1, 1); CP_COMMIT();

    int rA  = wm*64 + (lane&15);
    int kbA = (lane>>4)*16;
    int rB  = wn*32 + (lane&7) + ((lane>>4)<<3);
    int kbB = ((lane>>3)&1)*16;

    float acc[4][4][4];
    #pragma unroll
    for (int i=0;i<4;++i)
        #pragma unroll
        for (int j=0;j<4;++j)
            #pragma unroll
            for (int r=0;r<4;++r) acc[i][j][r]=0.f;

    for (int ck=0; ck<NC; ++ck){
        if (ck+2 < NC){ LOAD_STAGE((ck+2)%3, ck+2); CP_COMMIT(); asm volatile("cp.async.wait_group 2;\n":::"memory"); }
        else CP_WAIT0();
        __syncthreads();
        uint32_t base = sb + (ck%3)*STG;
        uint32_t uaH = base, uaL = base + 8192, ubH = base + 16384;
        #pragma unroll
        for (int ks=0; ks<2; ++ks){
            uint32_t bh_[2][4];
            #pragma unroll
            for (int ng=0;ng<2;++ng){
                uint32_t o = (uint32_t)(rB + ng*16)*64 + ks*32 + kbB;
                o = SWZ64(o);
                LDM4(bh_[ng][0],bh_[ng][1],bh_[ng][2],bh_[ng][3], ubH + o);
            }
            #pragma unroll
            for (int mi=0;mi<4;++mi){
                uint32_t ah[4], al[4];
                uint32_t o = (uint32_t)(rA + mi*16)*64 + ks*32 + kbA;
                o = SWZ64(o);
                LDM4(ah[0],ah[1],ah[2],ah[3], uaH + o);
                LDM4(al[0],al[1],al[2],al[3], uaL + o);
                #pragma unroll
                for (int ng=0;ng<2;++ng){
                    #pragma unroll
                    for (int j=0;j<2;++j){
                        MMA16816(acc[mi][ng*2+j], ah, bh_[ng][j*2], bh_[ng][j*2+1]);
                        MMA16816(acc[mi][ng*2+j], al, bh_[ng][j*2], bh_[ng][j*2+1]);
                    }
                }
            }
        }
        __syncthreads();
    }

    int g = lane>>2, tg = lane&3;
    #pragma unroll
    for (int mi=0;mi<4;++mi){
        #pragma unroll
        for (int half=0; half<2; ++half){
            int m = m0 + wm*64 + mi*16 + g + half*8;
            if (m < M){
                #pragma unroll
                for (int nj=0;nj<4;++nj){
                    int n = n0 + wn*32 + nj*8 + tg*2;
                    float v0 = acc[mi][nj][half*2+0] + __ldg(bias+n);
                    float v1 = acc[mi][nj][half*2+1] + __ldg(bias+n+1);
                    if (ACT==1){
                        v0 = 0.5f*v0*(1.0f+erff(v0*0.70710678118654752f));
                        v1 = 0.5f*v1*(1.0f+erff(v1*0.70710678118654752f));
                    }
                    if (ACT==2){ v0 = fmaxf(v0,0.f); v1 = fmaxf(v1,0.f); }
                    if (resid){
                        float2 rr = *(const float2*)(resid + (size_t)m*N + n);
                        v0 += rr.x; v1 += rr.y;
                    }
                    if (OUTBF==0){
                        float2 w; w.x=v0; w.y=v1;
                        *(float2*)(C + (size_t)m*N + n) = w;
                    } else {
                        split_store(Ch, Cl, (size_t)m*N + n, v0, v1);
                    }
                }
            }
        }
    }
}

// ---------------- QK gemm: S = scale*Q@K^T causal (per bh); Q 2-term, K single ----------------
#define QK_SMEM 49152
__global__ __launch_bounds__(256, 2)
void qk_gemm(const f16* __restrict__ qkvh, const f16* __restrict__ qkvl,
             float* __restrict__ S)
{
    int bh = blockIdx.z, b = bh>>4, h = bh&15;
    int m0 = blockIdx.y*128, n0 = blockIdx.x*128;
    if (n0 > m0) return;
    extern __shared__ char smem[];
    uint32_t sb = s2u(smem);
    uint32_t aH = sb, aL = sb+16384, bH = sb+32768;
    int tid = threadIdx.x, lane = tid&31, wid = tid>>5;
    int wm = wid&1, wn = wid>>1;

    const f16* qh = qkvh + (size_t)(b*SS)*3*DDIM + h*DH;
    const f16* ql = qkvl + (size_t)(b*SS)*3*DDIM + h*DH;
    const f16* kh = qh + DDIM;

    #pragma unroll
    for (int i=0;i<4;++i){
        int t = tid+256*i, r = t>>3, c = t&7;
        int ar = min(m0+r, SS-1), br = min(n0+r, SS-1);
        size_t ao = (size_t)ar*3*DDIM + c*8;
        size_t bo = (size_t)br*3*DDIM + c*8;
        uint32_t o = SWZ128((uint32_t)(r*128 + c*16));
        cp16(aH+o, qh+ao); cp16(aL+o, ql+ao);
        cp16(bH+o, kh+bo);
    }
    CP_COMMIT(); CP_WAIT0();
    __syncthreads();

    int rA  = wm*64 + (lane&15);
    int kbA = (lane>>4)*16;
    int rB  = wn*32 + (lane&7) + ((lane>>4)<<3);
    int kbB = ((lane>>3)&1)*16;

    float acc[4][4][4];
    #pragma unroll
    for (int i=0;i<4;++i)
        #pragma unroll
        for (int j=0;j<4;++j)
            #pragma unroll
            for (int r=0;r<4;++r) acc[i][j][r]=0.f;

    #pragma unroll
    for (int ks=0; ks<4; ++ks){
        uint32_t bhf[2][4];
        #pragma unroll
        for (int ng=0;ng<2;++ng){
            uint32_t o = SWZ128(((uint32_t)(rB + ng*16)<<7) + ks*32 + kbB);
            LDM4(bhf[ng][0],bhf[ng][1],bhf[ng][2],bhf[ng][3], bH + o);
        }
        #pragma unroll
        for (int mi=0;mi<4;++mi){
            uint32_t ah[4], al[4];
            uint32_t o = SWZ128(((uint32_t)(rA + mi*16)<<7) + ks*32 + kbA);
            LDM4(ah[0],ah[1],ah[2],ah[3], aH + o);
            LDM4(al[0],al[1],al[2],al[3], aL + o);
            #pragma unroll
            for (int ng=0;ng<2;++ng){
                #pragma unroll
                for (int j=0;j<2;++j){
                    MMA16816(acc[mi][ng*2+j], ah, bhf[ng][j*2], bhf[ng][j*2+1]);
                    MMA16816(acc[mi][ng*2+j], al, bhf[ng][j*2], bhf[ng][j*2+1]);
                }
            }
        }
    }

    float* Sb = S + (size_t)bh*SS*SPAD;
    int g = lane>>2, tg = lane&3;
    #pragma unroll
    for (int mi=0;mi<4;++mi){
        #pragma unroll
        for (int half=0; half<2; ++half){
            int qi = m0 + wm*64 + mi*16 + g + half*8;
            if (qi < SS){
                #pragma unroll
                for (int nj=0;nj<4;++nj){
                    int kj = n0 + wn*32 + nj*8 + tg*2;
                    float v0 = (kj   <= qi) ? acc[mi][nj][half*2+0]*0.125f : -1e30f;
                    float v1 = (kj+1 <= qi) ? acc[mi][nj][half*2+1]*0.125f : -1e30f;
                    float2 w; w.x=v0; w.y=v1;
                    *(float2*)(Sb + (size_t)qi*SPAD + kj) = w;
                }
            }
        }
    }
}

// ---------------- softmax: register-resident, 1 read + 1 write ----------------
__global__ __launch_bounds__(256)
void softmax_kernel(const float* __restrict__ S,
                    f16* __restrict__ Ph, f16* __restrict__ Pl)
{
    int i = blockIdx.x, bh = blockIdx.y, tid = threadIdx.x;
    const float* row = S + (size_t)bh*SS*SPAD + (size_t)i*SPAD;
    int kend = ((i>>7)+1)<<7;
    int c = tid*4;
    float4 v = make_float4(-1e30f,-1e30f,-1e30f,-1e30f);
    if (c < kend) v = *(const float4*)(row + c);

    __shared__ float sh[8];
    int ln = tid&31, w = tid>>5;
    // max reduce
    float mx = fmaxf(fmaxf(v.x,v.y), fmaxf(v.z,v.w));
    #pragma unroll
    for (int o=16;o>0;o>>=1) mx = fmaxf(mx, __shfl_xor_sync(0xffffffffu, mx, o));
    if (ln==0) sh[w]=mx;
    __syncthreads();
    if (w==0){
        float t = sh[ln&7];
        #pragma unroll
        for (int o=4;o>0;o>>=1) t = fmaxf(t, __shfl_xor_sync(0xffffffffu, t, o));
        if (ln==0) sh[0]=t;
    }
    __syncthreads();
    mx = sh[0];
    __syncthreads();
    float e0 = __expf(v.x-mx), e1 = __expf(v.y-mx);
    float e2 = __expf(v.z-mx), e3 = __expf(v.w-mx);
    float sm = (e0+e1)+(e2+e3);
    #pragma unroll
    for (int o=16;o>0;o>>=1) sm += __shfl_xor_sync(0xffffffffu, sm, o);
    if (ln==0) sh[w]=sm;
    __syncthreads();
    if (w==0){
        float t = sh[ln&7];
        #pragma unroll
        for (int o=4;o>0;o>>=1) t += __shfl_xor_sync(0xffffffffu, t, o);
        if (ln==0) sh[0]=t;
    }
    __syncthreads();
    float inv = 1.f/sh[0];
    if (c < kend){
        size_t ob = (size_t)bh*SS*SPAD + (size_t)i*SPAD + c;
        split_store(Ph, Pl, ob,   e0*inv, e1*inv);
        split_store(Ph, Pl, ob+2, e2*inv, e3*inv);
    }
}

// ---------------- V transpose per bh (hi only) ----------------
__global__ void vT_kernel(const f16* __restrict__ qkvh)
{
    int bh = blockIdx.y, b = bh>>4, h = bh&15;
    int t0 = blockIdx.x*64;
    __shared__ f16 sh[64][65];
    int tx = threadIdx.x, ty = threadIdx.y;
    #pragma unroll
    for (int i=0;i<8;++i){
        int tok = min(t0 + ty + 8*i, SS-1);
        size_t off = (size_t)(b*SS+tok)*3*DDIM + 2*DDIM + h*DH + tx*2;
        __half2 vh = *(const __half2*)(qkvh + off);
        sh[ty+8*i][tx*2] = vh.x; sh[ty+8*i][tx*2+1] = vh.y;
    }
    __syncthreads();
    f16* oh = g_vT_hi + (size_t)bh*DH*SPAD;
    #pragma unroll
    for (int i=0;i<8;++i){
        int d = ty + 8*i;
        __half2 H;
        H.x = sh[tx*2][d]; H.y = sh[tx*2+1][d];
        *(__half2*)(oh + (size_t)d*SPAD + t0 + tx*2) = H;
    }
}

// ---------------- PV gemm: O = P @ vT^T; P 2-term, V single ----------------
#define PV_STG 20480           // Ph 8K | Pl 8K | Vh 4K
#define PV_SMEM (2*PV_STG)
__global__ __launch_bounds__(256, 2)
void pv_gemm(const f16* __restrict__ Ph, const f16* __restrict__ Pl)
{
    int bh = blockIdx.z, b = bh>>4, h = bh&15;
    int m0 = blockIdx.y*128;
    extern __shared__ char smem[];
    uint32_t sb = s2u(smem);
    int tid = threadIdx.x, lane = tid&31, wid = tid>>5;
    int wm = wid&3, wn = wid>>2;

    const f16* Ah = Ph + (size_t)bh*SS*SPAD;
    const f16* Al = Pl + (size_t)bh*SS*SPAD;
    const f16* Bh = g_vT_hi + (size_t)bh*DH*SPAD;

    size_t aOff[2]; uint32_t aSw[2];
    #pragma unroll
    for (int i=0;i<2;++i){
        int t = tid+256*i, r = t>>2, c = t&3;
        aOff[i] = (size_t)min(m0+r, SS-1)*SPAD + c*8;
        aSw[i] = SWZ64((uint32_t)(r*64 + c*16));
    }
    size_t bOff; uint32_t bSw;
    {
        int r = tid>>2, c = tid&3;
        bOff = (size_t)r*SPAD + c*8;
        bSw = SWZ64((uint32_t)(r*64 + c*16));
    }

    const int NC = (m0+128)/32;
    #define PV_LOAD(s_, ck_) do { \
        uint32_t aH_ = sb + (s_)*PV_STG, aL_ = aH_ + 8192, bH_ = aH_ + 16384; \
        size_t ko_ = (size_t)(ck_)*32; \
        _Pragma("unroll") \
        for (int i=0;i<2;++i){ cp16(aH_+aSw[i], Ah+aOff[i]+ko_); cp16(aL_+aSw[i], Al+aOff[i]+ko_); } \
        cp16(bH_+bSw, Bh+bOff+ko_); \
    } while(0)

    PV_LOAD(0, 0); CP_COMMIT();

    int rA  = wm*32 + (lane&15);
    int kbA = (lane>>4)*16;
    int rB  = wn*32 + (lane&7) + ((lane>>4)<<3);
    int kbB = ((lane>>3)&1)*16;

    float acc[2][4][4];
    #pragma unroll
    for (int i=0;i<2;++i)
        #pragma unroll
        for (int j=0;j<4;++j)
            #pragma unroll
            for (int r=0;r<4;++r) acc[i][j][r]=0.f;

    for (int ck=0; ck<NC; ++ck){
        if (ck+1 < NC){ PV_LOAD((ck+1)&1, ck+1); CP_COMMIT(); CP_WAIT1(); }
        else CP_WAIT0();
        __syncthreads();
        uint32_t base = sb + (ck&1)*PV_STG;
        uint32_t uaH = base, uaL = base + 8192, ubH = base + 16384;
        #pragma unroll
        for (int ks=0; ks<2; ++ks){
            uint32_t bhf[2][4];
            #pragma unroll
            for (int ng=0;ng<2;++ng){
                uint32_t o = SWZ64((uint32_t)(rB + ng*16)*64 + ks*32 + kbB);
                LDM4(bhf[ng][0],bhf[ng][1],bhf[ng][2],bhf[ng][3], ubH + o);
            }
            #pragma unroll
            for (int mi=0;mi<2;++mi){
                uint32_t ah[4], al[4];
                uint32_t o = SWZ64((uint32_t)(rA + mi*16)*64 + ks*32 + kbA);
                LDM4(ah[0],ah[1],ah[2],ah[3], uaH + o);
                LDM4(al[0],al[1],al[2],al[3], uaL + o);
                #pragma unroll
                for (int ng=0;ng<2;++ng){
                    #pragma unroll
                    for (int j=0;j<2;++j){
                        MMA16816(acc[mi][ng*2+j], ah, bhf[ng][j*2], bhf[ng][j*2+1]);
                        MMA16816(acc[mi][ng*2+j], al, bhf[ng][j*2], bhf[ng][j*2+1]);
                    }
                }
            }
        }
        __syncthreads();
    }

    int g = lane>>2, tg = lane&3;
    #pragma unroll
    for (int mi=0;mi<2;++mi){
        #pragma unroll
        for (int half=0; half<2; ++half){
            int q = m0 + wm*32 + mi*16 + g + half*8;
            if (q < SS){
                size_t rowoff = (size_t)(b*SS+q)*DDIM + h*DH;
                #pragma unroll
                for (int nj=0;nj<4;++nj){
                    int d = wn*32 + nj*8 + tg*2;
                    split_store(g_o_hi, g_o_lo, rowoff + d,
                                acc[mi][nj][half*2+0], acc[mi][nj][half*2+1]);
                }
            }
        }
    }
}

// ---------------- fused prologue (weights/bias/idx/embed) ----------------
#define CV_MAIN 27648
#define CV_AUX  64
__global__ void convert_all(const float* __restrict__ wq, const float* __restrict__ wk,
                            const float* __restrict__ wv, const float* __restrict__ wo,
                            const float* __restrict__ w1, const float* __restrict__ w2,
                            const float* __restrict__ ho1, const float* __restrict__ ho2,
                            const float* __restrict__ he1,
                            const float* __restrict__ bq, const float* __restrict__ bk,
                            const float* __restrict__ bv,
                            const int* __restrict__ tokens, const float* __restrict__ pos_emb,
                            const float* __restrict__ emb_obs, const float* __restrict__ emb_act)
{
    int t = blockIdx.x;
    int tid = threadIdx.y*32 + threadIdx.x;
    if (t >= CV_MAIN + CV_AUX){
        int row = t - (CV_MAIN + CV_AUX);
        int s = row % SS;
        int tok = tokens[row];
        bool is_obs = (s % TPB_) < (TPB_-1);
        const float* e = is_obs ? (emb_obs + (size_t)min(tok,VOBS_-1)*DDIM)
                                : (emb_act + (size_t)min(tok,VACT_-1)*DDIM);
        const float* pe = pos_emb + (size_t)s*DDIM;
        float* xo = g_x + (size_t)row*DDIM;
        for (int d = tid; d < DDIM; d += 256) xo[d] = e[d] + pe[d];
        return;
    }
    if (t >= CV_MAIN){
        int idx = (t - CV_MAIN)*256 + tid;
        if (idx < LL*3*DDIM){
            int l = idx/(3*DDIM), r = idx%(3*DDIM), part = r/DDIM, d = r%DDIM;
            const float* src = part==0 ? bq : (part==1 ? bk : bv);
            g_bqkv[idx] = src[l*DDIM + d];
        }
        int j = idx - LL*3*DDIM;
        if (j >= 0 && j < NOBS){
            int b = j/960, jj = j%960, blk = jj/16, r = jj%16;
            g_obs_rows[j] = b*SS + blk*TPB_ + (r<15 ? r : 16);
        }
        if (j >= 0 && j < NACT){
            int b = j/60, blk = j%60;
            g_act_rows[j] = b*SS + blk*TPB_ + (TPB_-1);
        }
        return;
    }
    const float* src; int doff, K, N, base; size_t inMS, outMS;
    if      (t <  2048){ src=wq;  doff=WQKV_OFF;        K=DDIM; N=DDIM;  inMS=DD_; outMS=3*DD_; base=0; }
    else if (t <  4096){ src=wk;  doff=WQKV_OFF+DD_;    K=DDIM; N=DDIM;  inMS=DD_; outMS=3*DD_; base=2048; }
    else if (t <  6144){ src=wv;  doff=WQKV_OFF+2*DD_;  K=DDIM; N=DDIM;  inMS=DD_; outMS=3*DD_; base=4096; }
    else if (t <  8192){ src=wo;  doff=WO_OFF;          K=DDIM; N=DDIM;  inMS=DD_; outMS=DD_;   base=6144; }
    else if (t < 16384){ src=w1;  doff=W1_OFF;          K=DDIM; N=FF;    inMS=DF_; outMS=DF_;   base=8192; }
    else if (t < 24576){ src=w2;  doff=W2_OFF;          K=FF;   N=DDIM;  inMS=DF_; outMS=DF_;   base=16384; }
    else if (t < 25088){ src=ho1; doff=HO1_OFF;         K=DDIM; N=DDIM;  inMS=0;   outMS=0;     base=24576; }
    else if (t < 27136){ src=ho2; doff=HO2_OFF;         K=DDIM; N=VOBS_; inMS=0;   outMS=0;     base=25088; }
    else               { src=he1; doff=HE1_OFF;         K=DDIM; N=DDIM;  inMS=0;   outMS=0;     base=27136; }
    int r = t - base;
    int nt = N/32;
    int tpz = (K/64)*nt;
    int z = r/tpz, rr = r%tpz;
    int k0 = (rr/nt)*64, n0 = (rr%nt)*32;

    const float* Wm = src + (size_t)z*inMS;
    f16* Whm = g_wt_hi + doff + (size_t)z*outMS;

    __shared__ float tsh[64][33];
    int tx = threadIdx.x, ty = threadIdx.y;
    #pragma unroll
    for (int i=0;i<8;++i)
        tsh[ty+8*i][tx] = Wm[(size_t)(k0+ty+8*i)*N + n0+tx];
    __syncthreads();
    #pragma unroll
    for (int i=0;i<4;++i){
        int nn = ty + 8*i;
        __half2 H;
        H.x = __float2half_rn(tsh[tx*2][nn]);
        H.y = __float2half_rn(tsh[tx*2+1][nn]);
        *(__half2*)(Whm + (size_t)(n0+nn)*K + k0 + tx*2) = H;
    }
}

// ---------------- LN -> split fp16 ----------------
__device__ __forceinline__ float bsum256(float v)
{
    __shared__ float sh[8];
    int ln = threadIdx.x&31, w = threadIdx.x>>5;
    #pragma unroll
    for (int o=16;o>0;o>>=1) v += __shfl_xor_sync(0xffffffffu, v, o);
    if (ln==0) sh[w]=v;
    __syncthreads();
    if (w==0){
        float t = (ln<8)?sh[ln]:0.f;
        #pragma unroll
        for (int o=4;o>0;o>>=1) t += __shfl_xor_sync(0xffffffffu, t, o);
        if (ln==0) sh[0]=t;
    }
    __syncthreads();
    float r = sh[0];
    __syncthreads();
    return r;
}

__global__ void ln_kernel(const float* __restrict__ x, const float* __restrict__ g,
                          const float* __restrict__ b, f16* __restrict__ oh, f16* __restrict__ ol)
{
    int row = blockIdx.x, t = threadIdx.x;
    const float* xr = x + (size_t)row*DDIM;
    float v[4]; float s = 0.f;
    #pragma unroll
    for (int i=0;i<4;++i){ v[i]=xr[t+256*i]; s+=v[i]; }
    float mean = bsum256(s) * (1.f/DDIM);
    float q = 0.f;
    #pragma unroll
    for (int i=0;i<4;++i){ float d=v[i]-mean; q+=d*d; }
    float rstd = rsqrtf(bsum256(q)*(1.f/DDIM) + 1e-3f);
    #pragma unroll
    for (int i=0;i<4;++i){
        int idx = t+256*i;
        float y = (v[i]-mean)*rstd*g[idx] + b[idx];
        f16 h = __float2half_rn(y);
        oh[(size_t)row*DDIM+idx] = h;
        ol[(size_t)row*DDIM+idx] = __float2half_rn(y-__half2float(h));
    }
}

// ---------------- tiny N=2 head ----------------
__global__ void head_ends_kernel(const float* __restrict__ t2, const float* __restrict__ w,
                                 const float* __restrict__ bias, float* __restrict__ out)
{
    int r = blockIdx.x, tid = threadIdx.x;
    const float* a = t2 + (size_t)r*DDIM;
    float s0 = 0.f, s1 = 0.f;
    for (int k = tid; k < DDIM; k += 128){
        float av = a[k];
        s0 = fmaf(av, w[k*2], s0);
        s1 = fmaf(av, w[k*2+1], s1);
    }
    __shared__ float red[128];
    red[tid]=s0; __syncthreads();
    for (int st=64;st>0;st>>=1){ if (tid<st) red[tid]+=red[tid+st]; __syncthreads(); }
    if (tid==0) out[r*2] = red[0]+bias[0];
    __syncthreads();
    red[tid]=s1; __syncthreads();
    for (int st=64;st>0;st>>=1){ if (tid<st) red[tid]+=red[tid+st]; __syncthreads(); }
    if (tid==0) out[r*2+1] = red[0]+bias[1];
}

// ---------------- launch ----------------
extern "C" void kernel_launch(void* const* d_in, const int* in_sizes, int n_in,
                              void* d_out, int out_size)
{
    const int* tokens = (const int*)d_in[0];
    const float *pos_emb=(const float*)d_in[1], *emb_obs=(const float*)d_in[2], *emb_act=(const float*)d_in[3];
    const float *ln1_g=(const float*)d_in[4], *ln1_b=(const float*)d_in[5];
    const float *wq=(const float*)d_in[6], *bq=(const float*)d_in[7];
    const float *wk=(const float*)d_in[8], *bk=(const float*)d_in[9];
    const float *wv=(const float*)d_in[10], *bv=(const float*)d_in[11];
    const float *wo=(const float*)d_in[12], *bo=(const float*)d_in[13];
    const float *ln2_g=(const float*)d_in[14], *ln2_b=(const float*)d_in[15];
    const float *w1=(const float*)d_in[16], *b1=(const float*)d_in[17];
    const float *w2=(const float*)d_in[18], *b2=(const float*)d_in[19];
    const float *lnf_g=(const float*)d_in[20], *lnf_b=(const float*)d_in[21];
    const float *ho1=(const float*)d_in[22], *bo1=(const float*)d_in[23];
    const float *ho2=(const float*)d_in[24], *bo2=(const float*)d_in[25];
    const float *he1=(const float*)d_in[26], *be1=(const float*)d_in[27];
    const float *he2=(const float*)d_in[28], *be2=(const float*)d_in[29];
    float* out = (float*)d_out;

    float *x,*t2,*bqkv,*S;
    f16 *qkvh,*qkvl,*Ph,*Pl,*h_hi,*h_lo,*o_hi,*o_lo,*mid_hi,*mid_lo,*t1_hi,*t1_lo,*wt_hi;
    int *obsr,*actr;
    cudaGetSymbolAddress((void**)&x, g_x);
    cudaGetSymbolAddress((void**)&t2, g_t2);
    cudaGetSymbolAddress((void**)&bqkv, g_bqkv);
    cudaGetSymbolAddress((void**)&S, g_S);
    cudaGetSymbolAddress((void**)&qkvh, g_qkv_hi);
    cudaGetSymbolAddress((void**)&qkvl, g_qkv_lo);
    cudaGetSymbolAddress((void**)&Ph, g_P_hi);
    cudaGetSymbolAddress((void**)&Pl, g_P_lo);
    cudaGetSymbolAddress((void**)&h_hi, g_h_hi);
    cudaGetSymbolAddress((void**)&h_lo, g_h_lo);
    cudaGetSymbolAddress((void**)&o_hi, g_o_hi);
    cudaGetSymbolAddress((void**)&o_lo, g_o_lo);
    cudaGetSymbolAddress((void**)&mid_hi, g_mid_hi);
    cudaGetSymbolAddress((void**)&mid_lo, g_mid_lo);
    cudaGetSymbolAddress((void**)&t1_hi, g_t1_hi);
    cudaGetSymbolAddress((void**)&t1_lo, g_t1_lo);
    cudaGetSymbolAddress((void**)&wt_hi, g_wt_hi);
    cudaGetSymbolAddress((void**)&obsr, g_obs_rows);
    cudaGetSymbolAddress((void**)&actr, g_act_rows);

    cudaFuncSetAttribute(tcgemm<0,0>, cudaFuncAttributeMaxDynamicSharedMemorySize, GEMM_SMEM);
    cudaFuncSetAttribute(tcgemm<0,1>, cudaFuncAttributeMaxDynamicSharedMemorySize, GEMM_SMEM);
    cudaFuncSetAttribute(tcgemm<1,1>, cudaFuncAttributeMaxDynamicSharedMemorySize, GEMM_SMEM);
    cudaFuncSetAttribute(tcgemm<2,1>, cudaFuncAttributeMaxDynamicSharedMemorySize, GEMM_SMEM);
    cudaFuncSetAttribute(tcgemm<2,0>, cudaFuncAttributeMaxDynamicSharedMemorySize, GEMM_SMEM);
    cudaFuncSetAttribute(qk_gemm, cudaFuncAttributeMaxDynamicSharedMemorySize, QK_SMEM);
    cudaFuncSetAttribute(pv_gemm, cudaFuncAttributeMaxDynamicSharedMemorySize, PV_SMEM);

    convert_all<<<CV_MAIN + CV_AUX + NTOK, dim3(32,8)>>>(
        wq, wk, wv, wo, w1, w2, ho1, ho2, he1, bq, bk, bv,
        tokens, pos_emb, emb_obs, emb_act);

    #define GG(M_, N_) dim3((N_)/BN, ((M_)+BM-1)/BM)
    for (int l = 0; l < LL; ++l){
        size_t dd = (size_t)l*DD_;
        ln_kernel<<<NTOK, 256>>>(x, ln1_g+l*DDIM, ln1_b+l*DDIM, h_hi, h_lo);
        tcgemm<0,1><<<GG(NTOK, 3*DDIM), 256, GEMM_SMEM>>>(
            h_hi, h_lo, wt_hi+WQKV_OFF+(size_t)l*3*DD_,
            bqkv+(size_t)l*3*DDIM, nullptr, qkvh, qkvl, nullptr, nullptr, NTOK, 3*DDIM, DDIM);
        qk_gemm<<<dim3(8,8,NBH), 256, QK_SMEM>>>(qkvh, qkvl, S);
        vT_kernel<<<dim3(16,NBH), dim3(32,8)>>>(qkvh);
        softmax_kernel<<<dim3(SS,NBH), 256>>>(S, Ph, Pl);
        pv_gemm<<<dim3(1,8,NBH), 256, PV_SMEM>>>(Ph, Pl);
        tcgemm<0,0><<<GG(NTOK, DDIM), 256, GEMM_SMEM>>>(
            o_hi, o_lo, wt_hi+WO_OFF+dd,
            bo+l*DDIM, x, nullptr, nullptr, x, nullptr, NTOK, DDIM, DDIM);
        ln_kernel<<<NTOK, 256>>>(x, ln2_g+l*DDIM, ln2_b+l*DDIM, h_hi, h_lo);
        tcgemm<1,1><<<GG(NTOK, FF), 256, GEMM_SMEM>>>(
            h_hi, h_lo, wt_hi+W1_OFF+(size_t)l*DF_,
            b1+(size_t)l*FF, nullptr, mid_hi, mid_lo, nullptr, nullptr, NTOK, FF, DDIM);
        tcgemm<0,0><<<GG(NTOK, DDIM), 256, GEMM_SMEM>>>(
            mid_hi, mid_lo, wt_hi+W2_OFF+(size_t)l*DF_,
            b2+l*DDIM, x, nullptr, nullptr, x, nullptr, NTOK, DDIM, FF);
    }

    ln_kernel<<<NTOK, 256>>>(x, lnf_g, lnf_b, h_hi, h_lo);

    tcgemm<2,1><<<GG(NOBS, DDIM), 256, GEMM_SMEM>>>(
        h_hi, h_lo, wt_hi+HO1_OFF, bo1,
        nullptr, t1_hi, t1_lo, nullptr, obsr, NOBS, DDIM, DDIM);
    tcgemm<0,0><<<GG(NOBS, VOBS_), 256, GEMM_SMEM>>>(
        t1_hi, t1_lo, wt_hi+HO2_OFF, bo2,
        out, nullptr, nullptr, nullptr, nullptr, NOBS, VOBS_, DDIM);

    tcgemm<2,0><<<GG(NACT, DDIM), 256, GEMM_SMEM>>>(
        h_hi, h_lo, wt_hi+HE1_OFF, be1,
        t2, nullptr, nullptr, nullptr, actr, NACT, DDIM, DDIM);
    head_ends_kernel<<<NACT, 128>>>(t2, he2, be2, out + (size_t)NOBS*VOBS_);
}

// round 16
// speedup vs baseline: 1.9844x; 1.0295x over previous
#include <cuda_runtime.h>
#include <cuda_fp16.h>
#include <math.h>
#include <stdint.h>

typedef __half f16;

#define BB 4
#define SS 1020
#define DDIM 1024
#define HH 16
#define DH 64
#define LL 4
#define TPB_ 17
#define FF 4096
#define NTOK (BB*SS)
#define NOBS (BB*960)
#define NACT (BB*60)
#define VOBS_ 4096
#define VACT_ 16
#define DD_ (DDIM*DDIM)
#define DF_ (DDIM*FF)
#define SPAD 1024
#define NBH (BB*HH)

// ---------------- static scratch ----------------
__device__ __align__(256) float g_x[NTOK*DDIM];
__device__ __align__(256) float g_t2[NACT*DDIM];
__device__ __align__(256) f16 g_qkv_hi[NTOK*3*DDIM];
__device__ __align__(256) f16 g_qkv_lo[NTOK*3*DDIM];
__device__ __align__(256) float g_S[(size_t)NBH*SS*SPAD];
__device__ __align__(256) f16 g_P_hi[(size_t)NBH*SS*SPAD];
__device__ __align__(256) f16 g_P_lo[(size_t)NBH*SS*SPAD];
__device__ __align__(256) f16 g_vT_hi[NBH*DH*SPAD];
__device__ __align__(256) f16 g_h_hi[NTOK*DDIM];
__device__ __align__(256) f16 g_h_lo[NTOK*DDIM];
__device__ __align__(256) f16 g_o_hi[NTOK*DDIM];
__device__ __align__(256) f16 g_o_lo[NTOK*DDIM];
__device__ __align__(256) f16 g_mid_hi[NTOK*FF];
__device__ __align__(256) f16 g_mid_lo[NTOK*FF];
__device__ __align__(256) f16 g_t1_hi[NOBS*DDIM];
__device__ __align__(256) f16 g_t1_lo[NOBS*DDIM];
__device__ float g_bqkv[LL*3*DDIM];
__device__ int g_obs_rows[NOBS];
__device__ int g_act_rows[NACT];

#define WQKV_OFF 0
#define WO_OFF  (WQKV_OFF + LL*3*DD_)
#define W1_OFF  (WO_OFF + LL*DD_)
#define W2_OFF  (W1_OFF + LL*DF_)
#define HO1_OFF (W2_OFF + LL*DF_)
#define HO2_OFF (HO1_OFF + DD_)
#define HE1_OFF (HO2_OFF + VOBS_*DDIM)
#define WT_TOT  (HE1_OFF + DD_)
__device__ __align__(256) f16 g_wt_hi[WT_TOT];

// ---------------- PTX helpers ----------------
__device__ __forceinline__ uint32_t s2u(const void* p){ return (uint32_t)__cvta_generic_to_shared(p); }
__device__ __forceinline__ void cp16(uint32_t d, const void* s){
    asm volatile("cp.async.cg.shared.global [%0], [%1], 16;\n"::"r"(d),"l"(s));
}
#define CP_COMMIT() asm volatile("cp.async.commit_group;\n":::"memory")
#define CP_WAIT1()  asm volatile("cp.async.wait_group 1;\n":::"memory")
#define CP_WAIT0()  asm volatile("cp.async.wait_group 0;\n":::"memory")

#define SWZ64(o)  ((o) ^ (((o)>>3)&0x30))
#define SWZ128(o) ((o) ^ (((o)>>3)&0x70))

#define LDM4(r0,r1,r2,r3,a) \
    asm volatile("ldmatrix.sync.aligned.m8n8.x4.shared.b16 {%0,%1,%2,%3}, [%4];" \
        : "=r"(r0),"=r"(r1),"=r"(r2),"=r"(r3) : "r"(a))

#define MMA16816(c,a,b0,b1) \
    asm volatile("mma.sync.aligned.m16n8k16.row.col.f32.f16.f16.f32 " \
        "{%0,%1,%2,%3}, {%4,%5,%6,%7}, {%8,%9}, {%0,%1,%2,%3};" \
        : "+f"((c)[0]),"+f"((c)[1]),"+f"((c)[2]),"+f"((c)[3]) \
        : "r"((a)[0]),"r"((a)[1]),"r"((a)[2]),"r"((a)[3]), "r"(b0),"r"(b1))

__device__ __forceinline__ void split_store(f16* Ph, f16* Pl, size_t off, float v0, float v1){
    f16 h0=__float2half_rn(v0), h1=__float2half_rn(v1);
    __half2 H; H.x=h0; H.y=h1;
    __half2 L;
    L.x=__float2half_rn(v0-__half2float(h0));
    L.y=__float2half_rn(v1-__half2float(h1));
    *(__half2*)(Ph+off)=H;
    *(__half2*)(Pl+off)=L;
}

// ---------------- mma.sync fp16 GEMM: A 2-term split, B single; BK=64, 2-stage ----------------
#define BM 128
#define BN 128
#define STG 49152              // Ah 16K | Al 16K | Bh 16K (128B-pitch rows)
#define GEMM_SMEM (2*STG)      // 98304 -> 2 CTA/SM

template<int ACT, int OUTBF>
__global__ __launch_bounds__(256, 2)
void tcgemm(const f16* __restrict__ Ah, const f16* __restrict__ Al,
            const f16* __restrict__ Bh,
            const float* __restrict__ bias,
            float* __restrict__ C, f16* __restrict__ Ch, f16* __restrict__ Cl,
            const float* __restrict__ resid, const int* __restrict__ rowmap,
            int M, int N, int K)
{
    extern __shared__ char smem[];
    uint32_t sb = s2u(smem);
    int tid = threadIdx.x, lane = tid&31, wid = tid>>5;
    int wm = wid&1, wn = wid>>1;
    int m0 = blockIdx.y*BM, n0 = blockIdx.x*BN;

    size_t aOff[4], bOff[4]; uint32_t aSw[4];
    #pragma unroll
    for (int i=0;i<4;++i){
        int t = tid+256*i, r = t>>3, c = t&7;     // 128 rows x 8 granules (128B/row)
        int am = m0+r; if (am > M-1) am = M-1;
        int ar = rowmap ? rowmap[am] : am;
        aOff[i] = (size_t)ar*K + c*8;
        bOff[i] = (size_t)(n0+r)*K + c*8;
        aSw[i] = SWZ128((uint32_t)(r*128 + c*16));
    }

    const int NC = K/64;
    #define LOAD_STAGE(s_, ck_) do { \
        uint32_t aH_ = sb + (s_)*STG, aL_ = aH_ + 16384, bH_ = aH_ + 32768; \
        size_t ko_ = (size_t)(ck_)*64; \
        _Pragma("unroll") \
        for (int i=0;i<4;++i){ cp16(aH_+aSw[i], Ah+aOff[i]+ko_); cp16(aL_+aSw[i], Al+aOff[i]+ko_); \
                               cp16(bH_+aSw[i], Bh+bOff[i]+ko_); } \
    } while(0)

    LOAD_STAGE(0, 0); CP_COMMIT();

    int rA  = wm*64 + (lane&15);
    int kbA = (lane>>4)*16;
    int rB  = wn*32 + (lane&7) + ((lane>>4)<<3);
    int kbB = ((lane>>3)&1)*16;

    float acc[4][4][4];
    #pragma unroll
    for (int i=0;i<4;++i)
        #pragma unroll
        for (int j=0;j<4;++j)
            #pragma unroll
            for (int r=0;r<4;++r) acc[i][j][r]=0.f;

    for (int ck=0; ck<NC; ++ck){
        if (ck+1 < NC){ LOAD_STAGE((ck+1)&1, ck+1); CP_COMMIT(); CP_WAIT1(); }
        else CP_WAIT0();
        __syncthreads();
        uint32_t base = sb + (ck&1)*STG;
        uint32_t uaH = base, uaL = base + 16384, ubH = base + 32768;
        #pragma unroll
        for (int ks=0; ks<4; ++ks){
            uint32_t bh_[2][4];
            #pragma unroll
            for (int ng=0;ng<2;++ng){
                uint32_t o = SWZ128(((uint32_t)(rB + ng*16)<<7) + ks*32 + kbB);
                LDM4(bh_[ng][0],bh_[ng][1],bh_[ng][2],bh_[ng][3], ubH + o);
            }
            #pragma unroll
            for (int mi=0;mi<4;++mi){
                uint32_t ah[4], al[4];
                uint32_t o = SWZ128(((uint32_t)(rA + mi*16)<<7) + ks*32 + kbA);
                LDM4(ah[0],ah[1],ah[2],ah[3], uaH + o);
                LDM4(al[0],al[1],al[2],al[3], uaL + o);
                #pragma unroll
                for (int ng=0;ng<2;++ng){
                    #pragma unroll
                    for (int j=0;j<2;++j){
                        MMA16816(acc[mi][ng*2+j], ah, bh_[ng][j*2], bh_[ng][j*2+1]);
                        MMA16816(acc[mi][ng*2+j], al, bh_[ng][j*2], bh_[ng][j*2+1]);
                    }
                }
            }
        }
        __syncthreads();
    }

    int g = lane>>2, tg = lane&3;
    #pragma unroll
    for (int mi=0;mi<4;++mi){
        #pragma unroll
        for (int half=0; half<2; ++half){
            int m = m0 + wm*64 + mi*16 + g + half*8;
            if (m < M){
                #pragma unroll
                for (int nj=0;nj<4;++nj){
                    int n = n0 + wn*32 + nj*8 + tg*2;
                    float v0 = acc[mi][nj][half*2+0] + __ldg(bias+n);
                    float v1 = acc[mi][nj][half*2+1] + __ldg(bias+n+1);
                    if (ACT==1){
                        v0 = 0.5f*v0*(1.0f+erff(v0*0.70710678118654752f));
                        v1 = 0.5f*v1*(1.0f+erff(v1*0.70710678118654752f));
                    }
                    if (ACT==2){ v0 = fmaxf(v0,0.f); v1 = fmaxf(v1,0.f); }
                    if (resid){
                        float2 rr = *(const float2*)(resid + (size_t)m*N + n);
                        v0 += rr.x; v1 += rr.y;
                    }
                    if (OUTBF==0){
                        float2 w; w.x=v0; w.y=v1;
                        *(float2*)(C + (size_t)m*N + n) = w;
                    } else {
                        split_store(Ch, Cl, (size_t)m*N + n, v0, v1);
                    }
                }
            }
        }
    }
}

// ---------------- QK gemm: S = scale*Q@K^T causal; Q 2-term, K single ----------------
#define QK_SMEM 49152
__global__ __launch_bounds__(256, 2)
void qk_gemm(const f16* __restrict__ qkvh, const f16* __restrict__ qkvl,
             float* __restrict__ S)
{
    int bh = blockIdx.z, b = bh>>4, h = bh&15;
    int m0 = blockIdx.y*128, n0 = blockIdx.x*128;
    if (n0 > m0) return;
    extern __shared__ char smem[];
    uint32_t sb = s2u(smem);
    uint32_t aH = sb, aL = sb+16384, bH = sb+32768;
    int tid = threadIdx.x, lane = tid&31, wid = tid>>5;
    int wm = wid&1, wn = wid>>1;

    const f16* qh = qkvh + (size_t)(b*SS)*3*DDIM + h*DH;
    const f16* ql = qkvl + (size_t)(b*SS)*3*DDIM + h*DH;
    const f16* kh = qh + DDIM;

    #pragma unroll
    for (int i=0;i<4;++i){
        int t = tid+256*i, r = t>>3, c = t&7;
        int ar = min(m0+r, SS-1), br = min(n0+r, SS-1);
        size_t ao = (size_t)ar*3*DDIM + c*8;
        size_t bo = (size_t)br*3*DDIM + c*8;
        uint32_t o = SWZ128((uint32_t)(r*128 + c*16));
        cp16(aH+o, qh+ao); cp16(aL+o, ql+ao);
        cp16(bH+o, kh+bo);
    }
    CP_COMMIT(); CP_WAIT0();
    __syncthreads();

    int rA  = wm*64 + (lane&15);
    int kbA = (lane>>4)*16;
    int rB  = wn*32 + (lane&7) + ((lane>>4)<<3);
    int kbB = ((lane>>3)&1)*16;

    float acc[4][4][4];
    #pragma unroll
    for (int i=0;i<4;++i)
        #pragma unroll
        for (int j=0;j<4;++j)
            #pragma unroll
            for (int r=0;r<4;++r) acc[i][j][r]=0.f;

    #pragma unroll
    for (int ks=0; ks<4; ++ks){
        uint32_t bhf[2][4];
        #pragma unroll
        for (int ng=0;ng<2;++ng){
            uint32_t o = SWZ128(((uint32_t)(rB + ng*16)<<7) + ks*32 + kbB);
            LDM4(bhf[ng][0],bhf[ng][1],bhf[ng][2],bhf[ng][3], bH + o);
        }
        #pragma unroll
        for (int mi=0;mi<4;++mi){
            uint32_t ah[4], al[4];
            uint32_t o = SWZ128(((uint32_t)(rA + mi*16)<<7) + ks*32 + kbA);
            LDM4(ah[0],ah[1],ah[2],ah[3], aH + o);
            LDM4(al[0],al[1],al[2],al[3], aL + o);
            #pragma unroll
            for (int ng=0;ng<2;++ng){
                #pragma unroll
                for (int j=0;j<2;++j){
                    MMA16816(acc[mi][ng*2+j], ah, bhf[ng][j*2], bhf[ng][j*2+1]);
                    MMA16816(acc[mi][ng*2+j], al, bhf[ng][j*2], bhf[ng][j*2+1]);
                }
            }
        }
    }

    float* Sb = S + (size_t)bh*SS*SPAD;
    int g = lane>>2, tg = lane&3;
    #pragma unroll
    for (int mi=0;mi<4;++mi){
        #pragma unroll
        for (int half=0; half<2; ++half){
            int qi = m0 + wm*64 + mi*16 + g + half*8;
            if (qi < SS){
                #pragma unroll
                for (int nj=0;nj<4;++nj){
                    int kj = n0 + wn*32 + nj*8 + tg*2;
                    float v0 = (kj   <= qi) ? acc[mi][nj][half*2+0]*0.125f : -1e30f;
                    float v1 = (kj+1 <= qi) ? acc[mi][nj][half*2+1]*0.125f : -1e30f;
                    float2 w; w.x=v0; w.y=v1;
                    *(float2*)(Sb + (size_t)qi*SPAD + kj) = w;
                }
            }
        }
    }
}

// ---------------- softmax: register-resident ----------------
__global__ __launch_bounds__(256)
void softmax_kernel(const float* __restrict__ S,
                    f16* __restrict__ Ph, f16* __restrict__ Pl)
{
    int i = blockIdx.x, bh = blockIdx.y, tid = threadIdx.x;
    const float* row = S + (size_t)bh*SS*SPAD + (size_t)i*SPAD;
    int kend = ((i>>7)+1)<<7;
    int c = tid*4;
    float4 v = make_float4(-1e30f,-1e30f,-1e30f,-1e30f);
    if (c < kend) v = *(const float4*)(row + c);

    __shared__ float sh[8];
    int ln = tid&31, w = tid>>5;
    float mx = fmaxf(fmaxf(v.x,v.y), fmaxf(v.z,v.w));
    #pragma unroll
    for (int o=16;o>0;o>>=1) mx = fmaxf(mx, __shfl_xor_sync(0xffffffffu, mx, o));
    if (ln==0) sh[w]=mx;
    __syncthreads();
    if (w==0){
        float t = sh[ln&7];
        #pragma unroll
        for (int o=4;o>0;o>>=1) t = fmaxf(t, __shfl_xor_sync(0xffffffffu, t, o));
        if (ln==0) sh[0]=t;
    }
    __syncthreads();
    mx = sh[0];
    __syncthreads();
    float e0 = __expf(v.x-mx), e1 = __expf(v.y-mx);
    float e2 = __expf(v.z-mx), e3 = __expf(v.w-mx);
    float sm = (e0+e1)+(e2+e3);
    #pragma unroll
    for (int o=16;o>0;o>>=1) sm += __shfl_xor_sync(0xffffffffu, sm, o);
    if (ln==0) sh[w]=sm;
    __syncthreads();
    if (w==0){
        float t = sh[ln&7];
        #pragma unroll
        for (int o=4;o>0;o>>=1) t += __shfl_xor_sync(0xffffffffu, t, o);
        if (ln==0) sh[0]=t;
    }
    __syncthreads();
    float inv = 1.f/sh[0];
    if (c < kend){
        size_t ob = (size_t)bh*SS*SPAD + (size_t)i*SPAD + c;
        split_store(Ph, Pl, ob,   e0*inv, e1*inv);
        split_store(Ph, Pl, ob+2, e2*inv, e3*inv);
    }
}

// ---------------- V transpose per bh (hi only) ----------------
__global__ void vT_kernel(const f16* __restrict__ qkvh)
{
    int bh = blockIdx.y, b = bh>>4, h = bh&15;
    int t0 = blockIdx.x*64;
    __shared__ f16 sh[64][65];
    int tx = threadIdx.x, ty = threadIdx.y;
    #pragma unroll
    for (int i=0;i<8;++i){
        int tok = min(t0 + ty + 8*i, SS-1);
        size_t off = (size_t)(b*SS+tok)*3*DDIM + 2*DDIM + h*DH + tx*2;
        __half2 vh = *(const __half2*)(qkvh + off);
        sh[ty+8*i][tx*2] = vh.x; sh[ty+8*i][tx*2+1] = vh.y;
    }
    __syncthreads();
    f16* oh = g_vT_hi + (size_t)bh*DH*SPAD;
    #pragma unroll
    for (int i=0;i<8;++i){
        int d = ty + 8*i;
        __half2 H;
        H.x = sh[tx*2][d]; H.y = sh[tx*2+1][d];
        *(__half2*)(oh + (size_t)d*SPAD + t0 + tx*2) = H;
    }
}

// ---------------- PV gemm: O = P @ vT^T; P 2-term, V single ----------------
#define PV_STG 20480
#define PV_SMEM (2*PV_STG)
__global__ __launch_bounds__(256, 2)
void pv_gemm(const f16* __restrict__ Ph, const f16* __restrict__ Pl)
{
    int bh = blockIdx.z, b = bh>>4, h = bh&15;
    int m0 = blockIdx.y*128;
    extern __shared__ char smem[];
    uint32_t sb = s2u(smem);
    int tid = threadIdx.x, lane = tid&31, wid = tid>>5;
    int wm = wid&3, wn = wid>>2;

    const f16* Ah = Ph + (size_t)bh*SS*SPAD;
    const f16* Al = Pl + (size_t)bh*SS*SPAD;
    const f16* Bh = g_vT_hi + (size_t)bh*DH*SPAD;

    size_t aOff[2]; uint32_t aSw[2];
    #pragma unroll
    for (int i=0;i<2;++i){
        int t = tid+256*i, r = t>>2, c = t&3;
        aOff[i] = (size_t)min(m0+r, SS-1)*SPAD + c*8;
        aSw[i] = SWZ64((uint32_t)(r*64 + c*16));
    }
    size_t bOff; uint32_t bSw;
    {
        int r = tid>>2, c = tid&3;
        bOff = (size_t)r*SPAD + c*8;
        bSw = SWZ64((uint32_t)(r*64 + c*16));
    }

    const int NC = (m0+128)/32;
    #define PV_LOAD(s_, ck_) do { \
        uint32_t aH_ = sb + (s_)*PV_STG, aL_ = aH_ + 8192, bH_ = aH_ + 16384; \
        size_t ko_ = (size_t)(ck_)*32; \
        _Pragma("unroll") \
        for (int i=0;i<2;++i){ cp16(aH_+aSw[i], Ah+aOff[i]+ko_); cp16(aL_+aSw[i], Al+aOff[i]+ko_); } \
        cp16(bH_+bSw, Bh+bOff+ko_); \
    } while(0)

    PV_LOAD(0, 0); CP_COMMIT();

    int rA  = wm*32 + (lane&15);
    int kbA = (lane>>4)*16;
    int rB  = wn*32 + (lane&7) + ((lane>>4)<<3);
    int kbB = ((lane>>3)&1)*16;

    float acc[2][4][4];
    #pragma unroll
    for (int i=0;i<2;++i)
        #pragma unroll
        for (int j=0;j<4;++j)
            #pragma unroll
            for (int r=0;r<4;++r) acc[i][j][r]=0.f;

    for (int ck=0; ck<NC; ++ck){
        if (ck+1 < NC){ PV_LOAD((ck+1)&1, ck+1); CP_COMMIT(); CP_WAIT1(); }
        else CP_WAIT0();
        __syncthreads();
        uint32_t base = sb + (ck&1)*PV_STG;
        uint32_t uaH = base, uaL = base + 8192, ubH = base + 16384;
        #pragma unroll
        for (int ks=0; ks<2; ++ks){
            uint32_t bhf[2][4];
            #pragma unroll
            for (int ng=0;ng<2;++ng){
                uint32_t o = SWZ64((uint32_t)(rB + ng*16)*64 + ks*32 + kbB);
                LDM4(bhf[ng][0],bhf[ng][1],bhf[ng][2],bhf[ng][3], ubH + o);
            }
            #pragma unroll
            for (int mi=0;mi<2;++mi){
                uint32_t ah[4], al[4];
                uint32_t o = SWZ64((uint32_t)(rA + mi*16)*64 + ks*32 + kbA);
                LDM4(ah[0],ah[1],ah[2],ah[3], uaH + o);
                LDM4(al[0],al[1],al[2],al[3], uaL + o);
                #pragma unroll
                for (int ng=0;ng<2;++ng){
                    #pragma unroll
                    for (int j=0;j<2;++j){
                        MMA16816(acc[mi][ng*2+j], ah, bhf[ng][j*2], bhf[ng][j*2+1]);
                        MMA16816(acc[mi][ng*2+j], al, bhf[ng][j*2], bhf[ng][j*2+1]);
                    }
                }
            }
        }
        __syncthreads();
    }

    int g = lane>>2, tg = lane&3;
    #pragma unroll
    for (int mi=0;mi<2;++mi){
        #pragma unroll
        for (int half=0; half<2; ++half){
            int q = m0 + wm*32 + mi*16 + g + half*8;
            if (q < SS){
                size_t rowoff = (size_t)(b*SS+q)*DDIM + h*DH;
                #pragma unroll
                for (int nj=0;nj<4;++nj){
                    int d = wn*32 + nj*8 + tg*2;
                    split_store(g_o_hi, g_o_lo, rowoff + d,
                                acc[mi][nj][half*2+0], acc[mi][nj][half*2+1]);
                }
            }
        }
    }
}

// ---------------- fused prologue (weights/bias/idx/embed) ----------------
#define CV_MAIN 27648
#define CV_AUX  64
__global__ void convert_all(const float* __restrict__ wq, const float* __restrict__ wk,
                            const float* __restrict__ wv, const float* __restrict__ wo,
                            const float* __restrict__ w1, const float* __restrict__ w2,
                            const float* __restrict__ ho1, const float* __restrict__ ho2,
                            const float* __restrict__ he1,
                            const float* __restrict__ bq, const float* __restrict__ bk,
                            const float* __restrict__ bv,
                            const int* __restrict__ tokens, const float* __restrict__ pos_emb,
                            const float* __restrict__ emb_obs, const float* __restrict__ emb_act)
{
    int t = blockIdx.x;
    int tid = threadIdx.y*32 + threadIdx.x;
    if (t >= CV_MAIN + CV_AUX){
        int row = t - (CV_MAIN + CV_AUX);
        int s = row % SS;
        int tok = tokens[row];
        bool is_obs = (s % TPB_) < (TPB_-1);
        const float* e = is_obs ? (emb_obs + (size_t)min(tok,VOBS_-1)*DDIM)
                                : (emb_act + (size_t)min(tok,VACT_-1)*DDIM);
        const float* pe = pos_emb + (size_t)s*DDIM;
        float* xo = g_x + (size_t)row*DDIM;
        for (int d = tid; d < DDIM; d += 256) xo[d] = e[d] + pe[d];
        return;
    }
    if (t >= CV_MAIN){
        int idx = (t - CV_MAIN)*256 + tid;
        if (idx < LL*3*DDIM){
            int l = idx/(3*DDIM), r = idx%(3*DDIM), part = r/DDIM, d = r%DDIM;
            const float* src = part==0 ? bq : (part==1 ? bk : bv);
            g_bqkv[idx] = src[l*DDIM + d];
        }
        int j = idx - LL*3*DDIM;
        if (j >= 0 && j < NOBS){
            int b = j/960, jj = j%960, blk = jj/16, r = jj%16;
            g_obs_rows[j] = b*SS + blk*TPB_ + (r<15 ? r : 16);
        }
        if (j >= 0 && j < NACT){
            int b = j/60, blk = j%60;
            g_act_rows[j] = b*SS + blk*TPB_ + (TPB_-1);
        }
        return;
    }
    const float* src; int doff, K, N, base; size_t inMS, outMS;
    if      (t <  2048){ src=wq;  doff=WQKV_OFF;        K=DDIM; N=DDIM;  inMS=DD_; outMS=3*DD_; base=0; }
    else if (t <  4096){ src=wk;  doff=WQKV_OFF+DD_;    K=DDIM; N=DDIM;  inMS=DD_; outMS=3*DD_; base=2048; }
    else if (t <  6144){ src=wv;  doff=WQKV_OFF+2*DD_;  K=DDIM; N=DDIM;  inMS=DD_; outMS=3*DD_; base=4096; }
    else if (t <  8192){ src=wo;  doff=WO_OFF;          K=DDIM; N=DDIM;  inMS=DD_; outMS=DD_;   base=6144; }
    else if (t < 16384){ src=w1;  doff=W1_OFF;          K=DDIM; N=FF;    inMS=DF_; outMS=DF_;   base=8192; }
    else if (t < 24576){ src=w2;  doff=W2_OFF;          K=FF;   N=DDIM;  inMS=DF_; outMS=DF_;   base=16384; }
    else if (t < 25088){ src=ho1; doff=HO1_OFF;         K=DDIM; N=DDIM;  inMS=0;   outMS=0;     base=24576; }
    else if (t < 27136){ src=ho2; doff=HO2_OFF;         K=DDIM; N=VOBS_; inMS=0;   outMS=0;     base=25088; }
    else               { src=he1; doff=HE1_OFF;         K=DDIM; N=DDIM;  inMS=0;   outMS=0;     base=27136; }
    int r = t - base;
    int nt = N/32;
    int tpz = (K/64)*nt;
    int z = r/tpz, rr = r%tpz;
    int k0 = (rr/nt)*64, n0 = (rr%nt)*32;

    const float* Wm = src + (size_t)z*inMS;
    f16* Whm = g_wt_hi + doff + (size_t)z*outMS;

    __shared__ float tsh[64][33];
    int tx = threadIdx.x, ty = threadIdx.y;
    #pragma unroll
    for (int i=0;i<8;++i)
        tsh[ty+8*i][tx] = Wm[(size_t)(k0+ty+8*i)*N + n0+tx];
    __syncthreads();
    #pragma unroll
    for (int i=0;i<4;++i){
        int nn = ty + 8*i;
        __half2 H;
        H.x = __float2half_rn(tsh[tx*2][nn]);
        H.y = __float2half_rn(tsh[tx*2+1][nn]);
        *(__half2*)(Whm + (size_t)(n0+nn)*K + k0 + tx*2) = H;
    }
}

// ---------------- LN -> split fp16 ----------------
__device__ __forceinline__ float bsum256(float v)
{
    __shared__ float sh[8];
    int ln = threadIdx.x&31, w = threadIdx.x>>5;
    #pragma unroll
    for (int o=16;o>0;o>>=1) v += __shfl_xor_sync(0xffffffffu, v, o);
    if (ln==0) sh[w]=v;
    __syncthreads();
    if (w==0){
        float t = (ln<8)?sh[ln]:0.f;
        #pragma unroll
        for (int o=4;o>0;o>>=1) t += __shfl_xor_sync(0xffffffffu, t, o);
        if (ln==0) sh[0]=t;
    }
    __syncthreads();
    float r = sh[0];
    __syncthreads();
    return r;
}

__global__ void ln_kernel(const float* __restrict__ x, const float* __restrict__ g,
                          const float* __restrict__ b, f16* __restrict__ oh, f16* __restrict__ ol)
{
    int row = blockIdx.x, t = threadIdx.x;
    const float* xr = x + (size_t)row*DDIM;
    float v[4]; float s = 0.f;
    #pragma unroll
    for (int i=0;i<4;++i){ v[i]=xr[t+256*i]; s+=v[i]; }
    float mean = bsum256(s) * (1.f/DDIM);
    float q = 0.f;
    #pragma unroll
    for (int i=0;i<4;++i){ float d=v[i]-mean; q+=d*d; }
    float rstd = rsqrtf(bsum256(q)*(1.f/DDIM) + 1e-3f);
    #pragma unroll
    for (int i=0;i<4;++i){
        int idx = t+256*i;
        float y = (v[i]-mean)*rstd*g[idx] + b[idx];
        f16 h = __float2half_rn(y);
        oh[(size_t)row*DDIM+idx] = h;
        ol[(size_t)row*DDIM+idx] = __float2half_rn(y-__half2float(h));
    }
}

// ---------------- tiny N=2 head ----------------
__global__ void head_ends_kernel(const float* __restrict__ t2, const float* __restrict__ w,
                                 const float* __restrict__ bias, float* __restrict__ out)
{
    int r = blockIdx.x, tid = threadIdx.x;
    const float* a = t2 + (size_t)r*DDIM;
    float s0 = 0.f, s1 = 0.f;
    for (int k = tid; k < DDIM; k += 128){
        float av = a[k];
        s0 = fmaf(av, w[k*2], s0);
        s1 = fmaf(av, w[k*2+1], s1);
    }
    __shared__ float red[128];
    red[tid]=s0; __syncthreads();
    for (int st=64;st>0;st>>=1){ if (tid<st) red[tid]+=red[tid+st]; __syncthreads(); }
    if (tid==0) out[r*2] = red[0]+bias[0];
    __syncthreads();
    red[tid]=s1; __syncthreads();
    for (int st=64;st>0;st>>=1){ if (tid<st) red[tid]+=red[tid+st]; __syncthreads(); }
    if (tid==0) out[r*2+1] = red[0]+bias[1];
}

// ---------------- launch ----------------
extern "C" void kernel_launch(void* const* d_in, const int* in_sizes, int n_in,
                              void* d_out, int out_size)
{
    const int* tokens = (const int*)d_in[0];
    const float *pos_emb=(const float*)d_in[1], *emb_obs=(const float*)d_in[2], *emb_act=(const float*)d_in[3];
    const float *ln1_g=(const float*)d_in[4], *ln1_b=(const float*)d_in[5];
    const float *wq=(const float*)d_in[6], *bq=(const float*)d_in[7];
    const float *wk=(const float*)d_in[8], *bk=(const float*)d_in[9];
    const float *wv=(const float*)d_in[10], *bv=(const float*)d_in[11];
    const float *wo=(const float*)d_in[12], *bo=(const float*)d_in[13];
    const float *ln2_g=(const float*)d_in[14], *ln2_b=(const float*)d_in[15];
    const float *w1=(const float*)d_in[16], *b1=(const float*)d_in[17];
    const float *w2=(const float*)d_in[18], *b2=(const float*)d_in[19];
    const float *lnf_g=(const float*)d_in[20], *lnf_b=(const float*)d_in[21];
    const float *ho1=(const float*)d_in[22], *bo1=(const float*)d_in[23];
    const float *ho2=(const float*)d_in[24], *bo2=(const float*)d_in[25];
    const float *he1=(const float*)d_in[26], *be1=(const float*)d_in[27];
    const float *he2=(const float*)d_in[28], *be2=(const float*)d_in[29];
    float* out = (float*)d_out;

    float *x,*t2,*bqkv,*S;
    f16 *qkvh,*qkvl,*Ph,*Pl,*h_hi,*h_lo,*o_hi,*o_lo,*mid_hi,*mid_lo,*t1_hi,*t1_lo,*wt_hi;
    int *obsr,*actr;
    cudaGetSymbolAddress((void**)&x, g_x);
    cudaGetSymbolAddress((void**)&t2, g_t2);
    cudaGetSymbolAddress((void**)&bqkv, g_bqkv);
    cudaGetSymbolAddress((void**)&S, g_S);
    cudaGetSymbolAddress((void**)&qkvh, g_qkv_hi);
    cudaGetSymbolAddress((void**)&qkvl, g_qkv_lo);
    cudaGetSymbolAddress((void**)&Ph, g_P_hi);
    cudaGetSymbolAddress((void**)&Pl, g_P_lo);
    cudaGetSymbolAddress((void**)&h_hi, g_h_hi);
    cudaGetSymbolAddress((void**)&h_lo, g_h_lo);
    cudaGetSymbolAddress((void**)&o_hi, g_o_hi);
    cudaGetSymbolAddress((void**)&o_lo, g_o_lo);
    cudaGetSymbolAddress((void**)&mid_hi, g_mid_hi);
    cudaGetSymbolAddress((void**)&mid_lo, g_mid_lo);
    cudaGetSymbolAddress((void**)&t1_hi, g_t1_hi);
    cudaGetSymbolAddress((void**)&t1_lo, g_t1_lo);
    cudaGetSymbolAddress((void**)&wt_hi, g_wt_hi);
    cudaGetSymbolAddress((void**)&obsr, g_obs_rows);
    cudaGetSymbolAddress((void**)&actr, g_act_rows);

    cudaFuncSetAttribute(tcgemm<0,0>, cudaFuncAttributeMaxDynamicSharedMemorySize, GEMM_SMEM);
    cudaFuncSetAttribute(tcgemm<0,1>, cudaFuncAttributeMaxDynamicSharedMemorySize, GEMM_SMEM);
    cudaFuncSetAttribute(tcgemm<1,1>, cudaFuncAttributeMaxDynamicSharedMemorySize, GEMM_SMEM);
    cudaFuncSetAttribute(tcgemm<2,1>, cudaFuncAttributeMaxDynamicSharedMemorySize, GEMM_SMEM);
    cudaFuncSetAttribute(tcgemm<2,0>, cudaFuncAttributeMaxDynamicSharedMemorySize, GEMM_SMEM);
    cudaFuncSetAttribute(qk_gemm, cudaFuncAttributeMaxDynamicSharedMemorySize, QK_SMEM);
    cudaFuncSetAttribute(pv_gemm, cudaFuncAttributeMaxDynamicSharedMemorySize, PV_SMEM);

    convert_all<<<CV_MAIN + CV_AUX + NTOK, dim3(32,8)>>>(
        wq, wk, wv, wo, w1, w2, ho1, ho2, he1, bq, bk, bv,
        tokens, pos_emb, emb_obs, emb_act);

    #define GG(M_, N_) dim3((N_)/BN, ((M_)+BM-1)/BM)
    for (int l = 0; l < LL; ++l){
        size_t dd = (size_t)l*DD_;
        ln_kernel<<<NTOK, 256>>>(x, ln1_g+l*DDIM, ln1_b+l*DDIM, h_hi, h_lo);
        tcgemm<0,1><<<GG(NTOK, 3*DDIM), 256, GEMM_SMEM>>>(
            h_hi, h_lo, wt_hi+WQKV_OFF+(size_t)l*3*DD_,
            bqkv+(size_t)l*3*DDIM, nullptr, qkvh, qkvl, nullptr, nullptr, NTOK, 3*DDIM, DDIM);
        qk_gemm<<<dim3(8,8,NBH), 256, QK_SMEM>>>(qkvh, qkvl, S);
        vT_kernel<<<dim3(16,NBH), dim3(32,8)>>>(qkvh);
        softmax_kernel<<<dim3(SS,NBH), 256>>>(S, Ph, Pl);
        pv_gemm<<<dim3(1,8,NBH), 256, PV_SMEM>>>(Ph, Pl);
        tcgemm<0,0><<<GG(NTOK, DDIM), 256, GEMM_SMEM>>>(
            o_hi, o_lo, wt_hi+WO_OFF+dd,
            bo+l*DDIM, x, nullptr, nullptr, x, nullptr, NTOK, DDIM, DDIM);
        ln_kernel<<<NTOK, 256>>>(x, ln2_g+l*DDIM, ln2_b+l*DDIM, h_hi, h_lo);
        tcgemm<1,1><<<GG(NTOK, FF), 256, GEMM_SMEM>>>(
            h_hi, h_lo, wt_hi+W1_OFF+(size_t)l*DF_,
            b1+(size_t)l*FF, nullptr, mid_hi, mid_lo, nullptr, nullptr, NTOK, FF, DDIM);
        tcgemm<0,0><<<GG(NTOK, DDIM), 256, GEMM_SMEM>>>(
            mid_hi, mid_lo, wt_hi+W2_OFF+(size_t)l*DF_,
            b2+l*DDIM, x, nullptr, nullptr, x, nullptr, NTOK, DDIM, FF);
    }

    ln_kernel<<<NTOK, 256>>>(x, lnf_g, lnf_b, h_hi, h_lo);

    tcgemm<2,1><<<GG(NOBS, DDIM), 256, GEMM_SMEM>>>(
        h_hi, h_lo, wt_hi+HO1_OFF, bo1,
        nullptr, t1_hi, t1_lo, nullptr, obsr, NOBS, DDIM, DDIM);
    tcgemm<0,0><<<GG(NOBS, VOBS_), 256, GEMM_SMEM>>>(
        t1_hi, t1_lo, wt_hi+HO2_OFF, bo2,
        out, nullptr, nullptr, nullptr, nullptr, NOBS, VOBS_, DDIM);

    tcgemm<2,0><<<GG(NACT, DDIM), 256, GEMM_SMEM>>>(
        h_hi, h_lo, wt_hi+HE1_OFF, be1,
        t2, nullptr, nullptr, nullptr, actr, NACT, DDIM, DDIM);
    head_ends_kernel<<<NACT, 128>>>(t2, he2, be2, out + (size_t)NOBS*VOBS_);
}